// round 7
// baseline (speedup 1.0000x reference)
#include <cuda_runtime.h>
#include <math.h>
#include <stdint.h>
#include <stdio.h>

#define BB 2
#define TT 2048
#define DD 1024
#define HH 16
#define KVH 4
#define HDIM 64
#define HALF 32
#define DFF 4096
#define KW 15
#define MROWS (BB*TT)   // 4096
#define REP (HH/KVH)    // 4

#define SZ_X    4194304
#define SZ_COS  65536
#define SZ_NS   1024
#define SZ_QK   1048576
#define SZ_KK   262144
#define SZ_HNS  64
#define SZ_PWUP 2097152
#define SZ_DWK  15360

// ----------------- per-input device buffers (no arena) -----------------
__device__ __align__(256) float w_x   [SZ_X];
__device__ __align__(256) float w_cos [SZ_COS];
__device__ __align__(256) float w_sin [SZ_COS];
__device__ __align__(256) float w_ans [SZ_NS];
__device__ __align__(256) float w_qk  [SZ_QK];
__device__ __align__(256) float w_kk  [SZ_KK];
__device__ __align__(256) float w_vk  [SZ_KK];
__device__ __align__(256) float w_qns [SZ_HNS];
__device__ __align__(256) float w_kns [SZ_HNS];
__device__ __align__(256) float w_ok  [SZ_QK];
__device__ __align__(256) float w_cns [SZ_NS];
__device__ __align__(256) float w_pwup[SZ_PWUP];
__device__ __align__(256) float w_dwk [SZ_DWK];
__device__ __align__(256) float w_cins[SZ_NS];
__device__ __align__(256) float w_pwd [SZ_QK];
__device__ __align__(256) float w_fns [SZ_NS];
__device__ __align__(256) float w_gatew[SZ_X];
__device__ __align__(256) float w_upw  [SZ_X];
__device__ __align__(256) float w_downw[SZ_X];

// ----------------- scratch -----------------
__device__ __align__(256) float g_res [(size_t)MROWS*DD];
__device__ __align__(256) float g_h   [(size_t)MROWS*DD];
__device__ __align__(256) float g_qtmp[(size_t)MROWS*DD];
__device__ __align__(256) float g_ktmp[(size_t)MROWS*KVH*HDIM];
__device__ __align__(256) float g_vtmp[(size_t)MROWS*KVH*HDIM];
__device__ __align__(256) float g_q   [(size_t)BB*HH*TT*HDIM];
__device__ __align__(256) float g_k   [(size_t)BB*KVH*TT*HDIM];
__device__ __align__(256) float g_v   [(size_t)BB*KVH*TT*HDIM];
__device__ __align__(256) float g_attn[(size_t)MROWS*DD];
__device__ __align__(256) float g_u   [(size_t)MROWS*2*DD];
__device__ __align__(256) float g_g   [(size_t)MROWS*DD];
__device__ __align__(256) float g_c   [(size_t)MROWS*DD];
__device__ __align__(256) float g_gate[(size_t)MROWS*DFF];
__device__ __align__(256) float g_ff  [(size_t)MROWS*DFF];
__device__ float g_touchsink;

// ----------------- touch: force SM reads of a whole buffer -----------------
__global__ void __launch_bounds__(256) touch_kernel(const float* __restrict__ p, size_t n) {
    size_t i = (size_t)blockIdx.x * blockDim.x + threadIdx.x;
    float acc = 0.f;
    for (; i < n; i += (size_t)gridDim.x * blockDim.x) acc += p[i];
    if (acc == 1234567.891f) g_touchsink = acc;   // never true; defeats DCE
}

// ----------------- zcRMS over D=1024 -----------------
__global__ void __launch_bounds__(256) rmsnorm_kernel(const float* __restrict__ in,
                               const float* __restrict__ scale,
                               float* __restrict__ out) {
    size_t row = blockIdx.x;
    const float* xr = in + row * DD;
    float* orow = out + row * DD;
    int tid = threadIdx.x;
    float v[4];
    float ss = 0.f;
#pragma unroll
    for (int i = 0; i < 4; i++) { v[i] = xr[tid + i * 256]; ss += v[i] * v[i]; }
    __shared__ float red[256];
    red[tid] = ss; __syncthreads();
    for (int s = 128; s > 0; s >>= 1) { if (tid < s) red[tid] += red[tid + s]; __syncthreads(); }
    float inv = rsqrtf(red[0] / (float)DD + 1e-6f);
#pragma unroll
    for (int i = 0; i < 4; i++) {
        int c = tid + i * 256;
        orow[c] = (1.0f + scale[c]) * v[i] * inv;
    }
}

// ----------------- SGEMM 64x64x16; MODE 0:AB 1:res+AB 2:relu 3:relu*other 4:C+=AB -----------------
// lda = row stride of A (elements); loop runs K steps.
template <int MODE>
__global__ void __launch_bounds__(256) sgemm_kernel(const float* __restrict__ A, const float* __restrict__ W,
                             float* __restrict__ C, const float* __restrict__ res,
                             const float* __restrict__ other, int M, int N, int K, int lda) {
    __shared__ __align__(16) float As[16][64];
    __shared__ __align__(16) float Bs[16][64];
    int tid = threadIdx.x;
    int tx = tid & 15, ty = tid >> 4;
    int m0 = blockIdx.y * 64, n0 = blockIdx.x * 64;
    int arow = tid >> 2;
    int acol4 = (tid & 3) << 2;
    int brow = tid >> 6;
    int bcol = tid & 63;
    float acc[4][4] = {};
    for (int k0 = 0; k0 < K; k0 += 16) {
        float4 av = *reinterpret_cast<const float4*>(A + (size_t)(m0 + arow) * lda + k0 + acol4);
        As[acol4 + 0][arow] = av.x;
        As[acol4 + 1][arow] = av.y;
        As[acol4 + 2][arow] = av.z;
        As[acol4 + 3][arow] = av.w;
#pragma unroll
        for (int j = 0; j < 4; j++)
            Bs[brow + j * 4][bcol] = W[(size_t)(k0 + brow + j * 4) * N + n0 + bcol];
        __syncthreads();
#pragma unroll
        for (int kt = 0; kt < 16; kt++) {
            float4 a = *reinterpret_cast<const float4*>(&As[kt][ty * 4]);
            float4 b = *reinterpret_cast<const float4*>(&Bs[kt][tx * 4]);
            float aa[4] = {a.x, a.y, a.z, a.w};
            float bb[4] = {b.x, b.y, b.z, b.w};
#pragma unroll
            for (int i = 0; i < 4; i++)
#pragma unroll
                for (int j = 0; j < 4; j++) acc[i][j] += aa[i] * bb[j];
        }
        __syncthreads();
    }
#pragma unroll
    for (int i = 0; i < 4; i++)
#pragma unroll
        for (int j = 0; j < 4; j++) {
            int row = m0 + ty * 4 + i, col = n0 + tx * 4 + j;
            size_t o = (size_t)row * N + col;
            float v = acc[i][j];
            if (MODE == 1) v += res[o];
            if (MODE == 2) v = fmaxf(v, 0.f);
            if (MODE == 3) v = fmaxf(v, 0.f) * other[o];
            if (MODE == 4) v += C[o];
            C[o] = v;
        }
}

// ----------------- per-head zcRMS(64) + RoPE + transpose to (B,NH,T,HD) -----------------
__global__ void __launch_bounds__(256) qkpost_kernel(const float* __restrict__ tmp, const float* __restrict__ ns,
                              const float* __restrict__ cosp, const float* __restrict__ sinp,
                              float* __restrict__ out, int NH) {
    int warp = threadIdx.x >> 5, lane = threadIdx.x & 31;
    int row = blockIdx.x * 8 + warp;
    if (row >= BB * TT * NH) return;
    int hh = row % NH;
    int bt = row / NH;
    int t = bt % TT;
    int b = bt / TT;
    const float* xin = tmp + ((size_t)bt * NH + hh) * HDIM;
    float x1 = xin[lane], x2 = xin[lane + 32];
    float ss = x1 * x1 + x2 * x2;
#pragma unroll
    for (int o = 16; o > 0; o >>= 1) ss += __shfl_xor_sync(0xffffffffu, ss, o);
    float inv = rsqrtf(ss / (float)HDIM + 1e-6f);
    float y1 = (1.0f + ns[lane]) * x1 * inv;
    float y2 = (1.0f + ns[lane + 32]) * x2 * inv;
    float c = cosp[t * HALF + lane];
    float s = sinp[t * HALF + lane];
    float* orow = out + ((size_t)(b * NH + hh) * TT + t) * HDIM;
    orow[lane]      = y1 * c - y2 * s;
    orow[lane + 32] = y2 * c + y1 * s;
}

// ----------------- v transpose (B,T,KVH,HD) -> (B,KVH,T,HD) -----------------
__global__ void __launch_bounds__(256) vtrans_kernel() {
    int idx = blockIdx.x * blockDim.x + threadIdx.x;
    if (idx >= BB * TT * KVH * HDIM) return;
    int d = idx & 63;
    int r = idx >> 6;
    int hh = r % KVH;
    int bt = r / KVH;
    int t = bt % TT;
    int b = bt / TT;
    g_v[((size_t)(b * KVH + hh) * TT + t) * HDIM + d] = g_vtmp[idx];
}

// ----------------- flash attention: per (b,h), 64-row Q tile, streaming KV -----------------
#define FA_SMEM_FLOATS (4096 + 64*65 + 4096)
__global__ void __launch_bounds__(256) flash_kernel() {
    extern __shared__ float sm[];
    float* Qs = sm;                 // Qs[d*64 + i]
    float* KP = sm + 4096;          // K: KP[d*64 + j]; P: KP[k*65 + i]
    float* Vs = sm + 4096 + 64*65;  // Vs[k*64 + c]
    int z = blockIdx.y;             // b*H + h
    int b = z / HH, h = z % HH;
    const float* Q  = g_q + (size_t)z * TT * HDIM;
    const float* Kp = g_k + (size_t)(b * KVH + h / REP) * TT * HDIM;
    const float* Vp = g_v + (size_t)(b * KVH + h / REP) * TT * HDIM;
    int i0 = blockIdx.x * 64;
    int tid = threadIdx.x;
    int tx = tid & 15, ty = tid >> 4;

#pragma unroll
    for (int it = 0; it < 4; it++) {
        int sidx = tid + it * 256;
        int row = sidx >> 4;
        int col4 = (sidx & 15) << 2;
        float4 qv = *reinterpret_cast<const float4*>(Q + (size_t)(i0 + row) * HDIM + col4);
        Qs[(col4 + 0) * 64 + row] = qv.x;
        Qs[(col4 + 1) * 64 + row] = qv.y;
        Qs[(col4 + 2) * 64 + row] = qv.z;
        Qs[(col4 + 3) * 64 + row] = qv.w;
    }

    float m[4], l[4], o[4][4];
#pragma unroll
    for (int i = 0; i < 4; i++) {
        m[i] = -1e30f; l[i] = 0.f;
#pragma unroll
        for (int j = 0; j < 4; j++) o[i][j] = 0.f;
    }

    for (int j0 = 0; j0 < TT; j0 += 64) {
        __syncthreads();
#pragma unroll
        for (int it = 0; it < 4; it++) {
            int sidx = tid + it * 256;
            int row = sidx >> 4;
            int col4 = (sidx & 15) << 2;
            float4 kv = *reinterpret_cast<const float4*>(Kp + (size_t)(j0 + row) * HDIM + col4);
            KP[(col4 + 0) * 64 + row] = kv.x;
            KP[(col4 + 1) * 64 + row] = kv.y;
            KP[(col4 + 2) * 64 + row] = kv.z;
            KP[(col4 + 3) * 64 + row] = kv.w;
            float4 vv = *reinterpret_cast<const float4*>(Vp + (size_t)(j0 + row) * HDIM + col4);
            *reinterpret_cast<float4*>(Vs + row * 64 + col4) = vv;
        }
        __syncthreads();
        float s[4][4] = {};
#pragma unroll 8
        for (int d = 0; d < 64; d++) {
            float4 a = *reinterpret_cast<const float4*>(Qs + d * 64 + ty * 4);
            float4 bv = *reinterpret_cast<const float4*>(KP + d * 64 + tx * 4);
            float aa[4] = {a.x, a.y, a.z, a.w};
            float bb[4] = {bv.x, bv.y, bv.z, bv.w};
#pragma unroll
            for (int i = 0; i < 4; i++)
#pragma unroll
                for (int j = 0; j < 4; j++) s[i][j] += aa[i] * bb[j];
        }
        float mt[4], rs[4];
#pragma unroll
        for (int i = 0; i < 4; i++) {
            s[i][0] *= 0.125f; s[i][1] *= 0.125f; s[i][2] *= 0.125f; s[i][3] *= 0.125f;
            mt[i] = fmaxf(fmaxf(s[i][0], s[i][1]), fmaxf(s[i][2], s[i][3]));
        }
#pragma unroll
        for (int msk = 1; msk < 16; msk <<= 1)
#pragma unroll
            for (int i = 0; i < 4; i++) mt[i] = fmaxf(mt[i], __shfl_xor_sync(0xffffffffu, mt[i], msk));
#pragma unroll
        for (int i = 0; i < 4; i++) {
            float mn = fmaxf(m[i], mt[i]);
            float alpha = __expf(m[i] - mn);
            m[i] = mn;
            l[i] *= alpha;
            rs[i] = 0.f;
#pragma unroll
            for (int j = 0; j < 4; j++) {
                float p = __expf(s[i][j] - mn);
                s[i][j] = p;
                rs[i] += p;
                o[i][j] *= alpha;
            }
        }
#pragma unroll
        for (int msk = 1; msk < 16; msk <<= 1)
#pragma unroll
            for (int i = 0; i < 4; i++) rs[i] += __shfl_xor_sync(0xffffffffu, rs[i], msk);
#pragma unroll
        for (int i = 0; i < 4; i++) l[i] += rs[i];
        __syncthreads();
#pragma unroll
        for (int i = 0; i < 4; i++)
#pragma unroll
            for (int j = 0; j < 4; j++)
                KP[(tx * 4 + j) * 65 + ty * 4 + i] = s[i][j];
        __syncthreads();
#pragma unroll 8
        for (int k = 0; k < 64; k++) {
            float a[4];
#pragma unroll
            for (int i = 0; i < 4; i++) a[i] = KP[k * 65 + ty * 4 + i];
            float4 bv = *reinterpret_cast<const float4*>(Vs + k * 64 + tx * 4);
            float bb[4] = {bv.x, bv.y, bv.z, bv.w};
#pragma unroll
            for (int i = 0; i < 4; i++)
#pragma unroll
                for (int j = 0; j < 4; j++) o[i][j] += a[i] * bb[j];
        }
    }
#pragma unroll
    for (int i = 0; i < 4; i++) {
        float inv = 1.0f / l[i];
        int t_ = i0 + ty * 4 + i;
#pragma unroll
        for (int j = 0; j < 4; j++)
            g_attn[((size_t)(b * TT + t_) * HH + h) * HDIM + tx * 4 + j] = o[i][j] * inv;
    }
}

// ----------------- GLU -----------------
__global__ void __launch_bounds__(256) glu_kernel() {
    int idx = blockIdx.x * blockDim.x + threadIdx.x;
    if (idx >= MROWS * DD) return;
    int c = idx & (DD - 1);
    int r = idx >> 10;
    float u1 = g_u[(size_t)r * (2 * DD) + c];
    float u2 = g_u[(size_t)r * (2 * DD) + DD + c];
    g_g[idx] = u1 / (1.0f + __expf(-u2));
}

// ----------------- depthwise conv KW=15 SAME -----------------
__global__ void __launch_bounds__(256) dwconv_kernel(const float* __restrict__ dw) {
    int idx = blockIdx.x * blockDim.x + threadIdx.x;
    if (idx >= BB * TT * DD) return;
    int d = idx & (DD - 1);
    int t = (idx >> 10) & (TT - 1);
    int b = idx >> 21;
    float acc = 0.f;
#pragma unroll
    for (int w = 0; w < KW; w++) {
        int tt = t + w - 7;
        if (tt >= 0 && tt < TT)
            acc += g_g[((size_t)(b * TT + tt)) * DD + d] * dw[w * DD + d];
    }
    g_c[idx] = acc;
}

// ----------------- staged-sync diagnostics (no-op while capturing) -----------------
static void dbg(const char* name) {
    cudaStreamCaptureStatus st = cudaStreamCaptureStatusActive;
    cudaError_t qe = cudaStreamIsCapturing((cudaStream_t)0, &st);
    if (qe != cudaSuccess || st != cudaStreamCaptureStatusNone) return;
    cudaError_t e = cudaStreamSynchronize((cudaStream_t)0);
    fprintf(stderr, "[dbg] %-12s -> %s\n", name, cudaGetErrorString(e));
}

extern "C" void kernel_launch(void* const* d_in, const int* in_sizes, int n_in,
                              void* d_out, int out_size) {
    if (n_in < 20) { fprintf(stderr, "[klaunch] unexpected n_in=%d\n", n_in); return; }

    // resolve all symbol addresses
    float *x, *cosp, *sinp, *attn_ns, *qk, *kk, *vk, *qns, *kns, *ok;
    float *conv_ns, *pwup, *dwk, *cin_ns, *pwdown, *ffn_ns, *gatek, *upk, *downk;
    float *p_res, *p_h, *p_qtmp, *p_ktmp, *p_vtmp, *p_q, *p_k, *p_attn, *p_u, *p_c, *p_gate, *p_ff;
    cudaGetSymbolAddress((void**)&x, w_x);
    cudaGetSymbolAddress((void**)&cosp, w_cos);
    cudaGetSymbolAddress((void**)&sinp, w_sin);
    cudaGetSymbolAddress((void**)&attn_ns, w_ans);
    cudaGetSymbolAddress((void**)&qk, w_qk);
    cudaGetSymbolAddress((void**)&kk, w_kk);
    cudaGetSymbolAddress((void**)&vk, w_vk);
    cudaGetSymbolAddress((void**)&qns, w_qns);
    cudaGetSymbolAddress((void**)&kns, w_kns);
    cudaGetSymbolAddress((void**)&ok, w_ok);
    cudaGetSymbolAddress((void**)&conv_ns, w_cns);
    cudaGetSymbolAddress((void**)&pwup, w_pwup);
    cudaGetSymbolAddress((void**)&dwk, w_dwk);
    cudaGetSymbolAddress((void**)&cin_ns, w_cins);
    cudaGetSymbolAddress((void**)&pwdown, w_pwd);
    cudaGetSymbolAddress((void**)&ffn_ns, w_fns);
    cudaGetSymbolAddress((void**)&gatek, w_gatew);
    cudaGetSymbolAddress((void**)&upk, w_upw);
    cudaError_t es = cudaGetSymbolAddress((void**)&downk, w_downw);
    if (es != cudaSuccess) { fprintf(stderr, "[sym] downw err=%d\n", (int)es); return; }
    cudaGetSymbolAddress((void**)&p_res, g_res);
    cudaGetSymbolAddress((void**)&p_h, g_h);
    cudaGetSymbolAddress((void**)&p_qtmp, g_qtmp);
    cudaGetSymbolAddress((void**)&p_ktmp, g_ktmp);
    cudaGetSymbolAddress((void**)&p_vtmp, g_vtmp);
    cudaGetSymbolAddress((void**)&p_q, g_q);
    cudaGetSymbolAddress((void**)&p_k, g_k);
    cudaGetSymbolAddress((void**)&p_attn, g_attn);
    cudaGetSymbolAddress((void**)&p_u, g_u);
    cudaGetSymbolAddress((void**)&p_c, g_c);
    cudaGetSymbolAddress((void**)&p_gate, g_gate);
    es = cudaGetSymbolAddress((void**)&p_ff, g_ff);
    if (es != cudaSuccess) { fprintf(stderr, "[sym] g_ff err=%d\n", (int)es); return; }

    es = cudaFuncSetAttribute(flash_kernel, cudaFuncAttributeMaxDynamicSharedMemorySize,
                              FA_SMEM_FLOATS * 4);
    if (es != cudaSuccess) fprintf(stderr, "[klaunch] smem attr err=%d\n", (int)es);

    // ---- stage inputs (D2D memcpy; dict-order slots, mask at 1 skipped) ----
    struct { int slot; float* dst; int n; } cv[19] = {
        {0, x, SZ_X},        {2, cosp, SZ_COS},  {3, sinp, SZ_COS},
        {4, attn_ns, SZ_NS}, {5, qk, SZ_QK},     {6, kk, SZ_KK},
        {7, vk, SZ_KK},      {8, qns, SZ_HNS},   {9, kns, SZ_HNS},
        {10, ok, SZ_QK},     {11, conv_ns, SZ_NS}, {12, pwup, SZ_PWUP},
        {13, dwk, SZ_DWK},   {14, cin_ns, SZ_NS},  {15, pwdown, SZ_QK},
        {16, ffn_ns, SZ_NS}, {17, gatek, SZ_X},    {18, upk, SZ_X},
        {19, downk, SZ_X}
    };
    for (int i = 0; i < 19; i++) {
        cudaError_t ec = cudaMemcpyAsync(cv[i].dst, d_in[cv[i].slot],
                                         (size_t)cv[i].n * sizeof(float),
                                         cudaMemcpyDeviceToDevice, (cudaStream_t)0);
        if (ec != cudaSuccess) fprintf(stderr, "[memcpy] i=%d err=%d\n", i, (int)ec);
    }
    dbg("memcpy_in");

    // ---- attention block ----
    rmsnorm_kernel<<<MROWS, 256>>>(x, attn_ns, p_h);
    dbg("rmsnorm1");
    sgemm_kernel<0><<<dim3(DD / 64, MROWS / 64), 256>>>(p_h, qk, p_qtmp, nullptr, nullptr, MROWS, DD, DD, DD);
    sgemm_kernel<0><<<dim3((KVH * HDIM) / 64, MROWS / 64), 256>>>(p_h, kk, p_ktmp, nullptr, nullptr, MROWS, KVH * HDIM, DD, DD);
    sgemm_kernel<0><<<dim3((KVH * HDIM) / 64, MROWS / 64), 256>>>(p_h, vk, p_vtmp, nullptr, nullptr, MROWS, KVH * HDIM, DD, DD);
    dbg("qkv");
    qkpost_kernel<<<(BB * TT * HH) / 8, 256>>>(p_qtmp, qns, cosp, sinp, p_q, HH);
    qkpost_kernel<<<(BB * TT * KVH) / 8, 256>>>(p_ktmp, kns, cosp, sinp, p_k, KVH);
    vtrans_kernel<<<(BB * TT * KVH * HDIM) / 256, 256>>>();
    dbg("qkpost");
    flash_kernel<<<dim3(TT / 64, BB * HH), 256, FA_SMEM_FLOATS * 4>>>();
    dbg("flash");
    sgemm_kernel<1><<<dim3(DD / 64, MROWS / 64), 256>>>(p_attn, ok, p_res, x, nullptr, MROWS, DD, DD, DD);
    dbg("sgemm_o");

    // ---- conv block ----
    rmsnorm_kernel<<<MROWS, 256>>>(p_res, conv_ns, p_h);
    sgemm_kernel<0><<<dim3((2 * DD) / 64, MROWS / 64), 256>>>(p_h, pwup, p_u, nullptr, nullptr, MROWS, 2 * DD, DD, DD);
    dbg("pwup");
    glu_kernel<<<(MROWS * DD) / 256, 256>>>();
    dwconv_kernel<<<(BB * TT * DD) / 256, 256>>>(dwk);
    rmsnorm_kernel<<<MROWS, 256>>>(p_c, cin_ns, p_h);
    sgemm_kernel<1><<<dim3(DD / 64, MROWS / 64), 256>>>(p_h, pwdown, p_res, p_res, nullptr, MROWS, DD, DD, DD);
    dbg("pwdn");

    // ---- FFN block ----
    rmsnorm_kernel<<<MROWS, 256>>>(p_res, ffn_ns, p_h);
    sgemm_kernel<2><<<dim3(DFF / 64, MROWS / 64), 256>>>(p_h, gatek, p_gate, nullptr, nullptr, MROWS, DFF, DD, DD);
    sgemm_kernel<3><<<dim3(DFF / 64, MROWS / 64), 256>>>(p_h, upk, p_ff, nullptr, p_gate, MROWS, DFF, DD, DD);
    dbg("gateup");

    // touch diagnostics: full sweep of the two buffers the old faulting GEMM read
    touch_kernel<<<512, 256>>>(downk, (size_t)SZ_X);
    dbg("touch_down");
    touch_kernel<<<512, 256>>>(p_ff, (size_t)MROWS * DFF);
    dbg("touch_ff");

    // down GEMM split into 4 K-chunks of 1024 (all proven shapes)
    sgemm_kernel<1><<<dim3(DD / 64, MROWS / 64), 256>>>(p_ff,            downk,                p_res, p_res, nullptr, MROWS, DD, 1024, DFF);
    dbg("down0");
    sgemm_kernel<4><<<dim3(DD / 64, MROWS / 64), 256>>>(p_ff + 1024,     downk + 1024 * DD,    p_res, nullptr, nullptr, MROWS, DD, 1024, DFF);
    dbg("down1");
    sgemm_kernel<4><<<dim3(DD / 64, MROWS / 64), 256>>>(p_ff + 2048,     downk + 2048 * DD,    p_res, nullptr, nullptr, MROWS, DD, 1024, DFF);
    dbg("down2");
    sgemm_kernel<4><<<dim3(DD / 64, MROWS / 64), 256>>>(p_ff + 3072,     downk + 3072 * DD,    p_res, nullptr, nullptr, MROWS, DD, 1024, DFF);
    dbg("down3");

    // ---- result -> d_out ----
    cudaError_t eo = cudaMemcpyAsync(d_out, p_res, (size_t)MROWS * DD * sizeof(float),
                                     cudaMemcpyDeviceToDevice, (cudaStream_t)0);
    if (eo != cudaSuccess) fprintf(stderr, "[memcpy] out err=%d\n", (int)eo);
    dbg("memcpy_out");
}

// round 8
// speedup vs baseline: 2.3027x; 2.3027x over previous
#include <cuda_runtime.h>
#include <math.h>
#include <stdint.h>
#include <stdio.h>

#define BB 2
#define TT 2048
#define DD 1024
#define HH 16
#define KVH 4
#define HDIM 64
#define HALF 32
#define DFF 4096
#define KW 15
#define MROWS (BB*TT)   // 4096
#define REP (HH/KVH)    // 4

#define SZ_X    4194304
#define SZ_COS  65536
#define SZ_NS   1024
#define SZ_QK   1048576
#define SZ_KK   262144
#define SZ_HNS  64
#define SZ_PWUP 2097152
#define SZ_DWK  15360

// ----------------- per-input device buffers -----------------
__device__ __align__(256) float w_x   [SZ_X];
__device__ __align__(256) float w_cos [SZ_COS];
__device__ __align__(256) float w_sin [SZ_COS];
__device__ __align__(256) float w_ans [SZ_NS];
__device__ __align__(256) float w_qk  [SZ_QK];
__device__ __align__(256) float w_kk  [SZ_KK];
__device__ __align__(256) float w_vk  [SZ_KK];
__device__ __align__(256) float w_qns [SZ_HNS];
__device__ __align__(256) float w_kns [SZ_HNS];
__device__ __align__(256) float w_ok  [SZ_QK];
__device__ __align__(256) float w_cns [SZ_NS];
__device__ __align__(256) float w_pwup[SZ_PWUP];
__device__ __align__(256) float w_dwk [SZ_DWK];
__device__ __align__(256) float w_cins[SZ_NS];
__device__ __align__(256) float w_pwd [SZ_QK];
__device__ __align__(256) float w_fns [SZ_NS];
__device__ __align__(256) float w_gatew[SZ_X];
__device__ __align__(256) float w_upw  [SZ_X];
__device__ __align__(256) float w_downw[SZ_X];

// ----------------- scratch -----------------
__device__ __align__(256) float g_res [(size_t)MROWS*DD];
__device__ __align__(256) float g_h   [(size_t)MROWS*DD];
__device__ __align__(256) float g_qtmp[(size_t)MROWS*DD];
__device__ __align__(256) float g_ktmp[(size_t)MROWS*KVH*HDIM];
__device__ __align__(256) float g_vtmp[(size_t)MROWS*KVH*HDIM];
__device__ __align__(256) float g_q   [(size_t)BB*HH*TT*HDIM];
__device__ __align__(256) float g_k   [(size_t)BB*KVH*TT*HDIM];
__device__ __align__(256) float g_v   [(size_t)BB*KVH*TT*HDIM];
__device__ __align__(256) float g_attn[(size_t)MROWS*DD];
__device__ __align__(256) float g_u   [(size_t)MROWS*2*DD];
__device__ __align__(256) float g_g   [(size_t)MROWS*DD];
__device__ __align__(256) float g_c   [(size_t)MROWS*DD];
__device__ __align__(256) float g_gate[(size_t)MROWS*DFF];
__device__ __align__(256) float g_ff  [(size_t)MROWS*DFF];

// ----------------- tf32 rounding helpers -----------------
__device__ __forceinline__ float to_tf32(float x) {
    uint32_t u;
    asm("cvt.rna.tf32.f32 %0, %1;" : "=r"(u) : "f"(x));
    return __uint_as_float(u);
}

__global__ void __launch_bounds__(256) tf32ify_kernel(float* p, int n) {
    int i = blockIdx.x * blockDim.x + threadIdx.x;
    if (i < n) p[i] = to_tf32(p[i]);
}

// ----------------- zcRMS over D=1024 (output tf32-rounded: feeds GEMM A) -----------------
__global__ void __launch_bounds__(256) rmsnorm_kernel(const float* __restrict__ in,
                               const float* __restrict__ scale,
                               float* __restrict__ out) {
    size_t row = blockIdx.x;
    const float* xr = in + row * DD;
    float* orow = out + row * DD;
    int tid = threadIdx.x;
    float v[4];
    float ss = 0.f;
#pragma unroll
    for (int i = 0; i < 4; i++) { v[i] = xr[tid + i * 256]; ss += v[i] * v[i]; }
    __shared__ float red[256];
    red[tid] = ss; __syncthreads();
    for (int s = 128; s > 0; s >>= 1) { if (tid < s) red[tid] += red[tid + s]; __syncthreads(); }
    float inv = rsqrtf(red[0] / (float)DD + 1e-6f);
#pragma unroll
    for (int i = 0; i < 4; i++) {
        int c = tid + i * 256;
        orow[c] = to_tf32((1.0f + scale[c]) * v[i] * inv);
    }
}

// ----------------- tf32 tensor-core GEMM -----------------
// C[M,N] = A[M,K(lda)] @ W[K,N]; MODE 0:AB 1:res+AB 2:relu(AB) 3:tf32(relu(AB)*other) 4:C+=AB
#define BMT 128
#define BNT 128
#define BKT 32
#define ASTRIDE (BKT+4)                            // 36 floats (144B rows -> conflict-free ldmatrix)
#define BSTRIDE (BNT+4)                            // 132 floats
#define STAGE_FLOATS (BMT*ASTRIDE + BKT*BSTRIDE)   // 4608+4224 = 8832
#define TG_SMEM_BYTES (2*STAGE_FLOATS*4)           // 70656 B

__device__ __forceinline__ void cp16(uint32_t dst, const void* src) {
    asm volatile("cp.async.cg.shared.global [%0], [%1], 16;" :: "r"(dst), "l"(src));
}

template <int MODE>
__global__ void __launch_bounds__(256) tgemm_kernel(
    const float* __restrict__ A, const float* __restrict__ W,
    float* __restrict__ C, const float* __restrict__ res, const float* __restrict__ other,
    int M, int N, int K, int lda)
{
    extern __shared__ float sm[];
    int tid = threadIdx.x;
    int lane = tid & 31, warp = tid >> 5;
    int warp_m = warp >> 2;        // 0..1
    int warp_n = warp & 3;         // 0..3
    int m0 = blockIdx.y * BMT, n0 = blockIdx.x * BNT;
    const uint32_t s_u32 = (uint32_t)__cvta_generic_to_shared(sm);

    float acc[4][4][4];
#pragma unroll
    for (int mt = 0; mt < 4; mt++)
#pragma unroll
        for (int nt = 0; nt < 4; nt++)
#pragma unroll
            for (int r = 0; r < 4; r++) acc[mt][nt][r] = 0.f;

#define TG_ISSUE(s, k0) do {                                                          \
    uint32_t ab_ = s_u32 + (s) * (STAGE_FLOATS * 4);                                  \
    _Pragma("unroll")                                                                 \
    for (int j_ = 0; j_ < 4; j_++) {                                                  \
        int idx_ = j_ * 256 + tid; int r_ = idx_ >> 3, ch_ = idx_ & 7;                \
        cp16(ab_ + (uint32_t)(r_ * ASTRIDE + ch_ * 4) * 4,                            \
             A + (size_t)(m0 + r_) * lda + (k0) + ch_ * 4);                           \
    }                                                                                 \
    uint32_t bb_ = ab_ + BMT * ASTRIDE * 4;                                           \
    _Pragma("unroll")                                                                 \
    for (int j_ = 0; j_ < 4; j_++) {                                                  \
        int idx_ = j_ * 256 + tid; int r_ = idx_ >> 5, ch_ = idx_ & 31;               \
        cp16(bb_ + (uint32_t)(r_ * BSTRIDE + ch_ * 4) * 4,                            \
             W + (size_t)((k0) + r_) * N + n0 + ch_ * 4);                             \
    }                                                                                 \
    asm volatile("cp.async.commit_group;" ::: "memory");                              \
} while (0)

    int nk = K / BKT;
    TG_ISSUE(0, 0);

    for (int kt = 0; kt < nk; kt++) {
        int cur = kt & 1;
        asm volatile("cp.async.wait_group 0;" ::: "memory");
        __syncthreads();
        if (kt + 1 < nk) TG_ISSUE(cur ^ 1, (kt + 1) * BKT);

        uint32_t a_row = s_u32 + cur * (STAGE_FLOATS * 4)
                       + (uint32_t)((warp_m * 64 + (lane & 15)) * ASTRIDE + (lane >> 4) * 4) * 4;
        const float* BsF = sm + cur * STAGE_FLOATS + BMT * ASTRIDE;

#pragma unroll
        for (int kk = 0; kk < 4; kk++) {
            uint32_t a[4][4];
#pragma unroll
            for (int mt = 0; mt < 4; mt++) {
                uint32_t addr = a_row + (uint32_t)(mt * 16 * ASTRIDE + kk * 8) * 4;
                asm volatile("ldmatrix.sync.aligned.m8n8.x4.shared.b16 {%0,%1,%2,%3}, [%4];"
                             : "=r"(a[mt][0]), "=r"(a[mt][1]), "=r"(a[mt][2]), "=r"(a[mt][3])
                             : "r"(addr));
            }
            uint32_t b[4][2];
            int brow = kk * 8 + (lane & 3);
            int bcol = warp_n * 32 + (lane >> 2);
#pragma unroll
            for (int nt = 0; nt < 4; nt++) {
                b[nt][0] = __float_as_uint(BsF[brow * BSTRIDE + bcol + nt * 8]);
                b[nt][1] = __float_as_uint(BsF[(brow + 4) * BSTRIDE + bcol + nt * 8]);
            }
#pragma unroll
            for (int mt = 0; mt < 4; mt++)
#pragma unroll
                for (int nt = 0; nt < 4; nt++) {
                    asm volatile(
                        "mma.sync.aligned.m16n8k8.row.col.f32.tf32.tf32.f32 "
                        "{%0,%1,%2,%3}, {%4,%5,%6,%7}, {%8,%9}, {%0,%1,%2,%3};"
                        : "+f"(acc[mt][nt][0]), "+f"(acc[mt][nt][1]),
                          "+f"(acc[mt][nt][2]), "+f"(acc[mt][nt][3])
                        : "r"(a[mt][0]), "r"(a[mt][1]), "r"(a[mt][2]), "r"(a[mt][3]),
                          "r"(b[nt][0]), "r"(b[nt][1]));
                }
        }
    }
#undef TG_ISSUE

    // epilogue: c0:(g, 2q) c1:(g, 2q+1) c2:(g+8, 2q) c3:(g+8, 2q+1)
    int g = lane >> 2;
    int cb = 2 * (lane & 3);
#pragma unroll
    for (int mt = 0; mt < 4; mt++) {
#pragma unroll
        for (int nt = 0; nt < 4; nt++) {
            int col = n0 + warp_n * 32 + nt * 8 + cb;
#pragma unroll
            for (int half = 0; half < 2; half++) {
                int row = m0 + warp_m * 64 + mt * 16 + g + half * 8;
                size_t o0 = (size_t)row * N + col;
#pragma unroll
                for (int jj = 0; jj < 2; jj++) {
                    float v = acc[mt][nt][half * 2 + jj];
                    size_t o = o0 + jj;
                    if (MODE == 1) v += res[o];
                    if (MODE == 2) v = fmaxf(v, 0.f);
                    if (MODE == 3) v = to_tf32(fmaxf(v, 0.f) * other[o]);
                    if (MODE == 4) v += C[o];
                    C[o] = v;
                }
            }
        }
    }
}

// ----------------- per-head zcRMS(64) + RoPE + transpose to (B,NH,T,HD) -----------------
__global__ void __launch_bounds__(256) qkpost_kernel(const float* __restrict__ tmp, const float* __restrict__ ns,
                              const float* __restrict__ cosp, const float* __restrict__ sinp,
                              float* __restrict__ out, int NH) {
    int warp = threadIdx.x >> 5, lane = threadIdx.x & 31;
    int row = blockIdx.x * 8 + warp;
    if (row >= BB * TT * NH) return;
    int hh = row % NH;
    int bt = row / NH;
    int t = bt % TT;
    int b = bt / TT;
    const float* xin = tmp + ((size_t)bt * NH + hh) * HDIM;
    float x1 = xin[lane], x2 = xin[lane + 32];
    float ss = x1 * x1 + x2 * x2;
#pragma unroll
    for (int o = 16; o > 0; o >>= 1) ss += __shfl_xor_sync(0xffffffffu, ss, o);
    float inv = rsqrtf(ss / (float)HDIM + 1e-6f);
    float y1 = (1.0f + ns[lane]) * x1 * inv;
    float y2 = (1.0f + ns[lane + 32]) * x2 * inv;
    float c = cosp[t * HALF + lane];
    float s = sinp[t * HALF + lane];
    float* orow = out + ((size_t)(b * NH + hh) * TT + t) * HDIM;
    orow[lane]      = y1 * c - y2 * s;
    orow[lane + 32] = y2 * c + y1 * s;
}

// ----------------- v transpose -----------------
__global__ void __launch_bounds__(256) vtrans_kernel() {
    int idx = blockIdx.x * blockDim.x + threadIdx.x;
    if (idx >= BB * TT * KVH * HDIM) return;
    int d = idx & 63;
    int r = idx >> 6;
    int hh = r % KVH;
    int bt = r / KVH;
    int t = bt % TT;
    int b = bt / TT;
    g_v[((size_t)(b * KVH + hh) * TT + t) * HDIM + d] = g_vtmp[idx];
}

// ----------------- flash attention (fp32), output tf32-rounded (feeds o-proj A) -----------------
#define FA_SMEM_FLOATS (4096 + 64*65 + 4096)
__global__ void __launch_bounds__(256) flash_kernel() {
    extern __shared__ float smf[];
    float* Qs = smf;
    float* KP = smf + 4096;
    float* Vs = smf + 4096 + 64*65;
    int z = blockIdx.y;
    int b = z / HH, h = z % HH;
    const float* Q  = g_q + (size_t)z * TT * HDIM;
    const float* Kp = g_k + (size_t)(b * KVH + h / REP) * TT * HDIM;
    const float* Vp = g_v + (size_t)(b * KVH + h / REP) * TT * HDIM;
    int i0 = blockIdx.x * 64;
    int tid = threadIdx.x;
    int tx = tid & 15, ty = tid >> 4;

#pragma unroll
    for (int it = 0; it < 4; it++) {
        int sidx = tid + it * 256;
        int row = sidx >> 4;
        int col4 = (sidx & 15) << 2;
        float4 qv = *reinterpret_cast<const float4*>(Q + (size_t)(i0 + row) * HDIM + col4);
        Qs[(col4 + 0) * 64 + row] = qv.x;
        Qs[(col4 + 1) * 64 + row] = qv.y;
        Qs[(col4 + 2) * 64 + row] = qv.z;
        Qs[(col4 + 3) * 64 + row] = qv.w;
    }

    float m[4], l[4], o[4][4];
#pragma unroll
    for (int i = 0; i < 4; i++) {
        m[i] = -1e30f; l[i] = 0.f;
#pragma unroll
        for (int j = 0; j < 4; j++) o[i][j] = 0.f;
    }

    for (int j0 = 0; j0 < TT; j0 += 64) {
        __syncthreads();
#pragma unroll
        for (int it = 0; it < 4; it++) {
            int sidx = tid + it * 256;
            int row = sidx >> 4;
            int col4 = (sidx & 15) << 2;
            float4 kv = *reinterpret_cast<const float4*>(Kp + (size_t)(j0 + row) * HDIM + col4);
            KP[(col4 + 0) * 64 + row] = kv.x;
            KP[(col4 + 1) * 64 + row] = kv.y;
            KP[(col4 + 2) * 64 + row] = kv.z;
            KP[(col4 + 3) * 64 + row] = kv.w;
            float4 vv = *reinterpret_cast<const float4*>(Vp + (size_t)(j0 + row) * HDIM + col4);
            *reinterpret_cast<float4*>(Vs + row * 64 + col4) = vv;
        }
        __syncthreads();
        float s[4][4] = {};
#pragma unroll 8
        for (int d = 0; d < 64; d++) {
            float4 a = *reinterpret_cast<const float4*>(Qs + d * 64 + ty * 4);
            float4 bv = *reinterpret_cast<const float4*>(KP + d * 64 + tx * 4);
            float aa[4] = {a.x, a.y, a.z, a.w};
            float bb[4] = {bv.x, bv.y, bv.z, bv.w};
#pragma unroll
            for (int i = 0; i < 4; i++)
#pragma unroll
                for (int j = 0; j < 4; j++) s[i][j] += aa[i] * bb[j];
        }
        float mt[4], rs[4];
#pragma unroll
        for (int i = 0; i < 4; i++) {
            s[i][0] *= 0.125f; s[i][1] *= 0.125f; s[i][2] *= 0.125f; s[i][3] *= 0.125f;
            mt[i] = fmaxf(fmaxf(s[i][0], s[i][1]), fmaxf(s[i][2], s[i][3]));
        }
#pragma unroll
        for (int msk = 1; msk < 16; msk <<= 1)
#pragma unroll
            for (int i = 0; i < 4; i++) mt[i] = fmaxf(mt[i], __shfl_xor_sync(0xffffffffu, mt[i], msk));
#pragma unroll
        for (int i = 0; i < 4; i++) {
            float mn = fmaxf(m[i], mt[i]);
            float alpha = __expf(m[i] - mn);
            m[i] = mn;
            l[i] *= alpha;
            rs[i] = 0.f;
#pragma unroll
            for (int j = 0; j < 4; j++) {
                float p = __expf(s[i][j] - mn);
                s[i][j] = p;
                rs[i] += p;
                o[i][j] *= alpha;
            }
        }
#pragma unroll
        for (int msk = 1; msk < 16; msk <<= 1)
#pragma unroll
            for (int i = 0; i < 4; i++) rs[i] += __shfl_xor_sync(0xffffffffu, rs[i], msk);
#pragma unroll
        for (int i = 0; i < 4; i++) l[i] += rs[i];
        __syncthreads();
#pragma unroll
        for (int i = 0; i < 4; i++)
#pragma unroll
            for (int j = 0; j < 4; j++)
                KP[(tx * 4 + j) * 65 + ty * 4 + i] = s[i][j];
        __syncthreads();
#pragma unroll 8
        for (int k = 0; k < 64; k++) {
            float a[4];
#pragma unroll
            for (int i = 0; i < 4; i++) a[i] = KP[k * 65 + ty * 4 + i];
            float4 bv = *reinterpret_cast<const float4*>(Vs + k * 64 + tx * 4);
            float bb[4] = {bv.x, bv.y, bv.z, bv.w};
#pragma unroll
            for (int i = 0; i < 4; i++)
#pragma unroll
                for (int j = 0; j < 4; j++) o[i][j] += a[i] * bb[j];
        }
    }
#pragma unroll
    for (int i = 0; i < 4; i++) {
        float inv = 1.0f / l[i];
        int t_ = i0 + ty * 4 + i;
#pragma unroll
        for (int j = 0; j < 4; j++)
            g_attn[((size_t)(b * TT + t_) * HH + h) * HDIM + tx * 4 + j] = to_tf32(o[i][j] * inv);
    }
}

// ----------------- GLU -----------------
__global__ void __launch_bounds__(256) glu_kernel() {
    int idx = blockIdx.x * blockDim.x + threadIdx.x;
    if (idx >= MROWS * DD) return;
    int c = idx & (DD - 1);
    int r = idx >> 10;
    float u1 = g_u[(size_t)r * (2 * DD) + c];
    float u2 = g_u[(size_t)r * (2 * DD) + DD + c];
    g_g[idx] = u1 / (1.0f + __expf(-u2));
}

// ----------------- depthwise conv KW=15 SAME -----------------
__global__ void __launch_bounds__(256) dwconv_kernel(const float* __restrict__ dw) {
    int idx = blockIdx.x * blockDim.x + threadIdx.x;
    if (idx >= BB * TT * DD) return;
    int d = idx & (DD - 1);
    int t = (idx >> 10) & (TT - 1);
    int b = idx >> 21;
    float acc = 0.f;
#pragma unroll
    for (int w = 0; w < KW; w++) {
        int tt = t + w - 7;
        if (tt >= 0 && tt < TT)
            acc += g_g[((size_t)(b * TT + tt)) * DD + d] * dw[w * DD + d];
    }
    g_c[idx] = acc;
}

// ----------------- staged-sync diagnostics (no-op while capturing) -----------------
static void dbg(const char* name) {
    cudaStreamCaptureStatus st = cudaStreamCaptureStatusActive;
    cudaError_t qe = cudaStreamIsCapturing((cudaStream_t)0, &st);
    if (qe != cudaSuccess || st != cudaStreamCaptureStatusNone) return;
    cudaError_t e = cudaStreamSynchronize((cudaStream_t)0);
    fprintf(stderr, "[dbg] %-12s -> %s\n", name, cudaGetErrorString(e));
}

extern "C" void kernel_launch(void* const* d_in, const int* in_sizes, int n_in,
                              void* d_out, int out_size) {
    if (n_in < 20) { fprintf(stderr, "[klaunch] unexpected n_in=%d\n", n_in); return; }

    float *x, *cosp, *sinp, *attn_ns, *qk, *kk, *vk, *qns, *kns, *ok;
    float *conv_ns, *pwup, *dwk, *cin_ns, *pwdown, *ffn_ns, *gatek, *upk, *downk;
    float *p_res, *p_h, *p_qtmp, *p_ktmp, *p_vtmp, *p_q, *p_k, *p_attn, *p_u, *p_c, *p_gate, *p_ff;
    cudaGetSymbolAddress((void**)&x, w_x);
    cudaGetSymbolAddress((void**)&cosp, w_cos);
    cudaGetSymbolAddress((void**)&sinp, w_sin);
    cudaGetSymbolAddress((void**)&attn_ns, w_ans);
    cudaGetSymbolAddress((void**)&qk, w_qk);
    cudaGetSymbolAddress((void**)&kk, w_kk);
    cudaGetSymbolAddress((void**)&vk, w_vk);
    cudaGetSymbolAddress((void**)&qns, w_qns);
    cudaGetSymbolAddress((void**)&kns, w_kns);
    cudaGetSymbolAddress((void**)&ok, w_ok);
    cudaGetSymbolAddress((void**)&conv_ns, w_cns);
    cudaGetSymbolAddress((void**)&pwup, w_pwup);
    cudaGetSymbolAddress((void**)&dwk, w_dwk);
    cudaGetSymbolAddress((void**)&cin_ns, w_cins);
    cudaGetSymbolAddress((void**)&pwdown, w_pwd);
    cudaGetSymbolAddress((void**)&ffn_ns, w_fns);
    cudaGetSymbolAddress((void**)&gatek, w_gatew);
    cudaGetSymbolAddress((void**)&upk, w_upw);
    cudaError_t es = cudaGetSymbolAddress((void**)&downk, w_downw);
    if (es != cudaSuccess) { fprintf(stderr, "[sym] downw err=%d\n", (int)es); return; }
    cudaGetSymbolAddress((void**)&p_res, g_res);
    cudaGetSymbolAddress((void**)&p_h, g_h);
    cudaGetSymbolAddress((void**)&p_qtmp, g_qtmp);
    cudaGetSymbolAddress((void**)&p_ktmp, g_ktmp);
    cudaGetSymbolAddress((void**)&p_vtmp, g_vtmp);
    cudaGetSymbolAddress((void**)&p_q, g_q);
    cudaGetSymbolAddress((void**)&p_k, g_k);
    cudaGetSymbolAddress((void**)&p_attn, g_attn);
    cudaGetSymbolAddress((void**)&p_u, g_u);
    cudaGetSymbolAddress((void**)&p_c, g_c);
    cudaGetSymbolAddress((void**)&p_gate, g_gate);
    es = cudaGetSymbolAddress((void**)&p_ff, g_ff);
    if (es != cudaSuccess) { fprintf(stderr, "[sym] g_ff err=%d\n", (int)es); return; }

    cudaFuncSetAttribute(flash_kernel, cudaFuncAttributeMaxDynamicSharedMemorySize, FA_SMEM_FLOATS * 4);
    cudaFuncSetAttribute(tgemm_kernel<0>, cudaFuncAttributeMaxDynamicSharedMemorySize, TG_SMEM_BYTES);
    cudaFuncSetAttribute(tgemm_kernel<1>, cudaFuncAttributeMaxDynamicSharedMemorySize, TG_SMEM_BYTES);
    cudaFuncSetAttribute(tgemm_kernel<2>, cudaFuncAttributeMaxDynamicSharedMemorySize, TG_SMEM_BYTES);
    cudaFuncSetAttribute(tgemm_kernel<3>, cudaFuncAttributeMaxDynamicSharedMemorySize, TG_SMEM_BYTES);
    es = cudaFuncSetAttribute(tgemm_kernel<4>, cudaFuncAttributeMaxDynamicSharedMemorySize, TG_SMEM_BYTES);
    if (es != cudaSuccess) fprintf(stderr, "[klaunch] smem attr err=%d\n", (int)es);

    // ---- stage inputs (D2D memcpy; dict order, mask at slot 1 skipped) ----
    struct { int slot; float* dst; int n; } cv[19] = {
        {0, x, SZ_X},        {2, cosp, SZ_COS},  {3, sinp, SZ_COS},
        {4, attn_ns, SZ_NS}, {5, qk, SZ_QK},     {6, kk, SZ_KK},
        {7, vk, SZ_KK},      {8, qns, SZ_HNS},   {9, kns, SZ_HNS},
        {10, ok, SZ_QK},     {11, conv_ns, SZ_NS}, {12, pwup, SZ_PWUP},
        {13, dwk, SZ_DWK},   {14, cin_ns, SZ_NS},  {15, pwdown, SZ_QK},
        {16, ffn_ns, SZ_NS}, {17, gatek, SZ_X},    {18, upk, SZ_X},
        {19, downk, SZ_X}
    };
    for (int i = 0; i < 19; i++) {
        cudaError_t ec = cudaMemcpyAsync(cv[i].dst, d_in[cv[i].slot],
                                         (size_t)cv[i].n * sizeof(float),
                                         cudaMemcpyDeviceToDevice, (cudaStream_t)0);
        if (ec != cudaSuccess) fprintf(stderr, "[memcpy] i=%d err=%d\n", i, (int)ec);
    }

    // ---- round GEMM weights to tf32 in place (idempotent) ----
    float* wbufs[9] = {qk, kk, vk, ok, pwup, pwdown, gatek, upk, downk};
    int    wns[9]   = {SZ_QK, SZ_KK, SZ_KK, SZ_QK, SZ_PWUP, SZ_QK, SZ_X, SZ_X, SZ_X};
    for (int i = 0; i < 9; i++)
        tf32ify_kernel<<<(wns[i] + 255) / 256, 256>>>(wbufs[i], wns[i]);
    dbg("stage+cvt");

    // ---- attention block ----
    rmsnorm_kernel<<<MROWS, 256>>>(x, attn_ns, p_h);
    tgemm_kernel<0><<<dim3(DD / BNT, MROWS / BMT), 256, TG_SMEM_BYTES>>>(p_h, qk, p_qtmp, nullptr, nullptr, MROWS, DD, DD, DD);
    tgemm_kernel<0><<<dim3((KVH * HDIM) / BNT, MROWS / BMT), 256, TG_SMEM_BYTES>>>(p_h, kk, p_ktmp, nullptr, nullptr, MROWS, KVH * HDIM, DD, DD);
    tgemm_kernel<0><<<dim3((KVH * HDIM) / BNT, MROWS / BMT), 256, TG_SMEM_BYTES>>>(p_h, vk, p_vtmp, nullptr, nullptr, MROWS, KVH * HDIM, DD, DD);
    dbg("qkv");
    qkpost_kernel<<<(BB * TT * HH) / 8, 256>>>(p_qtmp, qns, cosp, sinp, p_q, HH);
    qkpost_kernel<<<(BB * TT * KVH) / 8, 256>>>(p_ktmp, kns, cosp, sinp, p_k, KVH);
    vtrans_kernel<<<(BB * TT * KVH * HDIM) / 256, 256>>>();
    flash_kernel<<<dim3(TT / 64, BB * HH), 256, FA_SMEM_FLOATS * 4>>>();
    dbg("flash");
    tgemm_kernel<1><<<dim3(DD / BNT, MROWS / BMT), 256, TG_SMEM_BYTES>>>(p_attn, ok, p_res, x, nullptr, MROWS, DD, DD, DD);
    dbg("oproj");

    // ---- conv block ----
    rmsnorm_kernel<<<MROWS, 256>>>(p_res, conv_ns, p_h);
    tgemm_kernel<0><<<dim3((2 * DD) / BNT, MROWS / BMT), 256, TG_SMEM_BYTES>>>(p_h, pwup, p_u, nullptr, nullptr, MROWS, 2 * DD, DD, DD);
    glu_kernel<<<(MROWS * DD) / 256, 256>>>();
    dwconv_kernel<<<(BB * TT * DD) / 256, 256>>>(dwk);
    rmsnorm_kernel<<<MROWS, 256>>>(p_c, cin_ns, p_h);
    tgemm_kernel<1><<<dim3(DD / BNT, MROWS / BMT), 256, TG_SMEM_BYTES>>>(p_h, pwdown, p_res, p_res, nullptr, MROWS, DD, DD, DD);
    dbg("conv");

    // ---- FFN block ----
    rmsnorm_kernel<<<MROWS, 256>>>(p_res, ffn_ns, p_h);
    tgemm_kernel<2><<<dim3(DFF / BNT, MROWS / BMT), 256, TG_SMEM_BYTES>>>(p_h, gatek, p_gate, nullptr, nullptr, MROWS, DFF, DD, DD);
    tgemm_kernel<3><<<dim3(DFF / BNT, MROWS / BMT), 256, TG_SMEM_BYTES>>>(p_h, upk, p_ff, nullptr, p_gate, MROWS, DFF, DD, DD);
    dbg("gateup");
    tgemm_kernel<1><<<dim3(DD / BNT, MROWS / BMT), 256, TG_SMEM_BYTES>>>(p_ff,        downk,             p_res, p_res, nullptr, MROWS, DD, 1024, DFF);
    tgemm_kernel<4><<<dim3(DD / BNT, MROWS / BMT), 256, TG_SMEM_BYTES>>>(p_ff + 1024, downk + 1024 * DD, p_res, nullptr, nullptr, MROWS, DD, 1024, DFF);
    tgemm_kernel<4><<<dim3(DD / BNT, MROWS / BMT), 256, TG_SMEM_BYTES>>>(p_ff + 2048, downk + 2048 * DD, p_res, nullptr, nullptr, MROWS, DD, 1024, DFF);
    tgemm_kernel<4><<<dim3(DD / BNT, MROWS / BMT), 256, TG_SMEM_BYTES>>>(p_ff + 3072, downk + 3072 * DD, p_res, nullptr, nullptr, MROWS, DD, 1024, DFF);
    dbg("down");

    // ---- result -> d_out ----
    cudaError_t eo = cudaMemcpyAsync(d_out, p_res, (size_t)MROWS * DD * sizeof(float),
                                     cudaMemcpyDeviceToDevice, (cudaStream_t)0);
    if (eo != cudaSuccess) fprintf(stderr, "[memcpy] out err=%d\n", (int)eo);
    dbg("memcpy_out");
}

// round 9
// speedup vs baseline: 3.5045x; 1.5220x over previous
#include <cuda_runtime.h>
#include <math.h>
#include <stdint.h>
#include <stdio.h>

#define BB 2
#define TT 2048
#define DD 1024
#define HH 16
#define KVH 4
#define HDIM 64
#define HALF 32
#define DFF 4096
#define KW 15
#define MROWS (BB*TT)   // 4096
#define REP (HH/KVH)    // 4

#define SZ_X    4194304
#define SZ_COS  65536
#define SZ_NS   1024
#define SZ_QK   1048576
#define SZ_KK   262144
#define SZ_HNS  64
#define SZ_PWUP 2097152
#define SZ_DWK  15360

// ----------------- per-input device buffers -----------------
__device__ __align__(256) float w_x   [SZ_X];
__device__ __align__(256) float w_cos [SZ_COS];
__device__ __align__(256) float w_sin [SZ_COS];
__device__ __align__(256) float w_ans [SZ_NS];
__device__ __align__(256) float w_qk  [SZ_QK];
__device__ __align__(256) float w_kk  [SZ_KK];
__device__ __align__(256) float w_vk  [SZ_KK];
__device__ __align__(256) float w_qns [SZ_HNS];
__device__ __align__(256) float w_kns [SZ_HNS];
__device__ __align__(256) float w_ok  [SZ_QK];
__device__ __align__(256) float w_cns [SZ_NS];
__device__ __align__(256) float w_pwup[SZ_PWUP];
__device__ __align__(256) float w_dwk [SZ_DWK];
__device__ __align__(256) float w_cins[SZ_NS];
__device__ __align__(256) float w_pwd [SZ_QK];
__device__ __align__(256) float w_fns [SZ_NS];
__device__ __align__(256) float w_gatew[SZ_X];
__device__ __align__(256) float w_upw  [SZ_X];
__device__ __align__(256) float w_downw[SZ_X];

// ----------------- scratch -----------------
__device__ __align__(256) float g_res [(size_t)MROWS*DD];
__device__ __align__(256) float g_h   [(size_t)MROWS*DD];
__device__ __align__(256) float g_qtmp[(size_t)MROWS*DD];
__device__ __align__(256) float g_ktmp[(size_t)MROWS*KVH*HDIM];
__device__ __align__(256) float g_vtmp[(size_t)MROWS*KVH*HDIM];
__device__ __align__(256) float g_q   [(size_t)BB*HH*TT*HDIM];
__device__ __align__(256) float g_k   [(size_t)BB*KVH*TT*HDIM];
__device__ __align__(256) float g_v   [(size_t)BB*KVH*TT*HDIM];
__device__ __align__(256) float g_attn[(size_t)MROWS*DD];
__device__ __align__(256) float g_u   [(size_t)MROWS*2*DD];
__device__ __align__(256) float g_g   [(size_t)MROWS*DD];
__device__ __align__(256) float g_c   [(size_t)MROWS*DD];
__device__ __align__(256) float g_gate[(size_t)MROWS*DFF];
__device__ __align__(256) float g_ff  [(size_t)MROWS*DFF];

// ----------------- tf32 helpers -----------------
__device__ __forceinline__ float to_tf32(float x) {
    uint32_t u;
    asm("cvt.rna.tf32.f32 %0, %1;" : "=r"(u) : "f"(x));
    return __uint_as_float(u);
}

__global__ void __launch_bounds__(256) tf32ify_kernel(float* p, int n) {
    int i = blockIdx.x * blockDim.x + threadIdx.x;
    if (i < n) p[i] = to_tf32(p[i]);
}

#define MMA_TF32(acc, a, b0, b1)                                              \
    asm volatile(                                                             \
        "mma.sync.aligned.m16n8k8.row.col.f32.tf32.tf32.f32 "                 \
        "{%0,%1,%2,%3}, {%4,%5,%6,%7}, {%8,%9}, {%0,%1,%2,%3};"               \
        : "+f"((acc)[0]), "+f"((acc)[1]), "+f"((acc)[2]), "+f"((acc)[3])      \
        : "r"((a)[0]), "r"((a)[1]), "r"((a)[2]), "r"((a)[3]),                 \
          "r"(b0), "r"(b1))

// ----------------- zcRMS over D=1024 (tf32-rounded out: feeds GEMM A) -----------------
__global__ void __launch_bounds__(256) rmsnorm_kernel(const float* __restrict__ in,
                               const float* __restrict__ scale,
                               float* __restrict__ out) {
    size_t row = blockIdx.x;
    const float* xr = in + row * DD;
    float* orow = out + row * DD;
    int tid = threadIdx.x;
    float v[4];
    float ss = 0.f;
#pragma unroll
    for (int i = 0; i < 4; i++) { v[i] = xr[tid + i * 256]; ss += v[i] * v[i]; }
    __shared__ float red[256];
    red[tid] = ss; __syncthreads();
    for (int s = 128; s > 0; s >>= 1) { if (tid < s) red[tid] += red[tid + s]; __syncthreads(); }
    float inv = rsqrtf(red[0] / (float)DD + 1e-6f);
#pragma unroll
    for (int i = 0; i < 4; i++) {
        int c = tid + i * 256;
        orow[c] = to_tf32((1.0f + scale[c]) * v[i] * inv);
    }
}

// ----------------- tf32 tensor-core GEMM -----------------
#define BMT 128
#define BNT 128
#define BKT 32
#define ASTRIDE (BKT+4)
#define BSTRIDE (BNT+4)
#define STAGE_FLOATS (BMT*ASTRIDE + BKT*BSTRIDE)
#define TG_SMEM_BYTES (2*STAGE_FLOATS*4)

__device__ __forceinline__ void cp16(uint32_t dst, const void* src) {
    asm volatile("cp.async.cg.shared.global [%0], [%1], 16;" :: "r"(dst), "l"(src));
}

template <int MODE>
__global__ void __launch_bounds__(256) tgemm_kernel(
    const float* __restrict__ A, const float* __restrict__ W,
    float* __restrict__ C, const float* __restrict__ res, const float* __restrict__ other,
    int M, int N, int K, int lda)
{
    extern __shared__ float sm[];
    int tid = threadIdx.x;
    int lane = tid & 31, warp = tid >> 5;
    int warp_m = warp >> 2;
    int warp_n = warp & 3;
    int m0 = blockIdx.y * BMT, n0 = blockIdx.x * BNT;
    const uint32_t s_u32 = (uint32_t)__cvta_generic_to_shared(sm);

    float acc[4][4][4];
#pragma unroll
    for (int mt = 0; mt < 4; mt++)
#pragma unroll
        for (int nt = 0; nt < 4; nt++)
#pragma unroll
            for (int r = 0; r < 4; r++) acc[mt][nt][r] = 0.f;

#define TG_ISSUE(s, k0) do {                                                          \
    uint32_t ab_ = s_u32 + (s) * (STAGE_FLOATS * 4);                                  \
    _Pragma("unroll")                                                                 \
    for (int j_ = 0; j_ < 4; j_++) {                                                  \
        int idx_ = j_ * 256 + tid; int r_ = idx_ >> 3, ch_ = idx_ & 7;                \
        cp16(ab_ + (uint32_t)(r_ * ASTRIDE + ch_ * 4) * 4,                            \
             A + (size_t)(m0 + r_) * lda + (k0) + ch_ * 4);                           \
    }                                                                                 \
    uint32_t bb_ = ab_ + BMT * ASTRIDE * 4;                                           \
    _Pragma("unroll")                                                                 \
    for (int j_ = 0; j_ < 4; j_++) {                                                  \
        int idx_ = j_ * 256 + tid; int r_ = idx_ >> 5, ch_ = idx_ & 31;               \
        cp16(bb_ + (uint32_t)(r_ * BSTRIDE + ch_ * 4) * 4,                            \
             W + (size_t)((k0) + r_) * N + n0 + ch_ * 4);                             \
    }                                                                                 \
    asm volatile("cp.async.commit_group;" ::: "memory");                              \
} while (0)

    int nk = K / BKT;
    TG_ISSUE(0, 0);

    for (int kt = 0; kt < nk; kt++) {
        int cur = kt & 1;
        asm volatile("cp.async.wait_group 0;" ::: "memory");
        __syncthreads();
        if (kt + 1 < nk) TG_ISSUE(cur ^ 1, (kt + 1) * BKT);

        uint32_t a_row = s_u32 + cur * (STAGE_FLOATS * 4)
                       + (uint32_t)((warp_m * 64 + (lane & 15)) * ASTRIDE + (lane >> 4) * 4) * 4;
        const float* BsF = sm + cur * STAGE_FLOATS + BMT * ASTRIDE;

#pragma unroll
        for (int kk = 0; kk < 4; kk++) {
            uint32_t a[4][4];
#pragma unroll
            for (int mt = 0; mt < 4; mt++) {
                uint32_t addr = a_row + (uint32_t)(mt * 16 * ASTRIDE + kk * 8) * 4;
                asm volatile("ldmatrix.sync.aligned.m8n8.x4.shared.b16 {%0,%1,%2,%3}, [%4];"
                             : "=r"(a[mt][0]), "=r"(a[mt][1]), "=r"(a[mt][2]), "=r"(a[mt][3])
                             : "r"(addr));
            }
            uint32_t b[4][2];
            int brow = kk * 8 + (lane & 3);
            int bcol = warp_n * 32 + (lane >> 2);
#pragma unroll
            for (int nt = 0; nt < 4; nt++) {
                b[nt][0] = __float_as_uint(BsF[brow * BSTRIDE + bcol + nt * 8]);
                b[nt][1] = __float_as_uint(BsF[(brow + 4) * BSTRIDE + bcol + nt * 8]);
            }
#pragma unroll
            for (int mt = 0; mt < 4; mt++)
#pragma unroll
                for (int nt = 0; nt < 4; nt++)
                    MMA_TF32(acc[mt][nt], a[mt], b[nt][0], b[nt][1]);
        }
    }
#undef TG_ISSUE

    int g = lane >> 2;
    int cb = 2 * (lane & 3);
#pragma unroll
    for (int mt = 0; mt < 4; mt++) {
#pragma unroll
        for (int nt = 0; nt < 4; nt++) {
            int col = n0 + warp_n * 32 + nt * 8 + cb;
#pragma unroll
            for (int half = 0; half < 2; half++) {
                int row = m0 + warp_m * 64 + mt * 16 + g + half * 8;
                size_t o0 = (size_t)row * N + col;
#pragma unroll
                for (int jj = 0; jj < 2; jj++) {
                    float v = acc[mt][nt][half * 2 + jj];
                    size_t o = o0 + jj;
                    if (MODE == 1) v += res[o];
                    if (MODE == 2) v = fmaxf(v, 0.f);
                    if (MODE == 3) v = to_tf32(fmaxf(v, 0.f) * other[o]);
                    if (MODE == 4) v += C[o];
                    C[o] = v;
                }
            }
        }
    }
}

// ----------------- per-head zcRMS(64) + RoPE (tf32-rounded: feeds flash mma) -----------------
__global__ void __launch_bounds__(256) qkpost_kernel(const float* __restrict__ tmp, const float* __restrict__ ns,
                              const float* __restrict__ cosp, const float* __restrict__ sinp,
                              float* __restrict__ out, int NH) {
    int warp = threadIdx.x >> 5, lane = threadIdx.x & 31;
    int row = blockIdx.x * 8 + warp;
    if (row >= BB * TT * NH) return;
    int hh = row % NH;
    int bt = row / NH;
    int t = bt % TT;
    int b = bt / TT;
    const float* xin = tmp + ((size_t)bt * NH + hh) * HDIM;
    float x1 = xin[lane], x2 = xin[lane + 32];
    float ss = x1 * x1 + x2 * x2;
#pragma unroll
    for (int o = 16; o > 0; o >>= 1) ss += __shfl_xor_sync(0xffffffffu, ss, o);
    float inv = rsqrtf(ss / (float)HDIM + 1e-6f);
    float y1 = (1.0f + ns[lane]) * x1 * inv;
    float y2 = (1.0f + ns[lane + 32]) * x2 * inv;
    float c = cosp[t * HALF + lane];
    float s = sinp[t * HALF + lane];
    float* orow = out + ((size_t)(b * NH + hh) * TT + t) * HDIM;
    orow[lane]      = to_tf32(y1 * c - y2 * s);
    orow[lane + 32] = to_tf32(y2 * c + y1 * s);
}

// ----------------- v transpose (tf32-rounded: feeds flash mma B) -----------------
__global__ void __launch_bounds__(256) vtrans_kernel() {
    int idx = blockIdx.x * blockDim.x + threadIdx.x;
    if (idx >= BB * TT * KVH * HDIM) return;
    int d = idx & 63;
    int r = idx >> 6;
    int hh = r % KVH;
    int bt = r / KVH;
    int t = bt % TT;
    int b = bt / TT;
    g_v[((size_t)(b * KVH + hh) * TT + t) * HDIM + d] = to_tf32(g_vtmp[idx]);
}

// ----------------- tensor-core flash attention -----------------
// CTA: 128 Q rows x 64-key tiles, 8 warps (warp = 16 rows), tf32 mma QK^T and PV.
#define FQR 128
#define FKV 64
#define KSTRIDE 68                      // 4g+q mod 32 bijective for K B-frags
#define VSTRIDE 72                      // 8q+g mod 32 bijective for V B-frags
#define FT_STAGE (FKV*KSTRIDE + FKV*VSTRIDE)   // 4352+4608 = 8960 floats
#define FT_SMEM_BYTES (2*FT_STAGE*4)           // 71680 B

__global__ void __launch_bounds__(256) flash_tc_kernel() {
    extern __shared__ float sm[];
    int tid = threadIdx.x;
    int lane = tid & 31, warp = tid >> 5;
    int g = lane >> 2, q = lane & 3;
    int z = blockIdx.y;                 // b*H + h
    int b = z / HH, h = z % HH;
    const float* Q  = g_q + (size_t)z * TT * HDIM;
    const float* Kp = g_k + (size_t)(b * KVH + h / REP) * TT * HDIM;
    const float* Vp = g_v + (size_t)(b * KVH + h / REP) * TT * HDIM;
    int i0 = blockIdx.x * FQR;
    const uint32_t s_u32 = (uint32_t)__cvta_generic_to_shared(sm);

    // preload Q A-fragments (loop-invariant; already tf32-rounded)
    uint32_t qa[8][4];
    {
        const float* Qw = Q + (size_t)(i0 + warp * 16) * HDIM;
#pragma unroll
        for (int k8 = 0; k8 < 8; k8++) {
            qa[k8][0] = __float_as_uint(Qw[(size_t)g * HDIM + k8 * 8 + q]);
            qa[k8][1] = __float_as_uint(Qw[(size_t)(g + 8) * HDIM + k8 * 8 + q]);
            qa[k8][2] = __float_as_uint(Qw[(size_t)g * HDIM + k8 * 8 + q + 4]);
            qa[k8][3] = __float_as_uint(Qw[(size_t)(g + 8) * HDIM + k8 * 8 + q + 4]);
        }
    }

    float o[8][4];
#pragma unroll
    for (int dt = 0; dt < 8; dt++)
#pragma unroll
        for (int r = 0; r < 4; r++) o[dt][r] = 0.f;
    float m0 = -1e30f, m1 = -1e30f, l0 = 0.f, l1 = 0.f;

#define FT_ISSUE(s, j0) do {                                                          \
    uint32_t kb_ = s_u32 + (s) * (FT_STAGE * 4);                                      \
    _Pragma("unroll")                                                                 \
    for (int j_ = 0; j_ < 4; j_++) {                                                  \
        int idx_ = j_ * 256 + tid; int r_ = idx_ >> 4, ch_ = idx_ & 15;               \
        cp16(kb_ + (uint32_t)(r_ * KSTRIDE + ch_ * 4) * 4,                            \
             Kp + (size_t)((j0) + r_) * HDIM + ch_ * 4);                              \
    }                                                                                 \
    uint32_t vb_ = kb_ + FKV * KSTRIDE * 4;                                           \
    _Pragma("unroll")                                                                 \
    for (int j_ = 0; j_ < 4; j_++) {                                                  \
        int idx_ = j_ * 256 + tid; int r_ = idx_ >> 4, ch_ = idx_ & 15;               \
        cp16(vb_ + (uint32_t)(r_ * VSTRIDE + ch_ * 4) * 4,                            \
             Vp + (size_t)((j0) + r_) * HDIM + ch_ * 4);                              \
    }                                                                                 \
    asm volatile("cp.async.commit_group;" ::: "memory");                              \
} while (0)

    FT_ISSUE(0, 0);

    for (int it = 0; it < TT / FKV; it++) {
        int cur = it & 1;
        asm volatile("cp.async.wait_group 0;" ::: "memory");
        __syncthreads();
        if (it + 1 < TT / FKV) FT_ISSUE(cur ^ 1, (it + 1) * FKV);

        const float* Ks = sm + cur * FT_STAGE;
        const float* Vs = Ks + FKV * KSTRIDE;

        // S = Q K^T (64 keys = 8 n-tiles)
        float s[8][4];
#pragma unroll
        for (int t = 0; t < 8; t++)
#pragma unroll
            for (int r = 0; r < 4; r++) s[t][r] = 0.f;
#pragma unroll
        for (int k8 = 0; k8 < 8; k8++)
#pragma unroll
            for (int t = 0; t < 8; t++) {
                uint32_t b0 = __float_as_uint(Ks[(8 * t + g) * KSTRIDE + k8 * 8 + q]);
                uint32_t b1 = __float_as_uint(Ks[(8 * t + g) * KSTRIDE + k8 * 8 + q + 4]);
                MMA_TF32(s[t], qa[k8], b0, b1);
            }

        // online softmax (rows g and g+8 owned fully by this warp's quad)
        float mx0 = -1e30f, mx1 = -1e30f;
#pragma unroll
        for (int t = 0; t < 8; t++) {
            s[t][0] *= 0.125f; s[t][1] *= 0.125f; s[t][2] *= 0.125f; s[t][3] *= 0.125f;
            mx0 = fmaxf(mx0, fmaxf(s[t][0], s[t][1]));
            mx1 = fmaxf(mx1, fmaxf(s[t][2], s[t][3]));
        }
#pragma unroll
        for (int off = 1; off < 4; off <<= 1) {
            mx0 = fmaxf(mx0, __shfl_xor_sync(0xffffffffu, mx0, off));
            mx1 = fmaxf(mx1, __shfl_xor_sync(0xffffffffu, mx1, off));
        }
        float mn0 = fmaxf(m0, mx0), mn1 = fmaxf(m1, mx1);
        float al0 = __expf(m0 - mn0), al1 = __expf(m1 - mn1);
        m0 = mn0; m1 = mn1;
        float rs0 = 0.f, rs1 = 0.f;
#pragma unroll
        for (int t = 0; t < 8; t++) {
            s[t][0] = __expf(s[t][0] - mn0);
            s[t][1] = __expf(s[t][1] - mn0);
            s[t][2] = __expf(s[t][2] - mn1);
            s[t][3] = __expf(s[t][3] - mn1);
            rs0 += s[t][0] + s[t][1];
            rs1 += s[t][2] + s[t][3];
        }
#pragma unroll
        for (int off = 1; off < 4; off <<= 1) {
            rs0 += __shfl_xor_sync(0xffffffffu, rs0, off);
            rs1 += __shfl_xor_sync(0xffffffffu, rs1, off);
        }
        l0 = l0 * al0 + rs0;
        l1 = l1 * al1 + rs1;
#pragma unroll
        for (int dt = 0; dt < 8; dt++) {
            o[dt][0] *= al0; o[dt][1] *= al0;
            o[dt][2] *= al1; o[dt][3] *= al1;
        }

        // O += P V : per k-tile, gather P A-frag from S acc via intra-quad shuffles
        int base = lane & ~3;
        int src0 = base | (q >> 1);
        int src1 = base | ((q >> 1) + 2);
#pragma unroll
        for (int kt = 0; kt < 8; kt++) {
            float v00 = __shfl_sync(0xffffffffu, s[kt][0], src0);
            float v01 = __shfl_sync(0xffffffffu, s[kt][1], src0);
            float v20 = __shfl_sync(0xffffffffu, s[kt][2], src0);
            float v21 = __shfl_sync(0xffffffffu, s[kt][3], src0);
            float w00 = __shfl_sync(0xffffffffu, s[kt][0], src1);
            float w01 = __shfl_sync(0xffffffffu, s[kt][1], src1);
            float w20 = __shfl_sync(0xffffffffu, s[kt][2], src1);
            float w21 = __shfl_sync(0xffffffffu, s[kt][3], src1);
            uint32_t pa[4];
            pa[0] = __float_as_uint(to_tf32((q & 1) ? v01 : v00));
            pa[1] = __float_as_uint(to_tf32((q & 1) ? v21 : v20));
            pa[2] = __float_as_uint(to_tf32((q & 1) ? w01 : w00));
            pa[3] = __float_as_uint(to_tf32((q & 1) ? w21 : w20));
#pragma unroll
            for (int dt = 0; dt < 8; dt++) {
                uint32_t b0 = __float_as_uint(Vs[(8 * kt + q) * VSTRIDE + 8 * dt + g]);
                uint32_t b1 = __float_as_uint(Vs[(8 * kt + q + 4) * VSTRIDE + 8 * dt + g]);
                MMA_TF32(o[dt], pa, b0, b1);
            }
        }
    }
#undef FT_ISSUE

    // epilogue: rows i0+16w+g, i0+16w+g+8; write (B,T,H,HD), tf32-rounded (feeds o-proj)
    float inv0 = 1.0f / l0, inv1 = 1.0f / l1;
    int r0 = i0 + warp * 16 + g;
    int r1 = r0 + 8;
    float* out0 = g_attn + ((size_t)(b * TT + r0) * HH + h) * HDIM;
    float* out1 = g_attn + ((size_t)(b * TT + r1) * HH + h) * HDIM;
#pragma unroll
    for (int dt = 0; dt < 8; dt++) {
        int c0 = 8 * dt + 2 * q;
        out0[c0]     = to_tf32(o[dt][0] * inv0);
        out0[c0 + 1] = to_tf32(o[dt][1] * inv0);
        out1[c0]     = to_tf32(o[dt][2] * inv1);
        out1[c0 + 1] = to_tf32(o[dt][3] * inv1);
    }
}

// ----------------- GLU -----------------
__global__ void __launch_bounds__(256) glu_kernel() {
    int idx = blockIdx.x * blockDim.x + threadIdx.x;
    if (idx >= MROWS * DD) return;
    int c = idx & (DD - 1);
    int r = idx >> 10;
    float u1 = g_u[(size_t)r * (2 * DD) + c];
    float u2 = g_u[(size_t)r * (2 * DD) + DD + c];
    g_g[idx] = u1 / (1.0f + __expf(-u2));
}

// ----------------- depthwise conv KW=15 SAME -----------------
__global__ void __launch_bounds__(256) dwconv_kernel(const float* __restrict__ dw) {
    int idx = blockIdx.x * blockDim.x + threadIdx.x;
    if (idx >= BB * TT * DD) return;
    int d = idx & (DD - 1);
    int t = (idx >> 10) & (TT - 1);
    int b = idx >> 21;
    float acc = 0.f;
#pragma unroll
    for (int w = 0; w < KW; w++) {
        int tt = t + w - 7;
        if (tt >= 0 && tt < TT)
            acc += g_g[((size_t)(b * TT + tt)) * DD + d] * dw[w * DD + d];
    }
    g_c[idx] = acc;
}

// ----------------- staged-sync diagnostics (no-op while capturing) -----------------
static void dbg(const char* name) {
    cudaStreamCaptureStatus st = cudaStreamCaptureStatusActive;
    cudaError_t qe = cudaStreamIsCapturing((cudaStream_t)0, &st);
    if (qe != cudaSuccess || st != cudaStreamCaptureStatusNone) return;
    cudaError_t e = cudaStreamSynchronize((cudaStream_t)0);
    fprintf(stderr, "[dbg] %-12s -> %s\n", name, cudaGetErrorString(e));
}

extern "C" void kernel_launch(void* const* d_in, const int* in_sizes, int n_in,
                              void* d_out, int out_size) {
    if (n_in < 20) { fprintf(stderr, "[klaunch] unexpected n_in=%d\n", n_in); return; }

    float *x, *cosp, *sinp, *attn_ns, *qk, *kk, *vk, *qns, *kns, *ok;
    float *conv_ns, *pwup, *dwk, *cin_ns, *pwdown, *ffn_ns, *gatek, *upk, *downk;
    float *p_res, *p_h, *p_qtmp, *p_ktmp, *p_vtmp, *p_q, *p_k, *p_attn, *p_u, *p_c, *p_gate, *p_ff;
    cudaGetSymbolAddress((void**)&x, w_x);
    cudaGetSymbolAddress((void**)&cosp, w_cos);
    cudaGetSymbolAddress((void**)&sinp, w_sin);
    cudaGetSymbolAddress((void**)&attn_ns, w_ans);
    cudaGetSymbolAddress((void**)&qk, w_qk);
    cudaGetSymbolAddress((void**)&kk, w_kk);
    cudaGetSymbolAddress((void**)&vk, w_vk);
    cudaGetSymbolAddress((void**)&qns, w_qns);
    cudaGetSymbolAddress((void**)&kns, w_kns);
    cudaGetSymbolAddress((void**)&ok, w_ok);
    cudaGetSymbolAddress((void**)&conv_ns, w_cns);
    cudaGetSymbolAddress((void**)&pwup, w_pwup);
    cudaGetSymbolAddress((void**)&dwk, w_dwk);
    cudaGetSymbolAddress((void**)&cin_ns, w_cins);
    cudaGetSymbolAddress((void**)&pwdown, w_pwd);
    cudaGetSymbolAddress((void**)&ffn_ns, w_fns);
    cudaGetSymbolAddress((void**)&gatek, w_gatew);
    cudaGetSymbolAddress((void**)&upk, w_upw);
    cudaError_t es = cudaGetSymbolAddress((void**)&downk, w_downw);
    if (es != cudaSuccess) { fprintf(stderr, "[sym] downw err=%d\n", (int)es); return; }
    cudaGetSymbolAddress((void**)&p_res, g_res);
    cudaGetSymbolAddress((void**)&p_h, g_h);
    cudaGetSymbolAddress((void**)&p_qtmp, g_qtmp);
    cudaGetSymbolAddress((void**)&p_ktmp, g_ktmp);
    cudaGetSymbolAddress((void**)&p_vtmp, g_vtmp);
    cudaGetSymbolAddress((void**)&p_q, g_q);
    cudaGetSymbolAddress((void**)&p_k, g_k);
    cudaGetSymbolAddress((void**)&p_attn, g_attn);
    cudaGetSymbolAddress((void**)&p_u, g_u);
    cudaGetSymbolAddress((void**)&p_c, g_c);
    cudaGetSymbolAddress((void**)&p_gate, g_gate);
    es = cudaGetSymbolAddress((void**)&p_ff, g_ff);
    if (es != cudaSuccess) { fprintf(stderr, "[sym] g_ff err=%d\n", (int)es); return; }

    cudaFuncSetAttribute(flash_tc_kernel, cudaFuncAttributeMaxDynamicSharedMemorySize, FT_SMEM_BYTES);
    cudaFuncSetAttribute(tgemm_kernel<0>, cudaFuncAttributeMaxDynamicSharedMemorySize, TG_SMEM_BYTES);
    cudaFuncSetAttribute(tgemm_kernel<1>, cudaFuncAttributeMaxDynamicSharedMemorySize, TG_SMEM_BYTES);
    cudaFuncSetAttribute(tgemm_kernel<2>, cudaFuncAttributeMaxDynamicSharedMemorySize, TG_SMEM_BYTES);
    cudaFuncSetAttribute(tgemm_kernel<3>, cudaFuncAttributeMaxDynamicSharedMemorySize, TG_SMEM_BYTES);
    es = cudaFuncSetAttribute(tgemm_kernel<4>, cudaFuncAttributeMaxDynamicSharedMemorySize, TG_SMEM_BYTES);
    if (es != cudaSuccess) fprintf(stderr, "[klaunch] smem attr err=%d\n", (int)es);

    // ---- stage inputs (D2D memcpy; dict order, mask at slot 1 skipped) ----
    struct { int slot; float* dst; int n; } cv[19] = {
        {0, x, SZ_X},        {2, cosp, SZ_COS},  {3, sinp, SZ_COS},
        {4, attn_ns, SZ_NS}, {5, qk, SZ_QK},     {6, kk, SZ_KK},
        {7, vk, SZ_KK},      {8, qns, SZ_HNS},   {9, kns, SZ_HNS},
        {10, ok, SZ_QK},     {11, conv_ns, SZ_NS}, {12, pwup, SZ_PWUP},
        {13, dwk, SZ_DWK},   {14, cin_ns, SZ_NS},  {15, pwdown, SZ_QK},
        {16, ffn_ns, SZ_NS}, {17, gatek, SZ_X},    {18, upk, SZ_X},
        {19, downk, SZ_X}
    };
    for (int i = 0; i < 19; i++) {
        cudaError_t ec = cudaMemcpyAsync(cv[i].dst, d_in[cv[i].slot],
                                         (size_t)cv[i].n * sizeof(float),
                                         cudaMemcpyDeviceToDevice, (cudaStream_t)0);
        if (ec != cudaSuccess) fprintf(stderr, "[memcpy] i=%d err=%d\n", i, (int)ec);
    }

    // ---- round GEMM weights to tf32 in place (idempotent) ----
    float* wbufs[9] = {qk, kk, vk, ok, pwup, pwdown, gatek, upk, downk};
    int    wns[9]   = {SZ_QK, SZ_KK, SZ_KK, SZ_QK, SZ_PWUP, SZ_QK, SZ_X, SZ_X, SZ_X};
    for (int i = 0; i < 9; i++)
        tf32ify_kernel<<<(wns[i] + 255) / 256, 256>>>(wbufs[i], wns[i]);
    dbg("stage+cvt");

    // ---- attention block ----
    rmsnorm_kernel<<<MROWS, 256>>>(x, attn_ns, p_h);
    tgemm_kernel<0><<<dim3(DD / BNT, MROWS / BMT), 256, TG_SMEM_BYTES>>>(p_h, qk, p_qtmp, nullptr, nullptr, MROWS, DD, DD, DD);
    tgemm_kernel<0><<<dim3((KVH * HDIM) / BNT, MROWS / BMT), 256, TG_SMEM_BYTES>>>(p_h, kk, p_ktmp, nullptr, nullptr, MROWS, KVH * HDIM, DD, DD);
    tgemm_kernel<0><<<dim3((KVH * HDIM) / BNT, MROWS / BMT), 256, TG_SMEM_BYTES>>>(p_h, vk, p_vtmp, nullptr, nullptr, MROWS, KVH * HDIM, DD, DD);
    qkpost_kernel<<<(BB * TT * HH) / 8, 256>>>(p_qtmp, qns, cosp, sinp, p_q, HH);
    qkpost_kernel<<<(BB * TT * KVH) / 8, 256>>>(p_ktmp, kns, cosp, sinp, p_k, KVH);
    vtrans_kernel<<<(BB * TT * KVH * HDIM) / 256, 256>>>();
    flash_tc_kernel<<<dim3(TT / FQR, BB * HH), 256, FT_SMEM_BYTES>>>();
    dbg("flash");
    tgemm_kernel<1><<<dim3(DD / BNT, MROWS / BMT), 256, TG_SMEM_BYTES>>>(p_attn, ok, p_res, x, nullptr, MROWS, DD, DD, DD);
    dbg("oproj");

    // ---- conv block ----
    rmsnorm_kernel<<<MROWS, 256>>>(p_res, conv_ns, p_h);
    tgemm_kernel<0><<<dim3((2 * DD) / BNT, MROWS / BMT), 256, TG_SMEM_BYTES>>>(p_h, pwup, p_u, nullptr, nullptr, MROWS, 2 * DD, DD, DD);
    glu_kernel<<<(MROWS * DD) / 256, 256>>>();
    dwconv_kernel<<<(BB * TT * DD) / 256, 256>>>(dwk);
    rmsnorm_kernel<<<MROWS, 256>>>(p_c, cin_ns, p_h);
    tgemm_kernel<1><<<dim3(DD / BNT, MROWS / BMT), 256, TG_SMEM_BYTES>>>(p_h, pwdown, p_res, p_res, nullptr, MROWS, DD, DD, DD);
    dbg("conv");

    // ---- FFN block ----
    rmsnorm_kernel<<<MROWS, 256>>>(p_res, ffn_ns, p_h);
    tgemm_kernel<2><<<dim3(DFF / BNT, MROWS / BMT), 256, TG_SMEM_BYTES>>>(p_h, gatek, p_gate, nullptr, nullptr, MROWS, DFF, DD, DD);
    tgemm_kernel<3><<<dim3(DFF / BNT, MROWS / BMT), 256, TG_SMEM_BYTES>>>(p_h, upk, p_ff, nullptr, p_gate, MROWS, DFF, DD, DD);
    tgemm_kernel<1><<<dim3(DD / BNT, MROWS / BMT), 256, TG_SMEM_BYTES>>>(p_ff,        downk,             p_res, p_res, nullptr, MROWS, DD, 1024, DFF);
    tgemm_kernel<4><<<dim3(DD / BNT, MROWS / BMT), 256, TG_SMEM_BYTES>>>(p_ff + 1024, downk + 1024 * DD, p_res, nullptr, nullptr, MROWS, DD, 1024, DFF);
    tgemm_kernel<4><<<dim3(DD / BNT, MROWS / BMT), 256, TG_SMEM_BYTES>>>(p_ff + 2048, downk + 2048 * DD, p_res, nullptr, nullptr, MROWS, DD, 1024, DFF);
    tgemm_kernel<4><<<dim3(DD / BNT, MROWS / BMT), 256, TG_SMEM_BYTES>>>(p_ff + 3072, downk + 3072 * DD, p_res, nullptr, nullptr, MROWS, DD, 1024, DFF);
    dbg("ffn");

    // ---- result -> d_out ----
    cudaError_t eo = cudaMemcpyAsync(d_out, p_res, (size_t)MROWS * DD * sizeof(float),
                                     cudaMemcpyDeviceToDevice, (cudaStream_t)0);
    if (eo != cudaSuccess) fprintf(stderr, "[memcpy] out err=%d\n", (int)eo);
    dbg("memcpy_out");
}

// round 10
// speedup vs baseline: 5.1289x; 1.4635x over previous
#include <cuda_runtime.h>
#include <cuda_fp16.h>
#include <math.h>
#include <stdint.h>
#include <stdio.h>

#define BB 2
#define TT 2048
#define DD 1024
#define HH 16
#define KVH 4
#define HDIM 64
#define HALF 32
#define DFF 4096
#define KW 15
#define MROWS (BB*TT)   // 4096
#define REP (HH/KVH)    // 4

#define SZ_X    4194304
#define SZ_COS  65536
#define SZ_NS   1024
#define SZ_QK   1048576
#define SZ_KK   262144
#define SZ_HNS  64
#define SZ_PWUP 2097152
#define SZ_DWK  15360

// ----------------- fp32 staging for inputs -----------------
__device__ __align__(256) float w_x   [SZ_X];
__device__ __align__(256) float w_cos [SZ_COS];
__device__ __align__(256) float w_sin [SZ_COS];
__device__ __align__(256) float w_ans [SZ_NS];
__device__ __align__(256) float w_qk  [SZ_QK];
__device__ __align__(256) float w_kk  [SZ_KK];
__device__ __align__(256) float w_vk  [SZ_KK];
__device__ __align__(256) float w_qns [SZ_HNS];
__device__ __align__(256) float w_kns [SZ_HNS];
__device__ __align__(256) float w_ok  [SZ_QK];
__device__ __align__(256) float w_cns [SZ_NS];
__device__ __align__(256) float w_pwup[SZ_PWUP];
__device__ __align__(256) float w_dwk [SZ_DWK];
__device__ __align__(256) float w_cins[SZ_NS];
__device__ __align__(256) float w_pwd [SZ_QK];
__device__ __align__(256) float w_fns [SZ_NS];
__device__ __align__(256) float w_gatew[SZ_X];
__device__ __align__(256) float w_upw  [SZ_X];
__device__ __align__(256) float w_downw[SZ_X];

// ----------------- fp16 transposed weights [N][K] -----------------
__device__ __align__(256) __half wh_qk  [SZ_QK];
__device__ __align__(256) __half wh_kk  [SZ_KK];
__device__ __align__(256) __half wh_vk  [SZ_KK];
__device__ __align__(256) __half wh_ok  [SZ_QK];
__device__ __align__(256) __half wh_pwup[SZ_PWUP];
__device__ __align__(256) __half wh_pwd [SZ_QK];
__device__ __align__(256) __half wh_gate[SZ_X];
__device__ __align__(256) __half wh_up  [SZ_X];
__device__ __align__(256) __half wh_down[SZ_X];

// ----------------- scratch -----------------
__device__ __align__(256) float  g_res [(size_t)MROWS*DD];
__device__ __align__(256) __half g_hh  [(size_t)MROWS*DD];        // rmsnorm out (GEMM A)
__device__ __align__(256) float  g_qtmp[(size_t)MROWS*DD];
__device__ __align__(256) float  g_ktmp[(size_t)MROWS*KVH*HDIM];
__device__ __align__(256) float  g_vtmp[(size_t)MROWS*KVH*HDIM];
__device__ __align__(256) __half g_qh  [(size_t)BB*HH*TT*HDIM];   // (B,H,T,HD) half
__device__ __align__(256) __half g_kh  [(size_t)BB*KVH*TT*HDIM];  // (B,KVH,T,HD) half
__device__ __align__(256) __half g_vth [(size_t)BB*KVH*HDIM*TT];  // (B,KVH,HD,T) half (transposed)
__device__ __align__(256) __half g_attnh[(size_t)MROWS*DD];       // flash out (B,T,H,HD) half
__device__ __align__(256) float  g_u   [(size_t)MROWS*2*DD];
__device__ __align__(256) float  g_g   [(size_t)MROWS*DD];
__device__ __align__(256) float  g_c   [(size_t)MROWS*DD];
__device__ __align__(256) float  g_gate[(size_t)MROWS*DFF];
__device__ __align__(256) __half g_ffh [(size_t)MROWS*DFF];       // relu*relu out (down A)

__device__ __forceinline__ uint32_t packh2(float a, float b) {
    __half2 h = __floats2half2_rn(a, b);
    return *reinterpret_cast<uint32_t*>(&h);
}

#define MMA_F16(acc, a, b0, b1)                                               \
    asm volatile(                                                             \
        "mma.sync.aligned.m16n8k16.row.col.f32.f16.f16.f32 "                  \
        "{%0,%1,%2,%3}, {%4,%5,%6,%7}, {%8,%9}, {%0,%1,%2,%3};"               \
        : "+f"((acc)[0]), "+f"((acc)[1]), "+f"((acc)[2]), "+f"((acc)[3])      \
        : "r"((a)[0]), "r"((a)[1]), "r"((a)[2]), "r"((a)[3]),                 \
          "r"(b0), "r"(b1))

__device__ __forceinline__ void cp16(uint32_t dst, const void* src) {
    asm volatile("cp.async.cg.shared.global [%0], [%1], 16;" :: "r"(dst), "l"(src));
}

// ----------------- weight transpose+convert: fp32 [K][N] -> half [N][K] -----------------
__global__ void __launch_bounds__(256) wtrans_kernel(const float* __restrict__ in,
                                                     __half* __restrict__ out, int K, int N) {
    __shared__ float t[32][33];
    int kb = blockIdx.y * 32, nb = blockIdx.x * 32;
    int tx = threadIdx.x, ty = threadIdx.y;
#pragma unroll
    for (int i = ty; i < 32; i += 8)
        t[i][tx] = in[(size_t)(kb + i) * N + nb + tx];
    __syncthreads();
#pragma unroll
    for (int i = ty; i < 32; i += 8)
        out[(size_t)(nb + i) * K + kb + tx] = __float2half(t[tx][i]);
}

// ----------------- zcRMS over D=1024, half out -----------------
__global__ void __launch_bounds__(256) rmsnorm_kernel(const float* __restrict__ in,
                               const float* __restrict__ scale,
                               __half* __restrict__ out) {
    size_t row = blockIdx.x;
    const float* xr = in + row * DD;
    __half* orow = out + row * DD;
    int tid = threadIdx.x;
    float v[4];
    float ss = 0.f;
#pragma unroll
    for (int i = 0; i < 4; i++) { v[i] = xr[tid + i * 256]; ss += v[i] * v[i]; }
    __shared__ float red[256];
    red[tid] = ss; __syncthreads();
    for (int s = 128; s > 0; s >>= 1) { if (tid < s) red[tid] += red[tid + s]; __syncthreads(); }
    float inv = rsqrtf(red[0] / (float)DD + 1e-6f);
#pragma unroll
    for (int i = 0; i < 4; i++) {
        int c = tid + i * 256;
        orow[c] = __float2half((1.0f + scale[c]) * v[i] * inv);
    }
}

// ----------------- fp16 tensor-core GEMM -----------------
// C = A[M,K(lda)] @ Wt^T (Wt: half [N][K], ldb) ; MODE 0:AB 1:res+AB 2:relu 3:half(relu*other) 4:C+=AB
#define BMT 128
#define BNT 128
#define BKT 32
#define ASTR 40                                  // halves; 80B rows
#define BSTR 40
#define STAGE_H (BMT*ASTR + BNT*BSTR)            // 10240 halves = 20480 B
#define TG_SMEM_BYTES (2*STAGE_H*2)              // 40960 B

template <int MODE>
__global__ void __launch_bounds__(256) tgemm_kernel(
    const __half* __restrict__ A, const __half* __restrict__ Wt,
    float* __restrict__ C, __half* __restrict__ Ch,
    const float* __restrict__ res, const float* __restrict__ other,
    int M, int N, int K, int lda, int ldb)
{
    extern __shared__ __half smh[];
    int tid = threadIdx.x;
    int lane = tid & 31, warp = tid >> 5;
    int g = lane >> 2, q = lane & 3;
    int warp_m = warp >> 2;
    int warp_n = warp & 3;
    int m0 = blockIdx.y * BMT, n0 = blockIdx.x * BNT;
    const uint32_t s_u32 = (uint32_t)__cvta_generic_to_shared(smh);

    float acc[4][4][4];
#pragma unroll
    for (int mt = 0; mt < 4; mt++)
#pragma unroll
        for (int nt = 0; nt < 4; nt++)
#pragma unroll
            for (int r = 0; r < 4; r++) acc[mt][nt][r] = 0.f;

#define TG_ISSUE(s, k0) do {                                                          \
    uint32_t ab_ = s_u32 + (s) * (STAGE_H * 2);                                       \
    _Pragma("unroll")                                                                 \
    for (int j_ = 0; j_ < 2; j_++) {                                                  \
        int idx_ = j_ * 256 + tid; int r_ = idx_ >> 2, ch_ = idx_ & 3;                \
        cp16(ab_ + (uint32_t)(r_ * ASTR + ch_ * 8) * 2,                               \
             A + (size_t)(m0 + r_) * lda + (k0) + ch_ * 8);                           \
    }                                                                                 \
    uint32_t bb_ = ab_ + BMT * ASTR * 2;                                              \
    _Pragma("unroll")                                                                 \
    for (int j_ = 0; j_ < 2; j_++) {                                                  \
        int idx_ = j_ * 256 + tid; int r_ = idx_ >> 2, ch_ = idx_ & 3;                \
        cp16(bb_ + (uint32_t)(r_ * BSTR + ch_ * 8) * 2,                               \
             Wt + (size_t)(n0 + r_) * ldb + (k0) + ch_ * 8);                          \
    }                                                                                 \
    asm volatile("cp.async.commit_group;" ::: "memory");                              \
} while (0)

    int nk = K / BKT;
    TG_ISSUE(0, 0);

    for (int kt = 0; kt < nk; kt++) {
        int cur = kt & 1;
        asm volatile("cp.async.wait_group 0;" ::: "memory");
        __syncthreads();
        if (kt + 1 < nk) TG_ISSUE(cur ^ 1, (kt + 1) * BKT);

        uint32_t a_row = s_u32 + cur * (STAGE_H * 2)
                       + (uint32_t)((warp_m * 64 + (lane & 15)) * ASTR + (lane >> 4) * 8) * 2;
        const __half* BsH = smh + cur * STAGE_H + BMT * ASTR;

#pragma unroll
        for (int kk = 0; kk < 2; kk++) {       // two k16 steps
            uint32_t a[4][4];
#pragma unroll
            for (int mt = 0; mt < 4; mt++) {
                uint32_t addr = a_row + (uint32_t)(mt * 16 * ASTR + kk * 16) * 2;
                asm volatile("ldmatrix.sync.aligned.m8n8.x4.shared.b16 {%0,%1,%2,%3}, [%4];"
                             : "=r"(a[mt][0]), "=r"(a[mt][1]), "=r"(a[mt][2]), "=r"(a[mt][3])
                             : "r"(addr));
            }
#pragma unroll
            for (int nt = 0; nt < 4; nt++) {
                const __half* bp = BsH + (warp_n * 32 + nt * 8 + g) * BSTR + kk * 16 + 2 * q;
                uint32_t b0 = *reinterpret_cast<const uint32_t*>(bp);
                uint32_t b1 = *reinterpret_cast<const uint32_t*>(bp + 8);
#pragma unroll
                for (int mt = 0; mt < 4; mt++)
                    MMA_F16(acc[mt][nt], a[mt], b0, b1);
            }
        }
    }
#undef TG_ISSUE

    int cb = 2 * q;
#pragma unroll
    for (int mt = 0; mt < 4; mt++) {
#pragma unroll
        for (int nt = 0; nt < 4; nt++) {
            int col = n0 + warp_n * 32 + nt * 8 + cb;
#pragma unroll
            for (int half_ = 0; half_ < 2; half_++) {
                int row = m0 + warp_m * 64 + mt * 16 + g + half_ * 8;
                size_t o0 = (size_t)row * N + col;
#pragma unroll
                for (int jj = 0; jj < 2; jj++) {
                    float v = acc[mt][nt][half_ * 2 + jj];
                    size_t o = o0 + jj;
                    if (MODE == 1) v += res[o];
                    if (MODE == 2) v = fmaxf(v, 0.f);
                    if (MODE == 4) v += C[o];
                    if (MODE == 3) Ch[o] = __float2half(fmaxf(v, 0.f) * other[o]);
                    else           C[o] = v;
                }
            }
        }
    }
}

// ----------------- per-head zcRMS(64) + RoPE, half out -----------------
__global__ void __launch_bounds__(256) qkpost_kernel(const float* __restrict__ tmp, const float* __restrict__ ns,
                              const float* __restrict__ cosp, const float* __restrict__ sinp,
                              __half* __restrict__ out, int NH) {
    int warp = threadIdx.x >> 5, lane = threadIdx.x & 31;
    int row = blockIdx.x * 8 + warp;
    if (row >= BB * TT * NH) return;
    int hh = row % NH;
    int bt = row / NH;
    int t = bt % TT;
    int b = bt / TT;
    const float* xin = tmp + ((size_t)bt * NH + hh) * HDIM;
    float x1 = xin[lane], x2 = xin[lane + 32];
    float ss = x1 * x1 + x2 * x2;
#pragma unroll
    for (int o = 16; o > 0; o >>= 1) ss += __shfl_xor_sync(0xffffffffu, ss, o);
    float inv = rsqrtf(ss / (float)HDIM + 1e-6f);
    float y1 = (1.0f + ns[lane]) * x1 * inv;
    float y2 = (1.0f + ns[lane + 32]) * x2 * inv;
    float c = cosp[t * HALF + lane];
    float s = sinp[t * HALF + lane];
    __half* orow = out + ((size_t)(b * NH + hh) * TT + t) * HDIM;
    orow[lane]      = __float2half(y1 * c - y2 * s);
    orow[lane + 32] = __float2half(y2 * c + y1 * s);
}

// ----------------- v transpose to (B,KVH,HD,T) half -----------------
__global__ void __launch_bounds__(256) vtrans_kernel() {
    int idx = blockIdx.x * blockDim.x + threadIdx.x;
    if (idx >= BB * TT * KVH * HDIM) return;
    int d = idx & 63;
    int r = idx >> 6;
    int hh = r % KVH;
    int bt = r / KVH;
    int t = bt % TT;
    int b = bt / TT;
    g_vth[(((size_t)(b * KVH + hh)) * HDIM + d) * TT + t] = __float2half(g_vtmp[idx]);
}

// ----------------- fp16 tensor-core flash attention -----------------
// CTA: 128 Q rows x 64-key tiles, 8 warps. m16n8k16 for QK^T and PV; P A-frags = packed S accs.
#define FQR 128
#define FKV 64
#define FKSTR 72                               // halves; banks (4g+q) bijective
#define FT_STAGE_H (FKV*FKSTR*2)               // K + V = 9216 halves = 18432 B
#define FT_SMEM_BYTES (2*FT_STAGE_H*2)         // 73728... (2 stages)

__global__ void __launch_bounds__(256) flash_tc_kernel() {
    extern __shared__ __half smh[];
    int tid = threadIdx.x;
    int lane = tid & 31, warp = tid >> 5;
    int g = lane >> 2, q = lane & 3;
    int z = blockIdx.y;
    int b = z / HH, h = z % HH;
    const __half* Q  = g_qh + (size_t)z * TT * HDIM;
    const __half* Kp = g_kh + (size_t)(b * KVH + h / REP) * TT * HDIM;
    const __half* Vt = g_vth + (size_t)(b * KVH + h / REP) * HDIM * TT;
    int i0 = blockIdx.x * FQR;
    const uint32_t s_u32 = (uint32_t)__cvta_generic_to_shared(smh);

    // preload Q A-frags: qa[kk] = {(g,2q),(g+8,2q),(g,2q+8),(g+8,2q+8)} halves pairs
    uint32_t qa[4][4];
    {
        const __half* Qw = Q + (size_t)(i0 + warp * 16) * HDIM;
#pragma unroll
        for (int kk = 0; kk < 4; kk++) {
            qa[kk][0] = *reinterpret_cast<const uint32_t*>(Qw + (size_t)g * HDIM + kk * 16 + 2 * q);
            qa[kk][1] = *reinterpret_cast<const uint32_t*>(Qw + (size_t)(g + 8) * HDIM + kk * 16 + 2 * q);
            qa[kk][2] = *reinterpret_cast<const uint32_t*>(Qw + (size_t)g * HDIM + kk * 16 + 2 * q + 8);
            qa[kk][3] = *reinterpret_cast<const uint32_t*>(Qw + (size_t)(g + 8) * HDIM + kk * 16 + 2 * q + 8);
        }
    }

    float o[8][4];
#pragma unroll
    for (int dt = 0; dt < 8; dt++)
#pragma unroll
        for (int r = 0; r < 4; r++) o[dt][r] = 0.f;
    float m0 = -1e30f, m1 = -1e30f, l0 = 0.f, l1 = 0.f;

#define FT_ISSUE(s, j0) do {                                                          \
    uint32_t kb_ = s_u32 + (s) * (FT_STAGE_H * 2);                                    \
    _Pragma("unroll")                                                                 \
    for (int j_ = 0; j_ < 2; j_++) {                                                  \
        int idx_ = j_ * 256 + tid; int r_ = idx_ >> 3, ch_ = idx_ & 7;                \
        cp16(kb_ + (uint32_t)(r_ * FKSTR + ch_ * 8) * 2,                              \
             Kp + (size_t)((j0) + r_) * HDIM + ch_ * 8);                              \
    }                                                                                 \
    uint32_t vb_ = kb_ + FKV * FKSTR * 2;                                             \
    _Pragma("unroll")                                                                 \
    for (int j_ = 0; j_ < 2; j_++) {                                                  \
        int idx_ = j_ * 256 + tid; int r_ = idx_ >> 3, ch_ = idx_ & 7;                \
        cp16(vb_ + (uint32_t)(r_ * FKSTR + ch_ * 8) * 2,                              \
             Vt + (size_t)r_ * TT + (j0) + ch_ * 8);                                  \
    }                                                                                 \
    asm volatile("cp.async.commit_group;" ::: "memory");                              \
} while (0)

    FT_ISSUE(0, 0);

    for (int it = 0; it < TT / FKV; it++) {
        int cur = it & 1;
        asm volatile("cp.async.wait_group 0;" ::: "memory");
        __syncthreads();
        if (it + 1 < TT / FKV) FT_ISSUE(cur ^ 1, (it + 1) * FKV);

        const __half* Ks = smh + cur * FT_STAGE_H;
        const __half* Vs = Ks + FKV * FKSTR;

        // S = Q K^T (8 n-tiles of 8 keys)
        float s[8][4];
#pragma unroll
        for (int t = 0; t < 8; t++)
#pragma unroll
            for (int r = 0; r < 4; r++) s[t][r] = 0.f;
#pragma unroll
        for (int kk = 0; kk < 4; kk++)
#pragma unroll
            for (int t = 0; t < 8; t++) {
                const __half* kp = Ks + (8 * t + g) * FKSTR + kk * 16 + 2 * q;
                uint32_t b0 = *reinterpret_cast<const uint32_t*>(kp);
                uint32_t b1 = *reinterpret_cast<const uint32_t*>(kp + 8);
                MMA_F16(s[t], qa[kk], b0, b1);
            }

        // online softmax (rows g, g+8; quad reduction)
        float mx0 = -1e30f, mx1 = -1e30f;
#pragma unroll
        for (int t = 0; t < 8; t++) {
            s[t][0] *= 0.125f; s[t][1] *= 0.125f; s[t][2] *= 0.125f; s[t][3] *= 0.125f;
            mx0 = fmaxf(mx0, fmaxf(s[t][0], s[t][1]));
            mx1 = fmaxf(mx1, fmaxf(s[t][2], s[t][3]));
        }
#pragma unroll
        for (int off = 1; off < 4; off <<= 1) {
            mx0 = fmaxf(mx0, __shfl_xor_sync(0xffffffffu, mx0, off));
            mx1 = fmaxf(mx1, __shfl_xor_sync(0xffffffffu, mx1, off));
        }
        float mn0 = fmaxf(m0, mx0), mn1 = fmaxf(m1, mx1);
        float al0 = __expf(m0 - mn0), al1 = __expf(m1 - mn1);
        m0 = mn0; m1 = mn1;
        float rs0 = 0.f, rs1 = 0.f;
#pragma unroll
        for (int t = 0; t < 8; t++) {
            s[t][0] = __expf(s[t][0] - mn0);
            s[t][1] = __expf(s[t][1] - mn0);
            s[t][2] = __expf(s[t][2] - mn1);
            s[t][3] = __expf(s[t][3] - mn1);
            rs0 += s[t][0] + s[t][1];
            rs1 += s[t][2] + s[t][3];
        }
#pragma unroll
        for (int off = 1; off < 4; off <<= 1) {
            rs0 += __shfl_xor_sync(0xffffffffu, rs0, off);
            rs1 += __shfl_xor_sync(0xffffffffu, rs1, off);
        }
        l0 = l0 * al0 + rs0;
        l1 = l1 * al1 + rs1;
#pragma unroll
        for (int dt = 0; dt < 8; dt++) {
            o[dt][0] *= al0; o[dt][1] *= al0;
            o[dt][2] *= al1; o[dt][3] *= al1;
        }

        // O += P V : P A-frags are packed S accumulators (no shuffles)
#pragma unroll
        for (int kt = 0; kt < 4; kt++) {
            uint32_t pa[4];
            pa[0] = packh2(s[2 * kt][0],     s[2 * kt][1]);
            pa[1] = packh2(s[2 * kt][2],     s[2 * kt][3]);
            pa[2] = packh2(s[2 * kt + 1][0], s[2 * kt + 1][1]);
            pa[3] = packh2(s[2 * kt + 1][2], s[2 * kt + 1][3]);
#pragma unroll
            for (int dt = 0; dt < 8; dt++) {
                const __half* vp = Vs + (8 * dt + g) * FKSTR + kt * 16 + 2 * q;
                uint32_t b0 = *reinterpret_cast<const uint32_t*>(vp);
                uint32_t b1 = *reinterpret_cast<const uint32_t*>(vp + 8);
                MMA_F16(o[dt], pa, b0, b1);
            }
        }
    }
#undef FT_ISSUE

    float inv0 = 1.0f / l0, inv1 = 1.0f / l1;
    int r0 = i0 + warp * 16 + g;
    int r1 = r0 + 8;
    __half* out0 = g_attnh + ((size_t)(b * TT + r0) * HH + h) * HDIM;
    __half* out1 = g_attnh + ((size_t)(b * TT + r1) * HH + h) * HDIM;
#pragma unroll
    for (int dt = 0; dt < 8; dt++) {
        int c0 = 8 * dt + 2 * q;
        out0[c0]     = __float2half(o[dt][0] * inv0);
        out0[c0 + 1] = __float2half(o[dt][1] * inv0);
        out1[c0]     = __float2half(o[dt][2] * inv1);
        out1[c0 + 1] = __float2half(o[dt][3] * inv1);
    }
}

// ----------------- GLU -----------------
__global__ void __launch_bounds__(256) glu_kernel() {
    int idx = blockIdx.x * blockDim.x + threadIdx.x;
    if (idx >= MROWS * DD) return;
    int c = idx & (DD - 1);
    int r = idx >> 10;
    float u1 = g_u[(size_t)r * (2 * DD) + c];
    float u2 = g_u[(size_t)r * (2 * DD) + DD + c];
    g_g[idx] = u1 / (1.0f + __expf(-u2));
}

// ----------------- depthwise conv KW=15 SAME -----------------
__global__ void __launch_bounds__(256) dwconv_kernel(const float* __restrict__ dw) {
    int idx = blockIdx.x * blockDim.x + threadIdx.x;
    if (idx >= BB * TT * DD) return;
    int d = idx & (DD - 1);
    int t = (idx >> 10) & (TT - 1);
    int b = idx >> 21;
    float acc = 0.f;
#pragma unroll
    for (int w = 0; w < KW; w++) {
        int tt = t + w - 7;
        if (tt >= 0 && tt < TT)
            acc += g_g[((size_t)(b * TT + tt)) * DD + d] * dw[w * DD + d];
    }
    g_c[idx] = acc;
}

// ----------------- staged-sync diagnostics (no-op while capturing) -----------------
static void dbg(const char* name) {
    cudaStreamCaptureStatus st = cudaStreamCaptureStatusActive;
    cudaError_t qe = cudaStreamIsCapturing((cudaStream_t)0, &st);
    if (qe != cudaSuccess || st != cudaStreamCaptureStatusNone) return;
    cudaError_t e = cudaStreamSynchronize((cudaStream_t)0);
    fprintf(stderr, "[dbg] %-12s -> %s\n", name, cudaGetErrorString(e));
}

extern "C" void kernel_launch(void* const* d_in, const int* in_sizes, int n_in,
                              void* d_out, int out_size) {
    if (n_in < 20) { fprintf(stderr, "[klaunch] unexpected n_in=%d\n", n_in); return; }

    float *x, *cosp, *sinp, *attn_ns, *qk, *kk, *vk, *qns, *kns, *ok;
    float *conv_ns, *pwup, *dwk, *cin_ns, *pwdown, *ffn_ns, *gatek, *upk, *downk;
    float *p_res, *p_qtmp, *p_ktmp, *p_vtmp, *p_u, *p_c, *p_gate;
    __half *ph_h, *ph_qk, *ph_kk, *ph_vk, *ph_ok, *ph_pwup, *ph_pwd, *ph_gate, *ph_up, *ph_down;
    __half *ph_attn, *ph_ff;
    cudaGetSymbolAddress((void**)&x, w_x);
    cudaGetSymbolAddress((void**)&cosp, w_cos);
    cudaGetSymbolAddress((void**)&sinp, w_sin);
    cudaGetSymbolAddress((void**)&attn_ns, w_ans);
    cudaGetSymbolAddress((void**)&qk, w_qk);
    cudaGetSymbolAddress((void**)&kk, w_kk);
    cudaGetSymbolAddress((void**)&vk, w_vk);
    cudaGetSymbolAddress((void**)&qns, w_qns);
    cudaGetSymbolAddress((void**)&kns, w_kns);
    cudaGetSymbolAddress((void**)&ok, w_ok);
    cudaGetSymbolAddress((void**)&conv_ns, w_cns);
    cudaGetSymbolAddress((void**)&pwup, w_pwup);
    cudaGetSymbolAddress((void**)&dwk, w_dwk);
    cudaGetSymbolAddress((void**)&cin_ns, w_cins);
    cudaGetSymbolAddress((void**)&pwdown, w_pwd);
    cudaGetSymbolAddress((void**)&ffn_ns, w_fns);
    cudaGetSymbolAddress((void**)&gatek, w_gatew);
    cudaGetSymbolAddress((void**)&upk, w_upw);
    cudaGetSymbolAddress((void**)&downk, w_downw);
    cudaGetSymbolAddress((void**)&ph_qk, wh_qk);
    cudaGetSymbolAddress((void**)&ph_kk, wh_kk);
    cudaGetSymbolAddress((void**)&ph_vk, wh_vk);
    cudaGetSymbolAddress((void**)&ph_ok, wh_ok);
    cudaGetSymbolAddress((void**)&ph_pwup, wh_pwup);
    cudaGetSymbolAddress((void**)&ph_pwd, wh_pwd);
    cudaGetSymbolAddress((void**)&ph_gate, wh_gate);
    cudaGetSymbolAddress((void**)&ph_up, wh_up);
    cudaGetSymbolAddress((void**)&ph_down, wh_down);
    cudaGetSymbolAddress((void**)&p_res, g_res);
    cudaGetSymbolAddress((void**)&ph_h, g_hh);
    cudaGetSymbolAddress((void**)&p_qtmp, g_qtmp);
    cudaGetSymbolAddress((void**)&p_ktmp, g_ktmp);
    cudaGetSymbolAddress((void**)&p_vtmp, g_vtmp);
    cudaGetSymbolAddress((void**)&ph_attn, g_attnh);
    cudaGetSymbolAddress((void**)&p_u, g_u);
    cudaGetSymbolAddress((void**)&p_c, g_c);
    cudaGetSymbolAddress((void**)&p_gate, g_gate);
    cudaError_t es = cudaGetSymbolAddress((void**)&ph_ff, g_ffh);
    if (es != cudaSuccess) { fprintf(stderr, "[sym] g_ffh err=%d\n", (int)es); return; }
    __half *ph_q, *ph_k, *ph_vt;
    cudaGetSymbolAddress((void**)&ph_q, g_qh);
    cudaGetSymbolAddress((void**)&ph_k, g_kh);
    es = cudaGetSymbolAddress((void**)&ph_vt, g_vth);
    if (es != cudaSuccess) { fprintf(stderr, "[sym] g_vth err=%d\n", (int)es); return; }

    cudaFuncSetAttribute(flash_tc_kernel, cudaFuncAttributeMaxDynamicSharedMemorySize, FT_SMEM_BYTES);
    cudaFuncSetAttribute(tgemm_kernel<0>, cudaFuncAttributeMaxDynamicSharedMemorySize, TG_SMEM_BYTES);
    cudaFuncSetAttribute(tgemm_kernel<1>, cudaFuncAttributeMaxDynamicSharedMemorySize, TG_SMEM_BYTES);
    cudaFuncSetAttribute(tgemm_kernel<2>, cudaFuncAttributeMaxDynamicSharedMemorySize, TG_SMEM_BYTES);
    cudaFuncSetAttribute(tgemm_kernel<3>, cudaFuncAttributeMaxDynamicSharedMemorySize, TG_SMEM_BYTES);
    es = cudaFuncSetAttribute(tgemm_kernel<4>, cudaFuncAttributeMaxDynamicSharedMemorySize, TG_SMEM_BYTES);
    if (es != cudaSuccess) fprintf(stderr, "[klaunch] smem attr err=%d\n", (int)es);

    // ---- stage inputs (D2D memcpy; dict order, mask at slot 1 skipped) ----
    struct { int slot; float* dst; int n; } cv[19] = {
        {0, x, SZ_X},        {2, cosp, SZ_COS},  {3, sinp, SZ_COS},
        {4, attn_ns, SZ_NS}, {5, qk, SZ_QK},     {6, kk, SZ_KK},
        {7, vk, SZ_KK},      {8, qns, SZ_HNS},   {9, kns, SZ_HNS},
        {10, ok, SZ_QK},     {11, conv_ns, SZ_NS}, {12, pwup, SZ_PWUP},
        {13, dwk, SZ_DWK},   {14, cin_ns, SZ_NS},  {15, pwdown, SZ_QK},
        {16, ffn_ns, SZ_NS}, {17, gatek, SZ_X},    {18, upk, SZ_X},
        {19, downk, SZ_X}
    };
    for (int i = 0; i < 19; i++) {
        cudaError_t ec = cudaMemcpyAsync(cv[i].dst, d_in[cv[i].slot],
                                         (size_t)cv[i].n * sizeof(float),
                                         cudaMemcpyDeviceToDevice, (cudaStream_t)0);
        if (ec != cudaSuccess) fprintf(stderr, "[memcpy] i=%d err=%d\n", i, (int)ec);
    }

    // ---- transpose+convert weights to half [N][K] ----
    struct { const float* in; __half* out; int K; int N; } tw[9] = {
        {qk, ph_qk, DD, DD},       {kk, ph_kk, DD, 256},   {vk, ph_vk, DD, 256},
        {ok, ph_ok, DD, DD},       {pwup, ph_pwup, DD, 2 * DD}, {pwdown, ph_pwd, DD, DD},
        {gatek, ph_gate, DD, DFF}, {upk, ph_up, DD, DFF},  {downk, ph_down, DFF, DD}
    };
    for (int i = 0; i < 9; i++)
        wtrans_kernel<<<dim3(tw[i].N / 32, tw[i].K / 32), dim3(32, 8)>>>(tw[i].in, tw[i].out, tw[i].K, tw[i].N);
    dbg("stage+wtrans");

    // ---- attention block ----
    rmsnorm_kernel<<<MROWS, 256>>>(x, attn_ns, ph_h);
    tgemm_kernel<0><<<dim3(DD / BNT, MROWS / BMT), 256, TG_SMEM_BYTES>>>(ph_h, ph_qk, p_qtmp, nullptr, nullptr, nullptr, MROWS, DD, DD, DD, DD);
    tgemm_kernel<0><<<dim3(256 / BNT, MROWS / BMT), 256, TG_SMEM_BYTES>>>(ph_h, ph_kk, p_ktmp, nullptr, nullptr, nullptr, MROWS, 256, DD, DD, DD);
    tgemm_kernel<0><<<dim3(256 / BNT, MROWS / BMT), 256, TG_SMEM_BYTES>>>(ph_h, ph_vk, p_vtmp, nullptr, nullptr, nullptr, MROWS, 256, DD, DD, DD);
    dbg("qkv");
    qkpost_kernel<<<(BB * TT * HH) / 8, 256>>>(p_qtmp, qns, cosp, sinp, ph_q, HH);
    qkpost_kernel<<<(BB * TT * KVH) / 8, 256>>>(p_ktmp, kns, cosp, sinp, ph_k, KVH);
    vtrans_kernel<<<(BB * TT * KVH * HDIM) / 256, 256>>>();
    flash_tc_kernel<<<dim3(TT / FQR, BB * HH), 256, FT_SMEM_BYTES>>>();
    dbg("flash");
    tgemm_kernel<1><<<dim3(DD / BNT, MROWS / BMT), 256, TG_SMEM_BYTES>>>(ph_attn, ph_ok, p_res, nullptr, x, nullptr, MROWS, DD, DD, DD, DD);
    dbg("oproj");

    // ---- conv block ----
    rmsnorm_kernel<<<MROWS, 256>>>(p_res, conv_ns, ph_h);
    tgemm_kernel<0><<<dim3((2 * DD) / BNT, MROWS / BMT), 256, TG_SMEM_BYTES>>>(ph_h, ph_pwup, p_u, nullptr, nullptr, nullptr, MROWS, 2 * DD, DD, DD, DD);
    glu_kernel<<<(MROWS * DD) / 256, 256>>>();
    dwconv_kernel<<<(BB * TT * DD) / 256, 256>>>(dwk);
    rmsnorm_kernel<<<MROWS, 256>>>(p_c, cin_ns, ph_h);
    tgemm_kernel<1><<<dim3(DD / BNT, MROWS / BMT), 256, TG_SMEM_BYTES>>>(ph_h, ph_pwd, p_res, nullptr, p_res, nullptr, MROWS, DD, DD, DD, DD);
    dbg("conv");

    // ---- FFN block ----
    rmsnorm_kernel<<<MROWS, 256>>>(p_res, ffn_ns, ph_h);
    tgemm_kernel<2><<<dim3(DFF / BNT, MROWS / BMT), 256, TG_SMEM_BYTES>>>(ph_h, ph_gate, p_gate, nullptr, nullptr, nullptr, MROWS, DFF, DD, DD, DD);
    tgemm_kernel<3><<<dim3(DFF / BNT, MROWS / BMT), 256, TG_SMEM_BYTES>>>(ph_h, ph_up, nullptr, ph_ff, nullptr, p_gate, MROWS, DFF, DD, DD, DD);
    tgemm_kernel<1><<<dim3(DD / BNT, MROWS / BMT), 256, TG_SMEM_BYTES>>>(ph_ff,        ph_down,        p_res, nullptr, p_res, nullptr, MROWS, DD, 1024, DFF, DFF);
    tgemm_kernel<4><<<dim3(DD / BNT, MROWS / BMT), 256, TG_SMEM_BYTES>>>(ph_ff + 1024, ph_down + 1024, p_res, nullptr, nullptr, nullptr, MROWS, DD, 1024, DFF, DFF);
    tgemm_kernel<4><<<dim3(DD / BNT, MROWS / BMT), 256, TG_SMEM_BYTES>>>(ph_ff + 2048, ph_down + 2048, p_res, nullptr, nullptr, nullptr, MROWS, DD, 1024, DFF, DFF);
    tgemm_kernel<4><<<dim3(DD / BNT, MROWS / BMT), 256, TG_SMEM_BYTES>>>(ph_ff + 3072, ph_down + 3072, p_res, nullptr, nullptr, nullptr, MROWS, DD, 1024, DFF, DFF);
    dbg("ffn");

    // ---- result -> d_out ----
    cudaError_t eo = cudaMemcpyAsync(d_out, p_res, (size_t)MROWS * DD * sizeof(float),
                                     cudaMemcpyDeviceToDevice, (cudaStream_t)0);
    if (eo != cudaSuccess) fprintf(stderr, "[memcpy] out err=%d\n", (int)eo);
    dbg("memcpy_out");
}

// round 11
// speedup vs baseline: 5.3914x; 1.0512x over previous
#include <cuda_runtime.h>
#include <cuda_fp16.h>
#include <math.h>
#include <stdint.h>
#include <stdio.h>

#define BB 2
#define TT 2048
#define DD 1024
#define HH 16
#define KVH 4
#define HDIM 64
#define HALF 32
#define DFF 4096
#define KW 15
#define MROWS (BB*TT)   // 4096
#define REP (HH/KVH)    // 4

#define SZ_X    4194304
#define SZ_COS  65536
#define SZ_NS   1024
#define SZ_QK   1048576
#define SZ_KK   262144
#define SZ_HNS  64
#define SZ_PWUP 2097152
#define SZ_DWK  15360

// ----------------- fp32 staging for inputs -----------------
__device__ __align__(256) float w_x   [SZ_X];
__device__ __align__(256) float w_cos [SZ_COS];
__device__ __align__(256) float w_sin [SZ_COS];
__device__ __align__(256) float w_ans [SZ_NS];
__device__ __align__(256) float w_qk  [SZ_QK];
__device__ __align__(256) float w_kk  [SZ_KK];
__device__ __align__(256) float w_vk  [SZ_KK];
__device__ __align__(256) float w_qns [SZ_HNS];
__device__ __align__(256) float w_kns [SZ_HNS];
__device__ __align__(256) float w_ok  [SZ_QK];
__device__ __align__(256) float w_cns [SZ_NS];
__device__ __align__(256) float w_pwup[SZ_PWUP];
__device__ __align__(256) float w_dwk [SZ_DWK];
__device__ __align__(256) float w_cins[SZ_NS];
__device__ __align__(256) float w_pwd [SZ_QK];
__device__ __align__(256) float w_fns [SZ_NS];
__device__ __align__(256) float w_gatew[SZ_X];
__device__ __align__(256) float w_upw  [SZ_X];
__device__ __align__(256) float w_downw[SZ_X];

// ----------------- fp16 transposed weights [N][K] (possibly column-interleaved) -----------------
__device__ __align__(256) __half wh_qk  [SZ_QK];
__device__ __align__(256) __half wh_kk  [SZ_KK];
__device__ __align__(256) __half wh_vk  [SZ_KK];
__device__ __align__(256) __half wh_ok  [SZ_QK];
__device__ __align__(256) __half wh_pwup[SZ_PWUP];     // interleaved u1/u2
__device__ __align__(256) __half wh_pwd [SZ_QK];
__device__ __align__(256) __half wh_gu  [2*SZ_X];      // interleaved gate/up [8192][1024]
__device__ __align__(256) __half wh_down[SZ_X];

// ----------------- scratch -----------------
__device__ __align__(256) float  g_res [(size_t)MROWS*DD];
__device__ __align__(256) __half g_hh  [(size_t)MROWS*DD];        // rmsnorm out (GEMM A)
__device__ __align__(256) __half g_qtmph[(size_t)MROWS*DD];
__device__ __align__(256) __half g_ktmph[(size_t)MROWS*KVH*HDIM];
__device__ __align__(256) __half g_vtmph[(size_t)MROWS*KVH*HDIM];
__device__ __align__(256) __half g_qh  [(size_t)BB*HH*TT*HDIM];
__device__ __align__(256) __half g_kh  [(size_t)BB*KVH*TT*HDIM];
__device__ __align__(256) __half g_vth [(size_t)BB*KVH*HDIM*TT];  // (B,KVH,HD,T)
__device__ __align__(256) __half g_attnh[(size_t)MROWS*DD];
__device__ __align__(256) __half g_gh  [(size_t)MROWS*DD];        // glu out (half)
__device__ __align__(256) float  g_c   [(size_t)MROWS*DD];        // conv out
__device__ __align__(256) __half g_ffh [(size_t)MROWS*DFF];       // relu*relu out

__device__ __forceinline__ uint32_t packh2(float a, float b) {
    __half2 h = __floats2half2_rn(a, b);
    return *reinterpret_cast<uint32_t*>(&h);
}

#define MMA_F16(acc, a, b0, b1)                                               \
    asm volatile(                                                             \
        "mma.sync.aligned.m16n8k16.row.col.f32.f16.f16.f32 "                  \
        "{%0,%1,%2,%3}, {%4,%5,%6,%7}, {%8,%9}, {%0,%1,%2,%3};"               \
        : "+f"((acc)[0]), "+f"((acc)[1]), "+f"((acc)[2]), "+f"((acc)[3])      \
        : "r"((a)[0]), "r"((a)[1]), "r"((a)[2]), "r"((a)[3]),                 \
          "r"(b0), "r"(b1))

__device__ __forceinline__ void cp16(uint32_t dst, const void* src) {
    asm volatile("cp.async.cg.shared.global [%0], [%1], 16;" :: "r"(dst), "l"(src));
}

// ----------------- weight transpose+convert: fp32 [K][N] -> half [rowmap(n)][K] -----------------
// imode 0: r=n ; 1: n<N/2 -> 2n else 2(n-N/2)+1 ; 2: r=2n ; 3: r=2n+1
__global__ void __launch_bounds__(256) wtrans_kernel(const float* __restrict__ in,
                                                     __half* __restrict__ out, int K, int N, int imode) {
    __shared__ float t[32][33];
    int kb = blockIdx.y * 32, nb = blockIdx.x * 32;
    int tx = threadIdx.x, ty = threadIdx.y;
#pragma unroll
    for (int i = ty; i < 32; i += 8)
        t[i][tx] = in[(size_t)(kb + i) * N + nb + tx];
    __syncthreads();
#pragma unroll
    for (int i = ty; i < 32; i += 8) {
        int n = nb + i;
        int r = (imode == 0) ? n
              : (imode == 1) ? ((n < N / 2) ? 2 * n : 2 * (n - N / 2) + 1)
              : (imode == 2) ? 2 * n : 2 * n + 1;
        out[(size_t)r * K + kb + tx] = __float2half(t[tx][i]);
    }
}

// ----------------- zcRMS over D=1024, half out -----------------
__global__ void __launch_bounds__(256) rmsnorm_kernel(const float* __restrict__ in,
                               const float* __restrict__ scale,
                               __half* __restrict__ out) {
    size_t row = blockIdx.x;
    const float* xr = in + row * DD;
    __half* orow = out + row * DD;
    int tid = threadIdx.x;
    float v[4];
    float ss = 0.f;
#pragma unroll
    for (int i = 0; i < 4; i++) { v[i] = xr[tid + i * 256]; ss += v[i] * v[i]; }
    __shared__ float red[256];
    red[tid] = ss; __syncthreads();
    for (int s = 128; s > 0; s >>= 1) { if (tid < s) red[tid] += red[tid + s]; __syncthreads(); }
    float inv = rsqrtf(red[0] / (float)DD + 1e-6f);
#pragma unroll
    for (int i = 0; i < 4; i++) {
        int c = tid + i * 256;
        orow[c] = __float2half((1.0f + scale[c]) * v[i] * inv);
    }
}

// ----------------- fp16 tensor-core GEMM -----------------
// MODE 1: C f32 = res+AB ; 4: C f32 += AB ; 5: Ch[M,N/2] = u1*sigmoid(u2) (paired cols)
// 7: Ch[M,N] = AB ; 6: Ch[M,N/2] = relu(even)*relu(odd)
#define BMT 128
#define BNT 128
#define BKT 32
#define ASTR 40
#define BSTR 40
#define STAGE_H (BMT*ASTR + BNT*BSTR)
#define TG_SMEM_BYTES (2*STAGE_H*2)

template <int MODE>
__global__ void __launch_bounds__(256) tgemm_kernel(
    const __half* __restrict__ A, const __half* __restrict__ Wt,
    float* __restrict__ C, __half* __restrict__ Ch,
    const float* __restrict__ res,
    int M, int N, int K, int lda, int ldb)
{
    extern __shared__ __half smh[];
    int tid = threadIdx.x;
    int lane = tid & 31, warp = tid >> 5;
    int g = lane >> 2, q = lane & 3;
    int warp_m = warp >> 2;
    int warp_n = warp & 3;
    int m0 = blockIdx.y * BMT, n0 = blockIdx.x * BNT;
    const uint32_t s_u32 = (uint32_t)__cvta_generic_to_shared(smh);

    float acc[4][4][4];
#pragma unroll
    for (int mt = 0; mt < 4; mt++)
#pragma unroll
        for (int nt = 0; nt < 4; nt++)
#pragma unroll
            for (int r = 0; r < 4; r++) acc[mt][nt][r] = 0.f;

#define TG_ISSUE(s, k0) do {                                                          \
    uint32_t ab_ = s_u32 + (s) * (STAGE_H * 2);                                       \
    _Pragma("unroll")                                                                 \
    for (int j_ = 0; j_ < 2; j_++) {                                                  \
        int idx_ = j_ * 256 + tid; int r_ = idx_ >> 2, ch_ = idx_ & 3;                \
        cp16(ab_ + (uint32_t)(r_ * ASTR + ch_ * 8) * 2,                               \
             A + (size_t)(m0 + r_) * lda + (k0) + ch_ * 8);                           \
    }                                                                                 \
    uint32_t bb_ = ab_ + BMT * ASTR * 2;                                              \
    _Pragma("unroll")                                                                 \
    for (int j_ = 0; j_ < 2; j_++) {                                                  \
        int idx_ = j_ * 256 + tid; int r_ = idx_ >> 2, ch_ = idx_ & 3;                \
        cp16(bb_ + (uint32_t)(r_ * BSTR + ch_ * 8) * 2,                               \
             Wt + (size_t)(n0 + r_) * ldb + (k0) + ch_ * 8);                          \
    }                                                                                 \
    asm volatile("cp.async.commit_group;" ::: "memory");                              \
} while (0)

    int nk = K / BKT;
    TG_ISSUE(0, 0);

    for (int kt = 0; kt < nk; kt++) {
        int cur = kt & 1;
        asm volatile("cp.async.wait_group 0;" ::: "memory");
        __syncthreads();
        if (kt + 1 < nk) TG_ISSUE(cur ^ 1, (kt + 1) * BKT);

        uint32_t a_row = s_u32 + cur * (STAGE_H * 2)
                       + (uint32_t)((warp_m * 64 + (lane & 15)) * ASTR + (lane >> 4) * 8) * 2;
        const __half* BsH = smh + cur * STAGE_H + BMT * ASTR;

#pragma unroll
        for (int kk = 0; kk < 2; kk++) {
            uint32_t a[4][4];
#pragma unroll
            for (int mt = 0; mt < 4; mt++) {
                uint32_t addr = a_row + (uint32_t)(mt * 16 * ASTR + kk * 16) * 2;
                asm volatile("ldmatrix.sync.aligned.m8n8.x4.shared.b16 {%0,%1,%2,%3}, [%4];"
                             : "=r"(a[mt][0]), "=r"(a[mt][1]), "=r"(a[mt][2]), "=r"(a[mt][3])
                             : "r"(addr));
            }
#pragma unroll
            for (int nt = 0; nt < 4; nt++) {
                const __half* bp = BsH + (warp_n * 32 + nt * 8 + g) * BSTR + kk * 16 + 2 * q;
                uint32_t b0 = *reinterpret_cast<const uint32_t*>(bp);
                uint32_t b1 = *reinterpret_cast<const uint32_t*>(bp + 8);
#pragma unroll
                for (int mt = 0; mt < 4; mt++)
                    MMA_F16(acc[mt][nt], a[mt], b0, b1);
            }
        }
    }
#undef TG_ISSUE

#pragma unroll
    for (int mt = 0; mt < 4; mt++) {
#pragma unroll
        for (int nt = 0; nt < 4; nt++) {
            int colbase = n0 + warp_n * 32 + nt * 8;
#pragma unroll
            for (int half_ = 0; half_ < 2; half_++) {
                int row = m0 + warp_m * 64 + mt * 16 + g + half_ * 8;
                float v0 = acc[mt][nt][half_ * 2 + 0];
                float v1 = acc[mt][nt][half_ * 2 + 1];
                if (MODE == 5) {
                    size_t o = (size_t)row * (N >> 1) + (colbase >> 1) + q;
                    Ch[o] = __float2half(v0 / (1.0f + __expf(-v1)));
                } else if (MODE == 6) {
                    size_t o = (size_t)row * (N >> 1) + (colbase >> 1) + q;
                    Ch[o] = __float2half(fmaxf(v0, 0.f) * fmaxf(v1, 0.f));
                } else if (MODE == 7) {
                    size_t o = (size_t)row * N + colbase + 2 * q;
                    Ch[o]     = __float2half(v0);
                    Ch[o + 1] = __float2half(v1);
                } else {
                    size_t o = (size_t)row * N + colbase + 2 * q;
                    if (MODE == 1) { C[o] = v0 + res[o]; C[o + 1] = v1 + res[o + 1]; }
                    if (MODE == 4) { C[o] += v0; C[o + 1] += v1; }
                }
            }
        }
    }
}

// ----------------- per-head zcRMS(64) + RoPE, half in/out -----------------
__global__ void __launch_bounds__(256) qkpost_kernel(const __half* __restrict__ tmp, const float* __restrict__ ns,
                              const float* __restrict__ cosp, const float* __restrict__ sinp,
                              __half* __restrict__ out, int NH) {
    int warp = threadIdx.x >> 5, lane = threadIdx.x & 31;
    int row = blockIdx.x * 8 + warp;
    if (row >= BB * TT * NH) return;
    int hh = row % NH;
    int bt = row / NH;
    int t = bt % TT;
    int b = bt / TT;
    const __half* xin = tmp + ((size_t)bt * NH + hh) * HDIM;
    float x1 = __half2float(xin[lane]), x2 = __half2float(xin[lane + 32]);
    float ss = x1 * x1 + x2 * x2;
#pragma unroll
    for (int o = 16; o > 0; o >>= 1) ss += __shfl_xor_sync(0xffffffffu, ss, o);
    float inv = rsqrtf(ss / (float)HDIM + 1e-6f);
    float y1 = (1.0f + ns[lane]) * x1 * inv;
    float y2 = (1.0f + ns[lane + 32]) * x2 * inv;
    float c = cosp[t * HALF + lane];
    float s = sinp[t * HALF + lane];
    __half* orow = out + ((size_t)(b * NH + hh) * TT + t) * HDIM;
    orow[lane]      = __float2half(y1 * c - y2 * s);
    orow[lane + 32] = __float2half(y2 * c + y1 * s);
}

// ----------------- v transpose to (B,KVH,HD,T) half -----------------
__global__ void __launch_bounds__(256) vtrans_kernel() {
    int idx = blockIdx.x * blockDim.x + threadIdx.x;
    if (idx >= BB * TT * KVH * HDIM) return;
    int d = idx & 63;
    int r = idx >> 6;
    int hh = r % KVH;
    int bt = r / KVH;
    int t = bt % TT;
    int b = bt / TT;
    g_vth[(((size_t)(b * KVH + hh)) * HDIM + d) * TT + t] = g_vtmph[idx];
}

// ----------------- fp16 tensor-core flash attention -----------------
#define FQR 128
#define FKV 64
#define FKSTR 72
#define FT_STAGE_H (FKV*FKSTR*2)
#define FT_SMEM_BYTES (2*FT_STAGE_H*2)

__global__ void __launch_bounds__(256) flash_tc_kernel() {
    extern __shared__ __half smh[];
    int tid = threadIdx.x;
    int lane = tid & 31, warp = tid >> 5;
    int g = lane >> 2, q = lane & 3;
    int z = blockIdx.y;
    int b = z / HH, h = z % HH;
    const __half* Q  = g_qh + (size_t)z * TT * HDIM;
    const __half* Kp = g_kh + (size_t)(b * KVH + h / REP) * TT * HDIM;
    const __half* Vt = g_vth + (size_t)(b * KVH + h / REP) * HDIM * TT;
    int i0 = blockIdx.x * FQR;
    const uint32_t s_u32 = (uint32_t)__cvta_generic_to_shared(smh);

    uint32_t qa[4][4];
    {
        const __half* Qw = Q + (size_t)(i0 + warp * 16) * HDIM;
#pragma unroll
        for (int kk = 0; kk < 4; kk++) {
            qa[kk][0] = *reinterpret_cast<const uint32_t*>(Qw + (size_t)g * HDIM + kk * 16 + 2 * q);
            qa[kk][1] = *reinterpret_cast<const uint32_t*>(Qw + (size_t)(g + 8) * HDIM + kk * 16 + 2 * q);
            qa[kk][2] = *reinterpret_cast<const uint32_t*>(Qw + (size_t)g * HDIM + kk * 16 + 2 * q + 8);
            qa[kk][3] = *reinterpret_cast<const uint32_t*>(Qw + (size_t)(g + 8) * HDIM + kk * 16 + 2 * q + 8);
        }
    }

    float o[8][4];
#pragma unroll
    for (int dt = 0; dt < 8; dt++)
#pragma unroll
        for (int r = 0; r < 4; r++) o[dt][r] = 0.f;
    float m0 = -1e30f, m1 = -1e30f, l0 = 0.f, l1 = 0.f;

#define FT_ISSUE(s, j0) do {                                                          \
    uint32_t kb_ = s_u32 + (s) * (FT_STAGE_H * 2);                                    \
    _Pragma("unroll")                                                                 \
    for (int j_ = 0; j_ < 2; j_++) {                                                  \
        int idx_ = j_ * 256 + tid; int r_ = idx_ >> 3, ch_ = idx_ & 7;                \
        cp16(kb_ + (uint32_t)(r_ * FKSTR + ch_ * 8) * 2,                              \
             Kp + (size_t)((j0) + r_) * HDIM + ch_ * 8);                              \
    }                                                                                 \
    uint32_t vb_ = kb_ + FKV * FKSTR * 2;                                             \
    _Pragma("unroll")                                                                 \
    for (int j_ = 0; j_ < 2; j_++) {                                                  \
        int idx_ = j_ * 256 + tid; int r_ = idx_ >> 3, ch_ = idx_ & 7;                \
        cp16(vb_ + (uint32_t)(r_ * FKSTR + ch_ * 8) * 2,                              \
             Vt + (size_t)r_ * TT + (j0) + ch_ * 8);                                  \
    }                                                                                 \
    asm volatile("cp.async.commit_group;" ::: "memory");                              \
} while (0)

    FT_ISSUE(0, 0);

    for (int it = 0; it < TT / FKV; it++) {
        int cur = it & 1;
        asm volatile("cp.async.wait_group 0;" ::: "memory");
        __syncthreads();
        if (it + 1 < TT / FKV) FT_ISSUE(cur ^ 1, (it + 1) * FKV);

        const __half* Ks = smh + cur * FT_STAGE_H;
        const __half* Vs = Ks + FKV * FKSTR;

        float s[8][4];
#pragma unroll
        for (int t = 0; t < 8; t++)
#pragma unroll
            for (int r = 0; r < 4; r++) s[t][r] = 0.f;
#pragma unroll
        for (int kk = 0; kk < 4; kk++)
#pragma unroll
            for (int t = 0; t < 8; t++) {
                const __half* kp = Ks + (8 * t + g) * FKSTR + kk * 16 + 2 * q;
                uint32_t b0 = *reinterpret_cast<const uint32_t*>(kp);
                uint32_t b1 = *reinterpret_cast<const uint32_t*>(kp + 8);
                MMA_F16(s[t], qa[kk], b0, b1);
            }

        float mx0 = -1e30f, mx1 = -1e30f;
#pragma unroll
        for (int t = 0; t < 8; t++) {
            s[t][0] *= 0.125f; s[t][1] *= 0.125f; s[t][2] *= 0.125f; s[t][3] *= 0.125f;
            mx0 = fmaxf(mx0, fmaxf(s[t][0], s[t][1]));
            mx1 = fmaxf(mx1, fmaxf(s[t][2], s[t][3]));
        }
#pragma unroll
        for (int off = 1; off < 4; off <<= 1) {
            mx0 = fmaxf(mx0, __shfl_xor_sync(0xffffffffu, mx0, off));
            mx1 = fmaxf(mx1, __shfl_xor_sync(0xffffffffu, mx1, off));
        }
        float mn0 = fmaxf(m0, mx0), mn1 = fmaxf(m1, mx1);
        float al0 = __expf(m0 - mn0), al1 = __expf(m1 - mn1);
        m0 = mn0; m1 = mn1;
        float rs0 = 0.f, rs1 = 0.f;
#pragma unroll
        for (int t = 0; t < 8; t++) {
            s[t][0] = __expf(s[t][0] - mn0);
            s[t][1] = __expf(s[t][1] - mn0);
            s[t][2] = __expf(s[t][2] - mn1);
            s[t][3] = __expf(s[t][3] - mn1);
            rs0 += s[t][0] + s[t][1];
            rs1 += s[t][2] + s[t][3];
        }
#pragma unroll
        for (int off = 1; off < 4; off <<= 1) {
            rs0 += __shfl_xor_sync(0xffffffffu, rs0, off);
            rs1 += __shfl_xor_sync(0xffffffffu, rs1, off);
        }
        l0 = l0 * al0 + rs0;
        l1 = l1 * al1 + rs1;
#pragma unroll
        for (int dt = 0; dt < 8; dt++) {
            o[dt][0] *= al0; o[dt][1] *= al0;
            o[dt][2] *= al1; o[dt][3] *= al1;
        }

#pragma unroll
        for (int kt = 0; kt < 4; kt++) {
            uint32_t pa[4];
            pa[0] = packh2(s[2 * kt][0],     s[2 * kt][1]);
            pa[1] = packh2(s[2 * kt][2],     s[2 * kt][3]);
            pa[2] = packh2(s[2 * kt + 1][0], s[2 * kt + 1][1]);
            pa[3] = packh2(s[2 * kt + 1][2], s[2 * kt + 1][3]);
#pragma unroll
            for (int dt = 0; dt < 8; dt++) {
                const __half* vp = Vs + (8 * dt + g) * FKSTR + kt * 16 + 2 * q;
                uint32_t b0 = *reinterpret_cast<const uint32_t*>(vp);
                uint32_t b1 = *reinterpret_cast<const uint32_t*>(vp + 8);
                MMA_F16(o[dt], pa, b0, b1);
            }
        }
    }
#undef FT_ISSUE

    float inv0 = 1.0f / l0, inv1 = 1.0f / l1;
    int r0 = i0 + warp * 16 + g;
    int r1 = r0 + 8;
    __half* out0 = g_attnh + ((size_t)(b * TT + r0) * HH + h) * HDIM;
    __half* out1 = g_attnh + ((size_t)(b * TT + r1) * HH + h) * HDIM;
#pragma unroll
    for (int dt = 0; dt < 8; dt++) {
        int c0 = 8 * dt + 2 * q;
        out0[c0]     = __float2half(o[dt][0] * inv0);
        out0[c0 + 1] = __float2half(o[dt][1] * inv0);
        out1[c0]     = __float2half(o[dt][2] * inv1);
        out1[c0 + 1] = __float2half(o[dt][3] * inv1);
    }
}

// ----------------- depthwise conv KW=15 SAME, 4 t per thread, half in / fp32 out -----------------
__global__ void __launch_bounds__(256) dwconv_kernel(const float* __restrict__ dw) {
    int idx = blockIdx.x * blockDim.x + threadIdx.x;    // BB*TT/4*DD = 2^20
    if (idx >= BB * (TT / 4) * DD) return;
    int d = idx & (DD - 1);
    int tq = (idx >> 10) & (TT / 4 - 1);
    int b = idx >> 19;
    float wv[KW];
#pragma unroll
    for (int w = 0; w < KW; w++) wv[w] = dw[w * DD + d];
    float gv[18];
    int tbase = tq * 4 - 7;
#pragma unroll
    for (int i = 0; i < 18; i++) {
        int t = tbase + i;
        gv[i] = (t >= 0 && t < TT) ? __half2float(g_gh[((size_t)(b * TT + t)) * DD + d]) : 0.f;
    }
#pragma unroll
    for (int j = 0; j < 4; j++) {
        float acc = 0.f;
#pragma unroll
        for (int w = 0; w < KW; w++) acc += gv[j + w] * wv[w];
        g_c[((size_t)(b * TT + tq * 4 + j)) * DD + d] = acc;
    }
}

// ----------------- staged-sync diagnostics (no-op while capturing) -----------------
static void dbg(const char* name) {
    cudaStreamCaptureStatus st = cudaStreamCaptureStatusActive;
    cudaError_t qe = cudaStreamIsCapturing((cudaStream_t)0, &st);
    if (qe != cudaSuccess || st != cudaStreamCaptureStatusNone) return;
    cudaError_t e = cudaStreamSynchronize((cudaStream_t)0);
    fprintf(stderr, "[dbg] %-12s -> %s\n", name, cudaGetErrorString(e));
}

extern "C" void kernel_launch(void* const* d_in, const int* in_sizes, int n_in,
                              void* d_out, int out_size) {
    if (n_in < 20) { fprintf(stderr, "[klaunch] unexpected n_in=%d\n", n_in); return; }

    float *x, *cosp, *sinp, *attn_ns, *qk, *kk, *vk, *qns, *kns, *ok;
    float *conv_ns, *pwup, *dwk, *cin_ns, *pwdown, *ffn_ns, *gatek, *upk, *downk;
    float *p_res, *p_c;
    __half *ph_h, *ph_qk, *ph_kk, *ph_vk, *ph_ok, *ph_pwup, *ph_pwd, *ph_gu, *ph_down;
    __half *ph_attn, *ph_ff, *ph_g, *ph_qtmp, *ph_ktmp, *ph_vtmp, *ph_q, *ph_k, *ph_vt;
    cudaGetSymbolAddress((void**)&x, w_x);
    cudaGetSymbolAddress((void**)&cosp, w_cos);
    cudaGetSymbolAddress((void**)&sinp, w_sin);
    cudaGetSymbolAddress((void**)&attn_ns, w_ans);
    cudaGetSymbolAddress((void**)&qk, w_qk);
    cudaGetSymbolAddress((void**)&kk, w_kk);
    cudaGetSymbolAddress((void**)&vk, w_vk);
    cudaGetSymbolAddress((void**)&qns, w_qns);
    cudaGetSymbolAddress((void**)&kns, w_kns);
    cudaGetSymbolAddress((void**)&ok, w_ok);
    cudaGetSymbolAddress((void**)&conv_ns, w_cns);
    cudaGetSymbolAddress((void**)&pwup, w_pwup);
    cudaGetSymbolAddress((void**)&dwk, w_dwk);
    cudaGetSymbolAddress((void**)&cin_ns, w_cins);
    cudaGetSymbolAddress((void**)&pwdown, w_pwd);
    cudaGetSymbolAddress((void**)&ffn_ns, w_fns);
    cudaGetSymbolAddress((void**)&gatek, w_gatew);
    cudaGetSymbolAddress((void**)&upk, w_upw);
    cudaGetSymbolAddress((void**)&downk, w_downw);
    cudaGetSymbolAddress((void**)&ph_qk, wh_qk);
    cudaGetSymbolAddress((void**)&ph_kk, wh_kk);
    cudaGetSymbolAddress((void**)&ph_vk, wh_vk);
    cudaGetSymbolAddress((void**)&ph_ok, wh_ok);
    cudaGetSymbolAddress((void**)&ph_pwup, wh_pwup);
    cudaGetSymbolAddress((void**)&ph_pwd, wh_pwd);
    cudaGetSymbolAddress((void**)&ph_gu, wh_gu);
    cudaGetSymbolAddress((void**)&ph_down, wh_down);
    cudaGetSymbolAddress((void**)&p_res, g_res);
    cudaGetSymbolAddress((void**)&ph_h, g_hh);
    cudaGetSymbolAddress((void**)&ph_qtmp, g_qtmph);
    cudaGetSymbolAddress((void**)&ph_ktmp, g_ktmph);
    cudaGetSymbolAddress((void**)&ph_vtmp, g_vtmph);
    cudaGetSymbolAddress((void**)&ph_attn, g_attnh);
    cudaGetSymbolAddress((void**)&ph_g, g_gh);
    cudaGetSymbolAddress((void**)&p_c, g_c);
    cudaGetSymbolAddress((void**)&ph_ff, g_ffh);
    cudaGetSymbolAddress((void**)&ph_q, g_qh);
    cudaGetSymbolAddress((void**)&ph_k, g_kh);
    cudaError_t es = cudaGetSymbolAddress((void**)&ph_vt, g_vth);
    if (es != cudaSuccess) { fprintf(stderr, "[sym] g_vth err=%d\n", (int)es); return; }

    cudaFuncSetAttribute(flash_tc_kernel, cudaFuncAttributeMaxDynamicSharedMemorySize, FT_SMEM_BYTES);
    cudaFuncSetAttribute(tgemm_kernel<1>, cudaFuncAttributeMaxDynamicSharedMemorySize, TG_SMEM_BYTES);
    cudaFuncSetAttribute(tgemm_kernel<4>, cudaFuncAttributeMaxDynamicSharedMemorySize, TG_SMEM_BYTES);
    cudaFuncSetAttribute(tgemm_kernel<5>, cudaFuncAttributeMaxDynamicSharedMemorySize, TG_SMEM_BYTES);
    cudaFuncSetAttribute(tgemm_kernel<6>, cudaFuncAttributeMaxDynamicSharedMemorySize, TG_SMEM_BYTES);
    es = cudaFuncSetAttribute(tgemm_kernel<7>, cudaFuncAttributeMaxDynamicSharedMemorySize, TG_SMEM_BYTES);
    if (es != cudaSuccess) fprintf(stderr, "[klaunch] smem attr err=%d\n", (int)es);

    // ---- stage inputs (D2D memcpy; dict order, mask at slot 1 skipped) ----
    struct { int slot; float* dst; int n; } cv[19] = {
        {0, x, SZ_X},        {2, cosp, SZ_COS},  {3, sinp, SZ_COS},
        {4, attn_ns, SZ_NS}, {5, qk, SZ_QK},     {6, kk, SZ_KK},
        {7, vk, SZ_KK},      {8, qns, SZ_HNS},   {9, kns, SZ_HNS},
        {10, ok, SZ_QK},     {11, conv_ns, SZ_NS}, {12, pwup, SZ_PWUP},
        {13, dwk, SZ_DWK},   {14, cin_ns, SZ_NS},  {15, pwdown, SZ_QK},
        {16, ffn_ns, SZ_NS}, {17, gatek, SZ_X},    {18, upk, SZ_X},
        {19, downk, SZ_X}
    };
    for (int i = 0; i < 19; i++) {
        cudaError_t ec = cudaMemcpyAsync(cv[i].dst, d_in[cv[i].slot],
                                         (size_t)cv[i].n * sizeof(float),
                                         cudaMemcpyDeviceToDevice, (cudaStream_t)0);
        if (ec != cudaSuccess) fprintf(stderr, "[memcpy] i=%d err=%d\n", i, (int)ec);
    }

    // ---- transpose+convert weights to half, with column interleaving where fused ----
    struct { const float* in; __half* out; int K; int N; int imode; } tw[9] = {
        {qk, ph_qk, DD, DD, 0},       {kk, ph_kk, DD, 256, 0},   {vk, ph_vk, DD, 256, 0},
        {ok, ph_ok, DD, DD, 0},       {pwup, ph_pwup, DD, 2 * DD, 1}, {pwdown, ph_pwd, DD, DD, 0},
        {gatek, ph_gu, DD, DFF, 2},   {upk, ph_gu, DD, DFF, 3},  {downk, ph_down, DFF, DD, 0}
    };
    for (int i = 0; i < 9; i++)
        wtrans_kernel<<<dim3(tw[i].N / 32, tw[i].K / 32), dim3(32, 8)>>>(tw[i].in, tw[i].out, tw[i].K, tw[i].N, tw[i].imode);
    dbg("stage+wtrans");

    // ---- attention block ----
    rmsnorm_kernel<<<MROWS, 256>>>(x, attn_ns, ph_h);
    tgemm_kernel<7><<<dim3(DD / BNT, MROWS / BMT), 256, TG_SMEM_BYTES>>>(ph_h, ph_qk, nullptr, ph_qtmp, nullptr, MROWS, DD, DD, DD, DD);
    tgemm_kernel<7><<<dim3(256 / BNT, MROWS / BMT), 256, TG_SMEM_BYTES>>>(ph_h, ph_kk, nullptr, ph_ktmp, nullptr, MROWS, 256, DD, DD, DD);
    tgemm_kernel<7><<<dim3(256 / BNT, MROWS / BMT), 256, TG_SMEM_BYTES>>>(ph_h, ph_vk, nullptr, ph_vtmp, nullptr, MROWS, 256, DD, DD, DD);
    dbg("qkv");
    qkpost_kernel<<<(BB * TT * HH) / 8, 256>>>(ph_qtmp, qns, cosp, sinp, ph_q, HH);
    qkpost_kernel<<<(BB * TT * KVH) / 8, 256>>>(ph_ktmp, kns, cosp, sinp, ph_k, KVH);
    vtrans_kernel<<<(BB * TT * KVH * HDIM) / 256, 256>>>();
    flash_tc_kernel<<<dim3(TT / FQR, BB * HH), 256, FT_SMEM_BYTES>>>();
    dbg("flash");
    tgemm_kernel<1><<<dim3(DD / BNT, MROWS / BMT), 256, TG_SMEM_BYTES>>>(ph_attn, ph_ok, p_res, nullptr, x, MROWS, DD, DD, DD, DD);
    dbg("oproj");

    // ---- conv block ----
    rmsnorm_kernel<<<MROWS, 256>>>(p_res, conv_ns, ph_h);
    tgemm_kernel<5><<<dim3((2 * DD) / BNT, MROWS / BMT), 256, TG_SMEM_BYTES>>>(ph_h, ph_pwup, nullptr, ph_g, nullptr, MROWS, 2 * DD, DD, DD, DD);
    dwconv_kernel<<<(BB * (TT / 4) * DD) / 256, 256>>>(dwk);
    rmsnorm_kernel<<<MROWS, 256>>>(p_c, cin_ns, ph_h);
    tgemm_kernel<1><<<dim3(DD / BNT, MROWS / BMT), 256, TG_SMEM_BYTES>>>(ph_h, ph_pwd, p_res, nullptr, p_res, MROWS, DD, DD, DD, DD);
    dbg("conv");

    // ---- FFN block ----
    rmsnorm_kernel<<<MROWS, 256>>>(p_res, ffn_ns, ph_h);
    tgemm_kernel<6><<<dim3((2 * DFF) / BNT, MROWS / BMT), 256, TG_SMEM_BYTES>>>(ph_h, ph_gu, nullptr, ph_ff, nullptr, MROWS, 2 * DFF, DD, DD, DD);
    tgemm_kernel<1><<<dim3(DD / BNT, MROWS / BMT), 256, TG_SMEM_BYTES>>>(ph_ff,        ph_down,        p_res, nullptr, p_res, MROWS, DD, 1024, DFF, DFF);
    tgemm_kernel<4><<<dim3(DD / BNT, MROWS / BMT), 256, TG_SMEM_BYTES>>>(ph_ff + 1024, ph_down + 1024, p_res, nullptr, nullptr, MROWS, DD, 1024, DFF, DFF);
    tgemm_kernel<4><<<dim3(DD / BNT, MROWS / BMT), 256, TG_SMEM_BYTES>>>(ph_ff + 2048, ph_down + 2048, p_res, nullptr, nullptr, MROWS, DD, 1024, DFF, DFF);
    tgemm_kernel<4><<<dim3(DD / BNT, MROWS / BMT), 256, TG_SMEM_BYTES>>>(ph_ff + 3072, ph_down + 3072, p_res, nullptr, nullptr, MROWS, DD, 1024, DFF, DFF);
    dbg("ffn");

    // ---- result -> d_out ----
    cudaError_t eo = cudaMemcpyAsync(d_out, p_res, (size_t)MROWS * DD * sizeof(float),
                                     cudaMemcpyDeviceToDevice, (cudaStream_t)0);
    if (eo != cudaSuccess) fprintf(stderr, "[memcpy] out err=%d\n", (int)eo);
    dbg("memcpy_out");
}

// round 12
// speedup vs baseline: 5.9027x; 1.0948x over previous
#include <cuda_runtime.h>
#include <cuda_fp16.h>
#include <math.h>
#include <stdint.h>
#include <stdio.h>

#define BB 2
#define TT 2048
#define DD 1024
#define HH 16
#define KVH 4
#define HDIM 64
#define HALF 32
#define DFF 4096
#define KW 15
#define MROWS (BB*TT)   // 4096
#define REP (HH/KVH)    // 4

#define SZ_QK   1048576
#define SZ_KK   262144
#define SZ_PWUP 2097152
#define SZ_X    4194304

// ----------------- fp16 transposed weights [N][K] (possibly column-interleaved) -----------------
__device__ __align__(256) __half wh_qk  [SZ_QK];
__device__ __align__(256) __half wh_kk  [SZ_KK];
__device__ __align__(256) __half wh_vk  [SZ_KK];
__device__ __align__(256) __half wh_ok  [SZ_QK];
__device__ __align__(256) __half wh_pwup[SZ_PWUP];     // interleaved u1/u2
__device__ __align__(256) __half wh_pwd [SZ_QK];
__device__ __align__(256) __half wh_gu  [2*SZ_X];      // interleaved gate/up [8192][1024]
__device__ __align__(256) __half wh_down[SZ_X];

// ----------------- scratch -----------------
__device__ __align__(256) float  g_res [(size_t)MROWS*DD];
__device__ __align__(256) __half g_hh  [(size_t)MROWS*DD];
__device__ __align__(256) __half g_qtmph[(size_t)MROWS*DD];
__device__ __align__(256) __half g_ktmph[(size_t)MROWS*KVH*HDIM];
__device__ __align__(256) __half g_vtmph[(size_t)MROWS*KVH*HDIM];
__device__ __align__(256) __half g_qh  [(size_t)BB*HH*TT*HDIM];
__device__ __align__(256) __half g_kh  [(size_t)BB*KVH*TT*HDIM];
__device__ __align__(256) __half g_vth [(size_t)BB*KVH*HDIM*TT];
__device__ __align__(256) __half g_attnh[(size_t)MROWS*DD];
__device__ __align__(256) __half g_gh  [(size_t)MROWS*DD];
__device__ __align__(256) float  g_c   [(size_t)MROWS*DD];
__device__ __align__(256) __half g_ffh [(size_t)MROWS*DFF];

__device__ __forceinline__ uint32_t packh2(float a, float b) {
    __half2 h = __floats2half2_rn(a, b);
    return *reinterpret_cast<uint32_t*>(&h);
}

#define MMA_F16(acc, a, b0, b1)                                               \
    asm volatile(                                                             \
        "mma.sync.aligned.m16n8k16.row.col.f32.f16.f16.f32 "                  \
        "{%0,%1,%2,%3}, {%4,%5,%6,%7}, {%8,%9}, {%0,%1,%2,%3};"               \
        : "+f"((acc)[0]), "+f"((acc)[1]), "+f"((acc)[2]), "+f"((acc)[3])      \
        : "r"((a)[0]), "r"((a)[1]), "r"((a)[2]), "r"((a)[3]),                 \
          "r"(b0), "r"(b1))

__device__ __forceinline__ void cp16(uint32_t dst, const void* src) {
    asm volatile("cp.async.cg.shared.global [%0], [%1], 16;" :: "r"(dst), "l"(src));
}

// ----------------- weight transpose+convert: fp32 [K][N] -> half [rowmap(n)][K] -----------------
// imode 0: r=n ; 1: n<N/2 -> 2n else 2(n-N/2)+1 ; 2: r=2n ; 3: r=2n+1
__global__ void __launch_bounds__(256) wtrans_kernel(const float* __restrict__ in,
                                                     __half* __restrict__ out, int K, int N, int imode) {
    __shared__ float t[32][33];
    int kb = blockIdx.y * 32, nb = blockIdx.x * 32;
    int tx = threadIdx.x, ty = threadIdx.y;
#pragma unroll
    for (int i = ty; i < 32; i += 8)
        t[i][tx] = in[(size_t)(kb + i) * N + nb + tx];
    __syncthreads();
#pragma unroll
    for (int i = ty; i < 32; i += 8) {
        int n = nb + i;
        int r = (imode == 0) ? n
              : (imode == 1) ? ((n < N / 2) ? 2 * n : 2 * (n - N / 2) + 1)
              : (imode == 2) ? 2 * n : 2 * n + 1;
        out[(size_t)r * K + kb + tx] = __float2half(t[tx][i]);
    }
}

// ----------------- zcRMS over D=1024, half out -----------------
__global__ void __launch_bounds__(256) rmsnorm_kernel(const float* __restrict__ in,
                               const float* __restrict__ scale,
                               __half* __restrict__ out) {
    size_t row = blockIdx.x;
    const float* xr = in + row * DD;
    __half* orow = out + row * DD;
    int tid = threadIdx.x;
    float v[4];
    float ss = 0.f;
#pragma unroll
    for (int i = 0; i < 4; i++) { v[i] = xr[tid + i * 256]; ss += v[i] * v[i]; }
    __shared__ float red[256];
    red[tid] = ss; __syncthreads();
    for (int s = 128; s > 0; s >>= 1) { if (tid < s) red[tid] += red[tid + s]; __syncthreads(); }
    float inv = rsqrtf(red[0] / (float)DD + 1e-6f);
#pragma unroll
    for (int i = 0; i < 4; i++) {
        int c = tid + i * 256;
        orow[c] = __float2half((1.0f + scale[c]) * v[i] * inv);
    }
}

// ----------------- fp16 tensor-core GEMM -----------------
// MODE 1: C f32 = res+AB ; 4: C f32 += AB ; 5: Ch[M,N/2] = u1*sigmoid(u2)
// 6: Ch[M,N/2] = relu(even)*relu(odd) ; 7: Ch[M,N] = AB
#define BMT 128
#define BNT 128
#define BKT 32
#define ASTR 40
#define BSTR 40
#define STAGE_H (BMT*ASTR + BNT*BSTR)
#define TG_SMEM_BYTES (2*STAGE_H*2)

template <int MODE>
__global__ void __launch_bounds__(256) tgemm_kernel(
    const __half* __restrict__ A, const __half* __restrict__ Wt,
    float* __restrict__ C, __half* __restrict__ Ch,
    const float* __restrict__ res,
    int M, int N, int K, int lda, int ldb)
{
    extern __shared__ __half smh[];
    int tid = threadIdx.x;
    int lane = tid & 31, warp = tid >> 5;
    int g = lane >> 2, q = lane & 3;
    int warp_m = warp >> 2;
    int warp_n = warp & 3;
    int m0 = blockIdx.y * BMT, n0 = blockIdx.x * BNT;
    const uint32_t s_u32 = (uint32_t)__cvta_generic_to_shared(smh);

    float acc[4][4][4];
#pragma unroll
    for (int mt = 0; mt < 4; mt++)
#pragma unroll
        for (int nt = 0; nt < 4; nt++)
#pragma unroll
            for (int r = 0; r < 4; r++) acc[mt][nt][r] = 0.f;

#define TG_ISSUE(s, k0) do {                                                          \
    uint32_t ab_ = s_u32 + (s) * (STAGE_H * 2);                                       \
    _Pragma("unroll")                                                                 \
    for (int j_ = 0; j_ < 2; j_++) {                                                  \
        int idx_ = j_ * 256 + tid; int r_ = idx_ >> 2, ch_ = idx_ & 3;                \
        cp16(ab_ + (uint32_t)(r_ * ASTR + ch_ * 8) * 2,                               \
             A + (size_t)(m0 + r_) * lda + (k0) + ch_ * 8);                           \
    }                                                                                 \
    uint32_t bb_ = ab_ + BMT * ASTR * 2;                                              \
    _Pragma("unroll")                                                                 \
    for (int j_ = 0; j_ < 2; j_++) {                                                  \
        int idx_ = j_ * 256 + tid; int r_ = idx_ >> 2, ch_ = idx_ & 3;                \
        cp16(bb_ + (uint32_t)(r_ * BSTR + ch_ * 8) * 2,                               \
             Wt + (size_t)(n0 + r_) * ldb + (k0) + ch_ * 8);                          \
    }                                                                                 \
    asm volatile("cp.async.commit_group;" ::: "memory");                              \
} while (0)

    int nk = K / BKT;
    TG_ISSUE(0, 0);

    for (int kt = 0; kt < nk; kt++) {
        int cur = kt & 1;
        asm volatile("cp.async.wait_group 0;" ::: "memory");
        __syncthreads();
        if (kt + 1 < nk) TG_ISSUE(cur ^ 1, (kt + 1) * BKT);

        uint32_t a_row = s_u32 + cur * (STAGE_H * 2)
                       + (uint32_t)((warp_m * 64 + (lane & 15)) * ASTR + (lane >> 4) * 8) * 2;
        const __half* BsH = smh + cur * STAGE_H + BMT * ASTR;

#pragma unroll
        for (int kk = 0; kk < 2; kk++) {
            uint32_t a[4][4];
#pragma unroll
            for (int mt = 0; mt < 4; mt++) {
                uint32_t addr = a_row + (uint32_t)(mt * 16 * ASTR + kk * 16) * 2;
                asm volatile("ldmatrix.sync.aligned.m8n8.x4.shared.b16 {%0,%1,%2,%3}, [%4];"
                             : "=r"(a[mt][0]), "=r"(a[mt][1]), "=r"(a[mt][2]), "=r"(a[mt][3])
                             : "r"(addr));
            }
#pragma unroll
            for (int nt = 0; nt < 4; nt++) {
                const __half* bp = BsH + (warp_n * 32 + nt * 8 + g) * BSTR + kk * 16 + 2 * q;
                uint32_t b0 = *reinterpret_cast<const uint32_t*>(bp);
                uint32_t b1 = *reinterpret_cast<const uint32_t*>(bp + 8);
#pragma unroll
                for (int mt = 0; mt < 4; mt++)
                    MMA_F16(acc[mt][nt], a[mt], b0, b1);
            }
        }
    }
#undef TG_ISSUE

#pragma unroll
    for (int mt = 0; mt < 4; mt++) {
#pragma unroll
        for (int nt = 0; nt < 4; nt++) {
            int colbase = n0 + warp_n * 32 + nt * 8;
#pragma unroll
            for (int half_ = 0; half_ < 2; half_++) {
                int row = m0 + warp_m * 64 + mt * 16 + g + half_ * 8;
                float v0 = acc[mt][nt][half_ * 2 + 0];
                float v1 = acc[mt][nt][half_ * 2 + 1];
                if (MODE == 5) {
                    size_t o = (size_t)row * (N >> 1) + (colbase >> 1) + q;
                    Ch[o] = __float2half(v0 / (1.0f + __expf(-v1)));
                } else if (MODE == 6) {
                    size_t o = (size_t)row * (N >> 1) + (colbase >> 1) + q;
                    Ch[o] = __float2half(fmaxf(v0, 0.f) * fmaxf(v1, 0.f));
                } else if (MODE == 7) {
                    size_t o = (size_t)row * N + colbase + 2 * q;
                    Ch[o]     = __float2half(v0);
                    Ch[o + 1] = __float2half(v1);
                } else {
                    size_t o = (size_t)row * N + colbase + 2 * q;
                    if (MODE == 1) { C[o] = v0 + res[o]; C[o + 1] = v1 + res[o + 1]; }
                    if (MODE == 4) { C[o] += v0; C[o + 1] += v1; }
                }
            }
        }
    }
}

// ----------------- per-head zcRMS(64) + RoPE, half in/out -----------------
__global__ void __launch_bounds__(256) qkpost_kernel(const __half* __restrict__ tmp, const float* __restrict__ ns,
                              const float* __restrict__ cosp, const float* __restrict__ sinp,
                              __half* __restrict__ out, int NH) {
    int warp = threadIdx.x >> 5, lane = threadIdx.x & 31;
    int row = blockIdx.x * 8 + warp;
    if (row >= BB * TT * NH) return;
    int hh = row % NH;
    int bt = row / NH;
    int t = bt % TT;
    int b = bt / TT;
    const __half* xin = tmp + ((size_t)bt * NH + hh) * HDIM;
    float x1 = __half2float(xin[lane]), x2 = __half2float(xin[lane + 32]);
    float ss = x1 * x1 + x2 * x2;
#pragma unroll
    for (int o = 16; o > 0; o >>= 1) ss += __shfl_xor_sync(0xffffffffu, ss, o);
    float inv = rsqrtf(ss / (float)HDIM + 1e-6f);
    float y1 = (1.0f + ns[lane]) * x1 * inv;
    float y2 = (1.0f + ns[lane + 32]) * x2 * inv;
    float c = cosp[t * HALF + lane];
    float s = sinp[t * HALF + lane];
    __half* orow = out + ((size_t)(b * NH + hh) * TT + t) * HDIM;
    orow[lane]      = __float2half(y1 * c - y2 * s);
    orow[lane + 32] = __float2half(y2 * c + y1 * s);
}

// ----------------- v transpose to (B,KVH,HD,T) half -----------------
__global__ void __launch_bounds__(256) vtrans_kernel() {
    int idx = blockIdx.x * blockDim.x + threadIdx.x;
    if (idx >= BB * TT * KVH * HDIM) return;
    int d = idx & 63;
    int r = idx >> 6;
    int hh = r % KVH;
    int bt = r / KVH;
    int t = bt % TT;
    int b = bt / TT;
    g_vth[(((size_t)(b * KVH + hh)) * HDIM + d) * TT + t] = g_vtmph[idx];
}

// ----------------- fp16 tensor-core flash attention -----------------
#define FQR 128
#define FKV 64
#define FKSTR 72
#define FT_STAGE_H (FKV*FKSTR*2)
#define FT_SMEM_BYTES (2*FT_STAGE_H*2)

__global__ void __launch_bounds__(256) flash_tc_kernel() {
    extern __shared__ __half smh[];
    int tid = threadIdx.x;
    int lane = tid & 31, warp = tid >> 5;
    int g = lane >> 2, q = lane & 3;
    int z = blockIdx.y;
    int b = z / HH, h = z % HH;
    const __half* Q  = g_qh + (size_t)z * TT * HDIM;
    const __half* Kp = g_kh + (size_t)(b * KVH + h / REP) * TT * HDIM;
    const __half* Vt = g_vth + (size_t)(b * KVH + h / REP) * HDIM * TT;
    int i0 = blockIdx.x * FQR;
    const uint32_t s_u32 = (uint32_t)__cvta_generic_to_shared(smh);

    uint32_t qa[4][4];
    {
        const __half* Qw = Q + (size_t)(i0 + warp * 16) * HDIM;
#pragma unroll
        for (int kk = 0; kk < 4; kk++) {
            qa[kk][0] = *reinterpret_cast<const uint32_t*>(Qw + (size_t)g * HDIM + kk * 16 + 2 * q);
            qa[kk][1] = *reinterpret_cast<const uint32_t*>(Qw + (size_t)(g + 8) * HDIM + kk * 16 + 2 * q);
            qa[kk][2] = *reinterpret_cast<const uint32_t*>(Qw + (size_t)g * HDIM + kk * 16 + 2 * q + 8);
            qa[kk][3] = *reinterpret_cast<const uint32_t*>(Qw + (size_t)(g + 8) * HDIM + kk * 16 + 2 * q + 8);
        }
    }

    float o[8][4];
#pragma unroll
    for (int dt = 0; dt < 8; dt++)
#pragma unroll
        for (int r = 0; r < 4; r++) o[dt][r] = 0.f;
    float m0 = -1e30f, m1 = -1e30f, l0 = 0.f, l1 = 0.f;

#define FT_ISSUE(s, j0) do {                                                          \
    uint32_t kb_ = s_u32 + (s) * (FT_STAGE_H * 2);                                    \
    _Pragma("unroll")                                                                 \
    for (int j_ = 0; j_ < 2; j_++) {                                                  \
        int idx_ = j_ * 256 + tid; int r_ = idx_ >> 3, ch_ = idx_ & 7;                \
        cp16(kb_ + (uint32_t)(r_ * FKSTR + ch_ * 8) * 2,                              \
             Kp + (size_t)((j0) + r_) * HDIM + ch_ * 8);                              \
    }                                                                                 \
    uint32_t vb_ = kb_ + FKV * FKSTR * 2;                                             \
    _Pragma("unroll")                                                                 \
    for (int j_ = 0; j_ < 2; j_++) {                                                  \
        int idx_ = j_ * 256 + tid; int r_ = idx_ >> 3, ch_ = idx_ & 7;                \
        cp16(vb_ + (uint32_t)(r_ * FKSTR + ch_ * 8) * 2,                              \
             Vt + (size_t)r_ * TT + (j0) + ch_ * 8);                                  \
    }                                                                                 \
    asm volatile("cp.async.commit_group;" ::: "memory");                              \
} while (0)

    FT_ISSUE(0, 0);

    for (int it = 0; it < TT / FKV; it++) {
        int cur = it & 1;
        asm volatile("cp.async.wait_group 0;" ::: "memory");
        __syncthreads();
        if (it + 1 < TT / FKV) FT_ISSUE(cur ^ 1, (it + 1) * FKV);

        const __half* Ks = smh + cur * FT_STAGE_H;
        const __half* Vs = Ks + FKV * FKSTR;

        float s[8][4];
#pragma unroll
        for (int t = 0; t < 8; t++)
#pragma unroll
            for (int r = 0; r < 4; r++) s[t][r] = 0.f;
#pragma unroll
        for (int kk = 0; kk < 4; kk++)
#pragma unroll
            for (int t = 0; t < 8; t++) {
                const __half* kp = Ks + (8 * t + g) * FKSTR + kk * 16 + 2 * q;
                uint32_t b0 = *reinterpret_cast<const uint32_t*>(kp);
                uint32_t b1 = *reinterpret_cast<const uint32_t*>(kp + 8);
                MMA_F16(s[t], qa[kk], b0, b1);
            }

        float mx0 = -1e30f, mx1 = -1e30f;
#pragma unroll
        for (int t = 0; t < 8; t++) {
            s[t][0] *= 0.125f; s[t][1] *= 0.125f; s[t][2] *= 0.125f; s[t][3] *= 0.125f;
            mx0 = fmaxf(mx0, fmaxf(s[t][0], s[t][1]));
            mx1 = fmaxf(mx1, fmaxf(s[t][2], s[t][3]));
        }
#pragma unroll
        for (int off = 1; off < 4; off <<= 1) {
            mx0 = fmaxf(mx0, __shfl_xor_sync(0xffffffffu, mx0, off));
            mx1 = fmaxf(mx1, __shfl_xor_sync(0xffffffffu, mx1, off));
        }
        float mn0 = fmaxf(m0, mx0), mn1 = fmaxf(m1, mx1);
        float al0 = __expf(m0 - mn0), al1 = __expf(m1 - mn1);
        m0 = mn0; m1 = mn1;
        float rs0 = 0.f, rs1 = 0.f;
#pragma unroll
        for (int t = 0; t < 8; t++) {
            s[t][0] = __expf(s[t][0] - mn0);
            s[t][1] = __expf(s[t][1] - mn0);
            s[t][2] = __expf(s[t][2] - mn1);
            s[t][3] = __expf(s[t][3] - mn1);
            rs0 += s[t][0] + s[t][1];
            rs1 += s[t][2] + s[t][3];
        }
#pragma unroll
        for (int off = 1; off < 4; off <<= 1) {
            rs0 += __shfl_xor_sync(0xffffffffu, rs0, off);
            rs1 += __shfl_xor_sync(0xffffffffu, rs1, off);
        }
        l0 = l0 * al0 + rs0;
        l1 = l1 * al1 + rs1;
#pragma unroll
        for (int dt = 0; dt < 8; dt++) {
            o[dt][0] *= al0; o[dt][1] *= al0;
            o[dt][2] *= al1; o[dt][3] *= al1;
        }

#pragma unroll
        for (int kt = 0; kt < 4; kt++) {
            uint32_t pa[4];
            pa[0] = packh2(s[2 * kt][0],     s[2 * kt][1]);
            pa[1] = packh2(s[2 * kt][2],     s[2 * kt][3]);
            pa[2] = packh2(s[2 * kt + 1][0], s[2 * kt + 1][1]);
            pa[3] = packh2(s[2 * kt + 1][2], s[2 * kt + 1][3]);
#pragma unroll
            for (int dt = 0; dt < 8; dt++) {
                const __half* vp = Vs + (8 * dt + g) * FKSTR + kt * 16 + 2 * q;
                uint32_t b0 = *reinterpret_cast<const uint32_t*>(vp);
                uint32_t b1 = *reinterpret_cast<const uint32_t*>(vp + 8);
                MMA_F16(o[dt], pa, b0, b1);
            }
        }
    }
#undef FT_ISSUE

    float inv0 = 1.0f / l0, inv1 = 1.0f / l1;
    int r0 = i0 + warp * 16 + g;
    int r1 = r0 + 8;
    __half* out0 = g_attnh + ((size_t)(b * TT + r0) * HH + h) * HDIM;
    __half* out1 = g_attnh + ((size_t)(b * TT + r1) * HH + h) * HDIM;
#pragma unroll
    for (int dt = 0; dt < 8; dt++) {
        int c0 = 8 * dt + 2 * q;
        out0[c0]     = __float2half(o[dt][0] * inv0);
        out0[c0 + 1] = __float2half(o[dt][1] * inv0);
        out1[c0]     = __float2half(o[dt][2] * inv1);
        out1[c0 + 1] = __float2half(o[dt][3] * inv1);
    }
}

// ----------------- depthwise conv KW=15 SAME, 4 t per thread -----------------
__global__ void __launch_bounds__(256) dwconv_kernel(const float* __restrict__ dw) {
    int idx = blockIdx.x * blockDim.x + threadIdx.x;
    if (idx >= BB * (TT / 4) * DD) return;
    int d = idx & (DD - 1);
    int tq = (idx >> 10) & (TT / 4 - 1);
    int b = idx >> 19;
    float wv[KW];
#pragma unroll
    for (int w = 0; w < KW; w++) wv[w] = dw[w * DD + d];
    float gv[18];
    int tbase = tq * 4 - 7;
#pragma unroll
    for (int i = 0; i < 18; i++) {
        int t = tbase + i;
        gv[i] = (t >= 0 && t < TT) ? __half2float(g_gh[((size_t)(b * TT + t)) * DD + d]) : 0.f;
    }
#pragma unroll
    for (int j = 0; j < 4; j++) {
        float acc = 0.f;
#pragma unroll
        for (int w = 0; w < KW; w++) acc += gv[j + w] * wv[w];
        g_c[((size_t)(b * TT + tq * 4 + j)) * DD + d] = acc;
    }
}

// ----------------- staged-sync diagnostics (no-op while capturing) -----------------
static void dbg(const char* name) {
    cudaStreamCaptureStatus st = cudaStreamCaptureStatusActive;
    cudaError_t qe = cudaStreamIsCapturing((cudaStream_t)0, &st);
    if (qe != cudaSuccess || st != cudaStreamCaptureStatusNone) return;
    cudaError_t e = cudaStreamSynchronize((cudaStream_t)0);
    fprintf(stderr, "[dbg] %-12s -> %s\n", name, cudaGetErrorString(e));
}

extern "C" void kernel_launch(void* const* d_in, const int* in_sizes, int n_in,
                              void* d_out, int out_size) {
    if (n_in < 20) { fprintf(stderr, "[klaunch] unexpected n_in=%d\n", n_in); return; }

    // dict-order harness inputs (verified R4); mask at slot 1 unused
    const float* x       = (const float*)d_in[0];
    const float* cosp    = (const float*)d_in[2];
    const float* sinp    = (const float*)d_in[3];
    const float* attn_ns = (const float*)d_in[4];
    const float* qk      = (const float*)d_in[5];
    const float* kk      = (const float*)d_in[6];
    const float* vk      = (const float*)d_in[7];
    const float* qns     = (const float*)d_in[8];
    const float* kns     = (const float*)d_in[9];
    const float* ok      = (const float*)d_in[10];
    const float* conv_ns = (const float*)d_in[11];
    const float* pwup    = (const float*)d_in[12];
    const float* dwk     = (const float*)d_in[13];
    const float* cin_ns  = (const float*)d_in[14];
    const float* pwdown  = (const float*)d_in[15];
    const float* ffn_ns  = (const float*)d_in[16];
    const float* gatek   = (const float*)d_in[17];
    const float* upk     = (const float*)d_in[18];
    const float* downk   = (const float*)d_in[19];
    float* out = (float*)d_out;

    float *p_res, *p_c;
    __half *ph_h, *ph_qk, *ph_kk, *ph_vk, *ph_ok, *ph_pwup, *ph_pwd, *ph_gu, *ph_down;
    __half *ph_attn, *ph_ff, *ph_g, *ph_qtmp, *ph_ktmp, *ph_vtmp, *ph_q, *ph_k, *ph_vt;
    cudaGetSymbolAddress((void**)&ph_qk, wh_qk);
    cudaGetSymbolAddress((void**)&ph_kk, wh_kk);
    cudaGetSymbolAddress((void**)&ph_vk, wh_vk);
    cudaGetSymbolAddress((void**)&ph_ok, wh_ok);
    cudaGetSymbolAddress((void**)&ph_pwup, wh_pwup);
    cudaGetSymbolAddress((void**)&ph_pwd, wh_pwd);
    cudaGetSymbolAddress((void**)&ph_gu, wh_gu);
    cudaGetSymbolAddress((void**)&ph_down, wh_down);
    cudaGetSymbolAddress((void**)&p_res, g_res);
    cudaGetSymbolAddress((void**)&ph_h, g_hh);
    cudaGetSymbolAddress((void**)&ph_qtmp, g_qtmph);
    cudaGetSymbolAddress((void**)&ph_ktmp, g_ktmph);
    cudaGetSymbolAddress((void**)&ph_vtmp, g_vtmph);
    cudaGetSymbolAddress((void**)&ph_attn, g_attnh);
    cudaGetSymbolAddress((void**)&ph_g, g_gh);
    cudaGetSymbolAddress((void**)&p_c, g_c);
    cudaGetSymbolAddress((void**)&ph_ff, g_ffh);
    cudaGetSymbolAddress((void**)&ph_q, g_qh);
    cudaGetSymbolAddress((void**)&ph_k, g_kh);
    cudaError_t es = cudaGetSymbolAddress((void**)&ph_vt, g_vth);
    if (es != cudaSuccess) { fprintf(stderr, "[sym] g_vth err=%d\n", (int)es); return; }

    cudaFuncSetAttribute(flash_tc_kernel, cudaFuncAttributeMaxDynamicSharedMemorySize, FT_SMEM_BYTES);
    cudaFuncSetAttribute(tgemm_kernel<1>, cudaFuncAttributeMaxDynamicSharedMemorySize, TG_SMEM_BYTES);
    cudaFuncSetAttribute(tgemm_kernel<5>, cudaFuncAttributeMaxDynamicSharedMemorySize, TG_SMEM_BYTES);
    cudaFuncSetAttribute(tgemm_kernel<6>, cudaFuncAttributeMaxDynamicSharedMemorySize, TG_SMEM_BYTES);
    es = cudaFuncSetAttribute(tgemm_kernel<7>, cudaFuncAttributeMaxDynamicSharedMemorySize, TG_SMEM_BYTES);
    if (es != cudaSuccess) fprintf(stderr, "[klaunch] smem attr err=%d\n", (int)es);

    // ---- transpose+convert weights to half directly from harness inputs ----
    struct { const float* in; __half* out; int K; int N; int imode; } tw[9] = {
        {qk, ph_qk, DD, DD, 0},       {kk, ph_kk, DD, 256, 0},   {vk, ph_vk, DD, 256, 0},
        {ok, ph_ok, DD, DD, 0},       {pwup, ph_pwup, DD, 2 * DD, 1}, {pwdown, ph_pwd, DD, DD, 0},
        {gatek, ph_gu, DD, DFF, 2},   {upk, ph_gu, DD, DFF, 3},  {downk, ph_down, DFF, DD, 0}
    };
    for (int i = 0; i < 9; i++)
        wtrans_kernel<<<dim3(tw[i].N / 32, tw[i].K / 32), dim3(32, 8)>>>(tw[i].in, tw[i].out, tw[i].K, tw[i].N, tw[i].imode);
    dbg("wtrans");

    // ---- attention block ----
    rmsnorm_kernel<<<MROWS, 256>>>(x, attn_ns, ph_h);
    tgemm_kernel<7><<<dim3(DD / BNT, MROWS / BMT), 256, TG_SMEM_BYTES>>>(ph_h, ph_qk, nullptr, ph_qtmp, nullptr, MROWS, DD, DD, DD, DD);
    tgemm_kernel<7><<<dim3(256 / BNT, MROWS / BMT), 256, TG_SMEM_BYTES>>>(ph_h, ph_kk, nullptr, ph_ktmp, nullptr, MROWS, 256, DD, DD, DD);
    tgemm_kernel<7><<<dim3(256 / BNT, MROWS / BMT), 256, TG_SMEM_BYTES>>>(ph_h, ph_vk, nullptr, ph_vtmp, nullptr, MROWS, 256, DD, DD, DD);
    dbg("qkv");
    qkpost_kernel<<<(BB * TT * HH) / 8, 256>>>(ph_qtmp, qns, cosp, sinp, ph_q, HH);
    qkpost_kernel<<<(BB * TT * KVH) / 8, 256>>>(ph_ktmp, kns, cosp, sinp, ph_k, KVH);
    vtrans_kernel<<<(BB * TT * KVH * HDIM) / 256, 256>>>();
    flash_tc_kernel<<<dim3(TT / FQR, BB * HH), 256, FT_SMEM_BYTES>>>();
    dbg("flash");
    tgemm_kernel<1><<<dim3(DD / BNT, MROWS / BMT), 256, TG_SMEM_BYTES>>>(ph_attn, ph_ok, p_res, nullptr, x, MROWS, DD, DD, DD, DD);
    dbg("oproj");

    // ---- conv block ----
    rmsnorm_kernel<<<MROWS, 256>>>(p_res, conv_ns, ph_h);
    tgemm_kernel<5><<<dim3((2 * DD) / BNT, MROWS / BMT), 256, TG_SMEM_BYTES>>>(ph_h, ph_pwup, nullptr, ph_g, nullptr, MROWS, 2 * DD, DD, DD, DD);
    dwconv_kernel<<<(BB * (TT / 4) * DD) / 256, 256>>>(dwk);
    rmsnorm_kernel<<<MROWS, 256>>>(p_c, cin_ns, ph_h);
    tgemm_kernel<1><<<dim3(DD / BNT, MROWS / BMT), 256, TG_SMEM_BYTES>>>(ph_h, ph_pwd, p_res, nullptr, p_res, MROWS, DD, DD, DD, DD);
    dbg("conv");

    // ---- FFN block ----
    rmsnorm_kernel<<<MROWS, 256>>>(p_res, ffn_ns, ph_h);
    tgemm_kernel<6><<<dim3((2 * DFF) / BNT, MROWS / BMT), 256, TG_SMEM_BYTES>>>(ph_h, ph_gu, nullptr, ph_ff, nullptr, MROWS, 2 * DFF, DD, DD, DD);
    // single K=4096 down GEMM, fused residual, writes final output directly
    tgemm_kernel<1><<<dim3(DD / BNT, MROWS / BMT), 256, TG_SMEM_BYTES>>>(ph_ff, ph_down, out, nullptr, p_res, MROWS, DD, DFF, DFF, DFF);
    dbg("ffn");
}

// round 13
// speedup vs baseline: 6.1406x; 1.0403x over previous
#include <cuda_runtime.h>
#include <cuda_fp16.h>
#include <math.h>
#include <stdint.h>
#include <stdio.h>

#define BB 2
#define TT 2048
#define DD 1024
#define HH 16
#define KVH 4
#define HDIM 64
#define HALF 32
#define DFF 4096
#define KW 15
#define MROWS (BB*TT)   // 4096
#define REP (HH/KVH)    // 4
#define NQKV 1536

#define SZ_QK   1048576
#define SZ_KK   262144
#define SZ_PWUP 2097152
#define SZ_X    4194304

// ----------------- fp16 transposed weights [N][K] (column-interleaved where fused) -----------------
__device__ __align__(256) __half wh_qkv [NQKV*DD];     // q rows 0-1023, k 1024-1279, v 1280-1535
__device__ __align__(256) __half wh_ok  [SZ_QK];
__device__ __align__(256) __half wh_pwup[SZ_PWUP];     // interleaved u1/u2
__device__ __align__(256) __half wh_pwd [SZ_QK];
__device__ __align__(256) __half wh_gu  [2*SZ_X];      // interleaved gate/up [8192][1024]
__device__ __align__(256) __half wh_down[SZ_X];

// ----------------- scratch -----------------
__device__ __align__(256) float  g_res [(size_t)MROWS*DD];
__device__ __align__(256) __half g_hh  [(size_t)MROWS*DD];
__device__ __align__(256) __half g_qkvh[(size_t)MROWS*NQKV];
__device__ __align__(256) __half g_qh  [(size_t)BB*HH*TT*HDIM];
__device__ __align__(256) __half g_kh  [(size_t)BB*KVH*TT*HDIM];
__device__ __align__(256) __half g_vth [(size_t)BB*KVH*HDIM*TT];
__device__ __align__(256) __half g_attnh[(size_t)MROWS*DD];
__device__ __align__(256) __half g_gh  [(size_t)MROWS*DD];
__device__ __align__(256) float  g_c   [(size_t)MROWS*DD];
__device__ __align__(256) __half g_ffh [(size_t)MROWS*DFF];

__device__ __forceinline__ uint32_t packh2(float a, float b) {
    __half2 h = __floats2half2_rn(a, b);
    return *reinterpret_cast<uint32_t*>(&h);
}

#define MMA_F16(acc, a, b0, b1)                                               \
    asm volatile(                                                             \
        "mma.sync.aligned.m16n8k16.row.col.f32.f16.f16.f32 "                  \
        "{%0,%1,%2,%3}, {%4,%5,%6,%7}, {%8,%9}, {%0,%1,%2,%3};"               \
        : "+f"((acc)[0]), "+f"((acc)[1]), "+f"((acc)[2]), "+f"((acc)[3])      \
        : "r"((a)[0]), "r"((a)[1]), "r"((a)[2]), "r"((a)[3]),                 \
          "r"(b0), "r"(b1))

__device__ __forceinline__ void cp16(uint32_t dst, const void* src) {
    asm volatile("cp.async.cg.shared.global [%0], [%1], 16;" :: "r"(dst), "l"(src));
}

// ----------------- weight transpose+convert: fp32 [K][N] -> half [rowmap(n)][K] -----------------
// imode 0: r=n ; 1: n<N/2 -> 2n else 2(n-N/2)+1 ; 2: r=2n ; 3: r=2n+1
__global__ void __launch_bounds__(256) wtrans_kernel(const float* __restrict__ in,
                                                     __half* __restrict__ out, int K, int N, int imode) {
    __shared__ float t[32][33];
    int kb = blockIdx.y * 32, nb = blockIdx.x * 32;
    int tx = threadIdx.x, ty = threadIdx.y;
#pragma unroll
    for (int i = ty; i < 32; i += 8)
        t[i][tx] = in[(size_t)(kb + i) * N + nb + tx];
    __syncthreads();
#pragma unroll
    for (int i = ty; i < 32; i += 8) {
        int n = nb + i;
        int r = (imode == 0) ? n
              : (imode == 1) ? ((n < N / 2) ? 2 * n : 2 * (n - N / 2) + 1)
              : (imode == 2) ? 2 * n : 2 * n + 1;
        out[(size_t)r * K + kb + tx] = __float2half(t[tx][i]);
    }
}

// ----------------- zcRMS over D=1024, half out -----------------
__global__ void __launch_bounds__(256) rmsnorm_kernel(const float* __restrict__ in,
                               const float* __restrict__ scale,
                               __half* __restrict__ out) {
    size_t row = blockIdx.x;
    const float* xr = in + row * DD;
    __half* orow = out + row * DD;
    int tid = threadIdx.x;
    float v[4];
    float ss = 0.f;
#pragma unroll
    for (int i = 0; i < 4; i++) { v[i] = xr[tid + i * 256]; ss += v[i] * v[i]; }
    __shared__ float red[256];
    red[tid] = ss; __syncthreads();
    for (int s = 128; s > 0; s >>= 1) { if (tid < s) red[tid] += red[tid + s]; __syncthreads(); }
    float inv = rsqrtf(red[0] / (float)DD + 1e-6f);
#pragma unroll
    for (int i = 0; i < 4; i++) {
        int c = tid + i * 256;
        orow[c] = __float2half((1.0f + scale[c]) * v[i] * inv);
    }
}

// ----------------- fp16 tensor-core GEMM -----------------
// MODE 1: C f32 = res+AB ; 5: Ch[M,N/2] = u1*sigmoid(u2)
// 6: Ch[M,N/2] = relu(even)*relu(odd) ; 7: Ch[M,N] = AB
#define BMT 128
#define BNT 128
#define BKT 32
#define ASTR 40
#define BSTR 40
#define STAGE_H (BMT*ASTR + BNT*BSTR)
#define TG_SMEM_BYTES (2*STAGE_H*2)

template <int MODE>
__global__ void __launch_bounds__(256, 2) tgemm_kernel(
    const __half* __restrict__ A, const __half* __restrict__ Wt,
    float* __restrict__ C, __half* __restrict__ Ch,
    const float* __restrict__ res,
    int M, int N, int K, int lda, int ldb)
{
    extern __shared__ __half smh[];
    int tid = threadIdx.x;
    int lane = tid & 31, warp = tid >> 5;
    int g = lane >> 2, q = lane & 3;
    int warp_m = warp >> 2;
    int warp_n = warp & 3;
    int m0 = blockIdx.y * BMT, n0 = blockIdx.x * BNT;
    const uint32_t s_u32 = (uint32_t)__cvta_generic_to_shared(smh);

    float acc[4][4][4];
#pragma unroll
    for (int mt = 0; mt < 4; mt++)
#pragma unroll
        for (int nt = 0; nt < 4; nt++)
#pragma unroll
            for (int r = 0; r < 4; r++) acc[mt][nt][r] = 0.f;

#define TG_ISSUE(s, k0) do {                                                          \
    uint32_t ab_ = s_u32 + (s) * (STAGE_H * 2);                                       \
    _Pragma("unroll")                                                                 \
    for (int j_ = 0; j_ < 2; j_++) {                                                  \
        int idx_ = j_ * 256 + tid; int r_ = idx_ >> 2, ch_ = idx_ & 3;                \
        cp16(ab_ + (uint32_t)(r_ * ASTR + ch_ * 8) * 2,                               \
             A + (size_t)(m0 + r_) * lda + (k0) + ch_ * 8);                           \
    }                                                                                 \
    uint32_t bb_ = ab_ + BMT * ASTR * 2;                                              \
    _Pragma("unroll")                                                                 \
    for (int j_ = 0; j_ < 2; j_++) {                                                  \
        int idx_ = j_ * 256 + tid; int r_ = idx_ >> 2, ch_ = idx_ & 3;                \
        cp16(bb_ + (uint32_t)(r_ * BSTR + ch_ * 8) * 2,                               \
             Wt + (size_t)(n0 + r_) * ldb + (k0) + ch_ * 8);                          \
    }                                                                                 \
    asm volatile("cp.async.commit_group;" ::: "memory");                              \
} while (0)

    int nk = K / BKT;
    TG_ISSUE(0, 0);

    for (int kt = 0; kt < nk; kt++) {
        int cur = kt & 1;
        asm volatile("cp.async.wait_group 0;" ::: "memory");
        __syncthreads();
        if (kt + 1 < nk) TG_ISSUE(cur ^ 1, (kt + 1) * BKT);

        uint32_t a_row = s_u32 + cur * (STAGE_H * 2)
                       + (uint32_t)((warp_m * 64 + (lane & 15)) * ASTR + (lane >> 4) * 8) * 2;
        const __half* BsH = smh + cur * STAGE_H + BMT * ASTR;

#pragma unroll
        for (int kk = 0; kk < 2; kk++) {
            uint32_t a[4][4];
#pragma unroll
            for (int mt = 0; mt < 4; mt++) {
                uint32_t addr = a_row + (uint32_t)(mt * 16 * ASTR + kk * 16) * 2;
                asm volatile("ldmatrix.sync.aligned.m8n8.x4.shared.b16 {%0,%1,%2,%3}, [%4];"
                             : "=r"(a[mt][0]), "=r"(a[mt][1]), "=r"(a[mt][2]), "=r"(a[mt][3])
                             : "r"(addr));
            }
#pragma unroll
            for (int nt = 0; nt < 4; nt++) {
                const __half* bp = BsH + (warp_n * 32 + nt * 8 + g) * BSTR + kk * 16 + 2 * q;
                uint32_t b0 = *reinterpret_cast<const uint32_t*>(bp);
                uint32_t b1 = *reinterpret_cast<const uint32_t*>(bp + 8);
#pragma unroll
                for (int mt = 0; mt < 4; mt++)
                    MMA_F16(acc[mt][nt], a[mt], b0, b1);
            }
        }
    }
#undef TG_ISSUE

#pragma unroll
    for (int mt = 0; mt < 4; mt++) {
#pragma unroll
        for (int nt = 0; nt < 4; nt++) {
            int colbase = n0 + warp_n * 32 + nt * 8;
#pragma unroll
            for (int half_ = 0; half_ < 2; half_++) {
                int row = m0 + warp_m * 64 + mt * 16 + g + half_ * 8;
                float v0 = acc[mt][nt][half_ * 2 + 0];
                float v1 = acc[mt][nt][half_ * 2 + 1];
                if (MODE == 5) {
                    size_t o = (size_t)row * (N >> 1) + (colbase >> 1) + q;
                    Ch[o] = __float2half(v0 / (1.0f + __expf(-v1)));
                } else if (MODE == 6) {
                    size_t o = (size_t)row * (N >> 1) + (colbase >> 1) + q;
                    Ch[o] = __float2half(fmaxf(v0, 0.f) * fmaxf(v1, 0.f));
                } else if (MODE == 7) {
                    size_t o = (size_t)row * N + colbase + 2 * q;
                    Ch[o]     = __float2half(v0);
                    Ch[o + 1] = __float2half(v1);
                } else {
                    size_t o = (size_t)row * N + colbase + 2 * q;
                    if (MODE == 1) { C[o] = v0 + res[o]; C[o + 1] = v1 + res[o + 1]; }
                }
            }
        }
    }
}

// ----------------- per-head zcRMS(64) + RoPE, half in/out; ldt = row stride of tmp -----------------
__global__ void __launch_bounds__(256) qkpost_kernel(const __half* __restrict__ tmp, int ldt,
                              const float* __restrict__ ns,
                              const float* __restrict__ cosp, const float* __restrict__ sinp,
                              __half* __restrict__ out, int NH) {
    int warp = threadIdx.x >> 5, lane = threadIdx.x & 31;
    int row = blockIdx.x * 8 + warp;
    if (row >= BB * TT * NH) return;
    int hh = row % NH;
    int bt = row / NH;
    int t = bt % TT;
    int b = bt / TT;
    const __half* xin = tmp + (size_t)bt * ldt + hh * HDIM;
    float x1 = __half2float(xin[lane]), x2 = __half2float(xin[lane + 32]);
    float ss = x1 * x1 + x2 * x2;
#pragma unroll
    for (int o = 16; o > 0; o >>= 1) ss += __shfl_xor_sync(0xffffffffu, ss, o);
    float inv = rsqrtf(ss / (float)HDIM + 1e-6f);
    float y1 = (1.0f + ns[lane]) * x1 * inv;
    float y2 = (1.0f + ns[lane + 32]) * x2 * inv;
    float c = cosp[t * HALF + lane];
    float s = sinp[t * HALF + lane];
    __half* orow = out + ((size_t)(b * NH + hh) * TT + t) * HDIM;
    orow[lane]      = __float2half(y1 * c - y2 * s);
    orow[lane + 32] = __float2half(y2 * c + y1 * s);
}

// ----------------- v transpose to (B,KVH,HD,T) half (reads qkv buffer cols 1280+) -----------------
__global__ void __launch_bounds__(256) vtrans_kernel() {
    int idx = blockIdx.x * blockDim.x + threadIdx.x;
    if (idx >= BB * TT * KVH * HDIM) return;
    int d = idx & 63;
    int r = idx >> 6;
    int hh = r % KVH;
    int bt = r / KVH;
    int t = bt % TT;
    int b = bt / TT;
    g_vth[(((size_t)(b * KVH + hh)) * HDIM + d) * TT + t] =
        g_qkvh[(size_t)bt * NQKV + 1280 + hh * HDIM + d];
}

// ----------------- fp16 tensor-core flash attention -----------------
#define FQR 128
#define FKV 64
#define FKSTR 72
#define FT_STAGE_H (FKV*FKSTR*2)
#define FT_SMEM_BYTES (2*FT_STAGE_H*2)

__global__ void __launch_bounds__(256) flash_tc_kernel() {
    extern __shared__ __half smh[];
    int tid = threadIdx.x;
    int lane = tid & 31, warp = tid >> 5;
    int g = lane >> 2, q = lane & 3;
    int z = blockIdx.y;
    int b = z / HH, h = z % HH;
    const __half* Q  = g_qh + (size_t)z * TT * HDIM;
    const __half* Kp = g_kh + (size_t)(b * KVH + h / REP) * TT * HDIM;
    const __half* Vt = g_vth + (size_t)(b * KVH + h / REP) * HDIM * TT;
    int i0 = blockIdx.x * FQR;
    const uint32_t s_u32 = (uint32_t)__cvta_generic_to_shared(smh);

    uint32_t qa[4][4];
    {
        const __half* Qw = Q + (size_t)(i0 + warp * 16) * HDIM;
#pragma unroll
        for (int kk = 0; kk < 4; kk++) {
            qa[kk][0] = *reinterpret_cast<const uint32_t*>(Qw + (size_t)g * HDIM + kk * 16 + 2 * q);
            qa[kk][1] = *reinterpret_cast<const uint32_t*>(Qw + (size_t)(g + 8) * HDIM + kk * 16 + 2 * q);
            qa[kk][2] = *reinterpret_cast<const uint32_t*>(Qw + (size_t)g * HDIM + kk * 16 + 2 * q + 8);
            qa[kk][3] = *reinterpret_cast<const uint32_t*>(Qw + (size_t)(g + 8) * HDIM + kk * 16 + 2 * q + 8);
        }
    }

    float o[8][4];
#pragma unroll
    for (int dt = 0; dt < 8; dt++)
#pragma unroll
        for (int r = 0; r < 4; r++) o[dt][r] = 0.f;
    float m0 = -1e30f, m1 = -1e30f, l0 = 0.f, l1 = 0.f;

#define FT_ISSUE(s, j0) do {                                                          \
    uint32_t kb_ = s_u32 + (s) * (FT_STAGE_H * 2);                                    \
    _Pragma("unroll")                                                                 \
    for (int j_ = 0; j_ < 2; j_++) {                                                  \
        int idx_ = j_ * 256 + tid; int r_ = idx_ >> 3, ch_ = idx_ & 7;                \
        cp16(kb_ + (uint32_t)(r_ * FKSTR + ch_ * 8) * 2,                              \
             Kp + (size_t)((j0) + r_) * HDIM + ch_ * 8);                              \
    }                                                                                 \
    uint32_t vb_ = kb_ + FKV * FKSTR * 2;                                             \
    _Pragma("unroll")                                                                 \
    for (int j_ = 0; j_ < 2; j_++) {                                                  \
        int idx_ = j_ * 256 + tid; int r_ = idx_ >> 3, ch_ = idx_ & 7;                \
        cp16(vb_ + (uint32_t)(r_ * FKSTR + ch_ * 8) * 2,                              \
             Vt + (size_t)r_ * TT + (j0) + ch_ * 8);                                  \
    }                                                                                 \
    asm volatile("cp.async.commit_group;" ::: "memory");                              \
} while (0)

    FT_ISSUE(0, 0);

    for (int it = 0; it < TT / FKV; it++) {
        int cur = it & 1;
        asm volatile("cp.async.wait_group 0;" ::: "memory");
        __syncthreads();
        if (it + 1 < TT / FKV) FT_ISSUE(cur ^ 1, (it + 1) * FKV);

        const __half* Ks = smh + cur * FT_STAGE_H;
        const __half* Vs = Ks + FKV * FKSTR;

        float s[8][4];
#pragma unroll
        for (int t = 0; t < 8; t++)
#pragma unroll
            for (int r = 0; r < 4; r++) s[t][r] = 0.f;
#pragma unroll
        for (int kk = 0; kk < 4; kk++)
#pragma unroll
            for (int t = 0; t < 8; t++) {
                const __half* kp = Ks + (8 * t + g) * FKSTR + kk * 16 + 2 * q;
                uint32_t b0 = *reinterpret_cast<const uint32_t*>(kp);
                uint32_t b1 = *reinterpret_cast<const uint32_t*>(kp + 8);
                MMA_F16(s[t], qa[kk], b0, b1);
            }

        float mx0 = -1e30f, mx1 = -1e30f;
#pragma unroll
        for (int t = 0; t < 8; t++) {
            s[t][0] *= 0.125f; s[t][1] *= 0.125f; s[t][2] *= 0.125f; s[t][3] *= 0.125f;
            mx0 = fmaxf(mx0, fmaxf(s[t][0], s[t][1]));
            mx1 = fmaxf(mx1, fmaxf(s[t][2], s[t][3]));
        }
#pragma unroll
        for (int off = 1; off < 4; off <<= 1) {
            mx0 = fmaxf(mx0, __shfl_xor_sync(0xffffffffu, mx0, off));
            mx1 = fmaxf(mx1, __shfl_xor_sync(0xffffffffu, mx1, off));
        }
        float mn0 = fmaxf(m0, mx0), mn1 = fmaxf(m1, mx1);
        float al0 = __expf(m0 - mn0), al1 = __expf(m1 - mn1);
        m0 = mn0; m1 = mn1;
        float rs0 = 0.f, rs1 = 0.f;
#pragma unroll
        for (int t = 0; t < 8; t++) {
            s[t][0] = __expf(s[t][0] - mn0);
            s[t][1] = __expf(s[t][1] - mn0);
            s[t][2] = __expf(s[t][2] - mn1);
            s[t][3] = __expf(s[t][3] - mn1);
            rs0 += s[t][0] + s[t][1];
            rs1 += s[t][2] + s[t][3];
        }
#pragma unroll
        for (int off = 1; off < 4; off <<= 1) {
            rs0 += __shfl_xor_sync(0xffffffffu, rs0, off);
            rs1 += __shfl_xor_sync(0xffffffffu, rs1, off);
        }
        l0 = l0 * al0 + rs0;
        l1 = l1 * al1 + rs1;
#pragma unroll
        for (int dt = 0; dt < 8; dt++) {
            o[dt][0] *= al0; o[dt][1] *= al0;
            o[dt][2] *= al1; o[dt][3] *= al1;
        }

#pragma unroll
        for (int kt = 0; kt < 4; kt++) {
            uint32_t pa[4];
            pa[0] = packh2(s[2 * kt][0],     s[2 * kt][1]);
            pa[1] = packh2(s[2 * kt][2],     s[2 * kt][3]);
            pa[2] = packh2(s[2 * kt + 1][0], s[2 * kt + 1][1]);
            pa[3] = packh2(s[2 * kt + 1][2], s[2 * kt + 1][3]);
#pragma unroll
            for (int dt = 0; dt < 8; dt++) {
                const __half* vp = Vs + (8 * dt + g) * FKSTR + kt * 16 + 2 * q;
                uint32_t b0 = *reinterpret_cast<const uint32_t*>(vp);
                uint32_t b1 = *reinterpret_cast<const uint32_t*>(vp + 8);
                MMA_F16(o[dt], pa, b0, b1);
            }
        }
    }
#undef FT_ISSUE

    float inv0 = 1.0f / l0, inv1 = 1.0f / l1;
    int r0 = i0 + warp * 16 + g;
    int r1 = r0 + 8;
    __half* out0 = g_attnh + ((size_t)(b * TT + r0) * HH + h) * HDIM;
    __half* out1 = g_attnh + ((size_t)(b * TT + r1) * HH + h) * HDIM;
#pragma unroll
    for (int dt = 0; dt < 8; dt++) {
        int c0 = 8 * dt + 2 * q;
        out0[c0]     = __float2half(o[dt][0] * inv0);
        out0[c0 + 1] = __float2half(o[dt][1] * inv0);
        out1[c0]     = __float2half(o[dt][2] * inv1);
        out1[c0 + 1] = __float2half(o[dt][3] * inv1);
    }
}

// ----------------- depthwise conv KW=15 SAME, 4 t per thread -----------------
__global__ void __launch_bounds__(256) dwconv_kernel(const float* __restrict__ dw) {
    int idx = blockIdx.x * blockDim.x + threadIdx.x;
    if (idx >= BB * (TT / 4) * DD) return;
    int d = idx & (DD - 1);
    int tq = (idx >> 10) & (TT / 4 - 1);
    int b = idx >> 19;
    float wv[KW];
#pragma unroll
    for (int w = 0; w < KW; w++) wv[w] = dw[w * DD + d];
    float gv[18];
    int tbase = tq * 4 - 7;
#pragma unroll
    for (int i = 0; i < 18; i++) {
        int t = tbase + i;
        gv[i] = (t >= 0 && t < TT) ? __half2float(g_gh[((size_t)(b * TT + t)) * DD + d]) : 0.f;
    }
#pragma unroll
    for (int j = 0; j < 4; j++) {
        float acc = 0.f;
#pragma unroll
        for (int w = 0; w < KW; w++) acc += gv[j + w] * wv[w];
        g_c[((size_t)(b * TT + tq * 4 + j)) * DD + d] = acc;
    }
}

// ----------------- staged-sync diagnostics (no-op while capturing) -----------------
static void dbg(const char* name) {
    cudaStreamCaptureStatus st = cudaStreamCaptureStatusActive;
    cudaError_t qe = cudaStreamIsCapturing((cudaStream_t)0, &st);
    if (qe != cudaSuccess || st != cudaStreamCaptureStatusNone) return;
    cudaError_t e = cudaStreamSynchronize((cudaStream_t)0);
    fprintf(stderr, "[dbg] %-12s -> %s\n", name, cudaGetErrorString(e));
}

extern "C" void kernel_launch(void* const* d_in, const int* in_sizes, int n_in,
                              void* d_out, int out_size) {
    if (n_in < 20) { fprintf(stderr, "[klaunch] unexpected n_in=%d\n", n_in); return; }

    const float* x       = (const float*)d_in[0];
    const float* cosp    = (const float*)d_in[2];
    const float* sinp    = (const float*)d_in[3];
    const float* attn_ns = (const float*)d_in[4];
    const float* qk      = (const float*)d_in[5];
    const float* kk      = (const float*)d_in[6];
    const float* vk      = (const float*)d_in[7];
    const float* qns     = (const float*)d_in[8];
    const float* kns     = (const float*)d_in[9];
    const float* ok      = (const float*)d_in[10];
    const float* conv_ns = (const float*)d_in[11];
    const float* pwup    = (const float*)d_in[12];
    const float* dwk     = (const float*)d_in[13];
    const float* cin_ns  = (const float*)d_in[14];
    const float* pwdown  = (const float*)d_in[15];
    const float* ffn_ns  = (const float*)d_in[16];
    const float* gatek   = (const float*)d_in[17];
    const float* upk     = (const float*)d_in[18];
    const float* downk   = (const float*)d_in[19];
    float* out = (float*)d_out;

    float *p_res, *p_c;
    __half *ph_h, *ph_qkvw, *ph_ok, *ph_pwup, *ph_pwd, *ph_gu, *ph_down;
    __half *ph_attn, *ph_ff, *ph_g, *ph_qkv, *ph_q, *ph_k, *ph_vt;
    cudaGetSymbolAddress((void**)&ph_qkvw, wh_qkv);
    cudaGetSymbolAddress((void**)&ph_ok, wh_ok);
    cudaGetSymbolAddress((void**)&ph_pwup, wh_pwup);
    cudaGetSymbolAddress((void**)&ph_pwd, wh_pwd);
    cudaGetSymbolAddress((void**)&ph_gu, wh_gu);
    cudaGetSymbolAddress((void**)&ph_down, wh_down);
    cudaGetSymbolAddress((void**)&p_res, g_res);
    cudaGetSymbolAddress((void**)&ph_h, g_hh);
    cudaGetSymbolAddress((void**)&ph_qkv, g_qkvh);
    cudaGetSymbolAddress((void**)&ph_attn, g_attnh);
    cudaGetSymbolAddress((void**)&ph_g, g_gh);
    cudaGetSymbolAddress((void**)&p_c, g_c);
    cudaGetSymbolAddress((void**)&ph_ff, g_ffh);
    cudaGetSymbolAddress((void**)&ph_q, g_qh);
    cudaGetSymbolAddress((void**)&ph_k, g_kh);
    cudaError_t es = cudaGetSymbolAddress((void**)&ph_vt, g_vth);
    if (es != cudaSuccess) { fprintf(stderr, "[sym] g_vth err=%d\n", (int)es); return; }

    cudaFuncSetAttribute(flash_tc_kernel, cudaFuncAttributeMaxDynamicSharedMemorySize, FT_SMEM_BYTES);
    cudaFuncSetAttribute(tgemm_kernel<1>, cudaFuncAttributeMaxDynamicSharedMemorySize, TG_SMEM_BYTES);
    cudaFuncSetAttribute(tgemm_kernel<5>, cudaFuncAttributeMaxDynamicSharedMemorySize, TG_SMEM_BYTES);
    cudaFuncSetAttribute(tgemm_kernel<6>, cudaFuncAttributeMaxDynamicSharedMemorySize, TG_SMEM_BYTES);
    es = cudaFuncSetAttribute(tgemm_kernel<7>, cudaFuncAttributeMaxDynamicSharedMemorySize, TG_SMEM_BYTES);
    if (es != cudaSuccess) fprintf(stderr, "[klaunch] smem attr err=%d\n", (int)es);

    // ---- transpose+convert weights (q/k/v packed into one [1536][1024] buffer) ----
    struct { const float* in; __half* out; int K; int N; int imode; } tw[9] = {
        {qk, ph_qkvw, DD, DD, 0},
        {kk, ph_qkvw + (size_t)1024 * DD, DD, 256, 0},
        {vk, ph_qkvw + (size_t)1280 * DD, DD, 256, 0},
        {ok, ph_ok, DD, DD, 0},
        {pwup, ph_pwup, DD, 2 * DD, 1},
        {pwdown, ph_pwd, DD, DD, 0},
        {gatek, ph_gu, DD, DFF, 2},
        {upk, ph_gu, DD, DFF, 3},
        {downk, ph_down, DFF, DD, 0}
    };
    for (int i = 0; i < 9; i++)
        wtrans_kernel<<<dim3(tw[i].N / 32, tw[i].K / 32), dim3(32, 8)>>>(tw[i].in, tw[i].out, tw[i].K, tw[i].N, tw[i].imode);
    dbg("wtrans");

    // ---- attention block ----
    rmsnorm_kernel<<<MROWS, 256>>>(x, attn_ns, ph_h);
    tgemm_kernel<7><<<dim3(NQKV / BNT, MROWS / BMT), 256, TG_SMEM_BYTES>>>(ph_h, ph_qkvw, nullptr, ph_qkv, nullptr, MROWS, NQKV, DD, DD, DD);
    dbg("qkv");
    qkpost_kernel<<<(BB * TT * HH) / 8, 256>>>(ph_qkv, NQKV, qns, cosp, sinp, ph_q, HH);
    qkpost_kernel<<<(BB * TT * KVH) / 8, 256>>>(ph_qkv + 1024, NQKV, kns, cosp, sinp, ph_k, KVH);
    vtrans_kernel<<<(BB * TT * KVH * HDIM) / 256, 256>>>();
    flash_tc_kernel<<<dim3(TT / FQR, BB * HH), 256, FT_SMEM_BYTES>>>();
    dbg("flash");
    tgemm_kernel<1><<<dim3(DD / BNT, MROWS / BMT), 256, TG_SMEM_BYTES>>>(ph_attn, ph_ok, p_res, nullptr, x, MROWS, DD, DD, DD, DD);
    dbg("oproj");

    // ---- conv block ----
    rmsnorm_kernel<<<MROWS, 256>>>(p_res, conv_ns, ph_h);
    tgemm_kernel<5><<<dim3((2 * DD) / BNT, MROWS / BMT), 256, TG_SMEM_BYTES>>>(ph_h, ph_pwup, nullptr, ph_g, nullptr, MROWS, 2 * DD, DD, DD, DD);
    dwconv_kernel<<<(BB * (TT / 4) * DD) / 256, 256>>>(dwk);
    rmsnorm_kernel<<<MROWS, 256>>>(p_c, cin_ns, ph_h);
    tgemm_kernel<1><<<dim3(DD / BNT, MROWS / BMT), 256, TG_SMEM_BYTES>>>(ph_h, ph_pwd, p_res, nullptr, p_res, MROWS, DD, DD, DD, DD);
    dbg("conv");

    // ---- FFN block ----
    rmsnorm_kernel<<<MROWS, 256>>>(p_res, ffn_ns, ph_h);
    tgemm_kernel<6><<<dim3((2 * DFF) / BNT, MROWS / BMT), 256, TG_SMEM_BYTES>>>(ph_h, ph_gu, nullptr, ph_ff, nullptr, MROWS, 2 * DFF, DD, DD, DD);
    tgemm_kernel<1><<<dim3(DD / BNT, MROWS / BMT), 256, TG_SMEM_BYTES>>>(ph_ff, ph_down, out, nullptr, p_res, MROWS, DD, DFF, DFF, DFF);
    dbg("ffn");
}

// round 14
// speedup vs baseline: 6.9734x; 1.1356x over previous
#include <cuda_runtime.h>
#include <cuda_fp16.h>
#include <math.h>
#include <stdint.h>
#include <stdio.h>

#define BB 2
#define TT 2048
#define DD 1024
#define HH 16
#define KVH 4
#define HDIM 64
#define HALF 32
#define DFF 4096
#define KW 15
#define MROWS (BB*TT)   // 4096
#define REP (HH/KVH)    // 4
#define NQKV 1536

#define SZ_QK   1048576
#define SZ_KK   262144
#define SZ_PWUP 2097152
#define SZ_X    4194304

// ----------------- fp16 transposed weights [N][K] (column-interleaved where fused) -----------------
__device__ __align__(256) __half wh_qkv [NQKV*DD];     // q rows 0-1023, k 1024-1279, v 1280-1535
__device__ __align__(256) __half wh_ok  [SZ_QK];
__device__ __align__(256) __half wh_pwup[SZ_PWUP];     // interleaved u1/u2
__device__ __align__(256) __half wh_pwd [SZ_QK];
__device__ __align__(256) __half wh_gu  [2*SZ_X];      // interleaved gate/up [8192][1024]
__device__ __align__(256) __half wh_down[SZ_X];

// ----------------- scratch -----------------
__device__ __align__(256) float  g_res [(size_t)MROWS*DD];
__device__ __align__(256) __half g_hh  [(size_t)MROWS*DD];
__device__ __align__(256) __half g_qkvh[(size_t)MROWS*NQKV];
__device__ __align__(256) __half g_qh  [(size_t)BB*HH*TT*HDIM];
__device__ __align__(256) __half g_kh  [(size_t)BB*KVH*TT*HDIM];
__device__ __align__(256) __half g_vth [(size_t)BB*KVH*HDIM*TT];
__device__ __align__(256) __half g_attnh[(size_t)MROWS*DD];
__device__ __align__(256) __half g_gh  [(size_t)MROWS*DD];
__device__ __align__(256) float  g_c   [(size_t)MROWS*DD];
__device__ __align__(256) __half g_ffh [(size_t)MROWS*DFF];

__device__ __forceinline__ uint32_t packh2(float a, float b) {
    __half2 h = __floats2half2_rn(a, b);
    return *reinterpret_cast<uint32_t*>(&h);
}

#define MMA_F16(acc, a, b0, b1)                                               \
    asm volatile(                                                             \
        "mma.sync.aligned.m16n8k16.row.col.f32.f16.f16.f32 "                  \
        "{%0,%1,%2,%3}, {%4,%5,%6,%7}, {%8,%9}, {%0,%1,%2,%3};"               \
        : "+f"((acc)[0]), "+f"((acc)[1]), "+f"((acc)[2]), "+f"((acc)[3])      \
        : "r"((a)[0]), "r"((a)[1]), "r"((a)[2]), "r"((a)[3]),                 \
          "r"(b0), "r"(b1))

__device__ __forceinline__ void cp16(uint32_t dst, const void* src) {
    asm volatile("cp.async.cg.shared.global [%0], [%1], 16;" :: "r"(dst), "l"(src));
}

// ----------------- weight transpose+convert: fp32 [K][N] -> half [rowmap(n)][K] -----------------
// imode 0: r=n ; 1: n<N/2 -> 2n else 2(n-N/2)+1 ; 2: r=2n ; 3: r=2n+1
__global__ void __launch_bounds__(256) wtrans_kernel(const float* __restrict__ in,
                                                     __half* __restrict__ out, int K, int N, int imode) {
    __shared__ float t[32][33];
    int kb = blockIdx.y * 32, nb = blockIdx.x * 32;
    int tx = threadIdx.x, ty = threadIdx.y;
#pragma unroll
    for (int i = ty; i < 32; i += 8)
        t[i][tx] = in[(size_t)(kb + i) * N + nb + tx];
    __syncthreads();
#pragma unroll
    for (int i = ty; i < 32; i += 8) {
        int n = nb + i;
        int r = (imode == 0) ? n
              : (imode == 1) ? ((n < N / 2) ? 2 * n : 2 * (n - N / 2) + 1)
              : (imode == 2) ? 2 * n : 2 * n + 1;
        out[(size_t)r * K + kb + tx] = __float2half(t[tx][i]);
    }
}

// ----------------- zcRMS over D=1024, half out -----------------
__global__ void __launch_bounds__(256) rmsnorm_kernel(const float* __restrict__ in,
                               const float* __restrict__ scale,
                               __half* __restrict__ out) {
    size_t row = blockIdx.x;
    const float* xr = in + row * DD;
    __half* orow = out + row * DD;
    int tid = threadIdx.x;
    float v[4];
    float ss = 0.f;
#pragma unroll
    for (int i = 0; i < 4; i++) { v[i] = xr[tid + i * 256]; ss += v[i] * v[i]; }
    __shared__ float red[256];
    red[tid] = ss; __syncthreads();
    for (int s = 128; s > 0; s >>= 1) { if (tid < s) red[tid] += red[tid + s]; __syncthreads(); }
    float inv = rsqrtf(red[0] / (float)DD + 1e-6f);
#pragma unroll
    for (int i = 0; i < 4; i++) {
        int c = tid + i * 256;
        orow[c] = __float2half((1.0f + scale[c]) * v[i] * inv);
    }
}

// ----------------- fp16 tensor-core GEMM, BKT=64 -----------------
// MODE 1: C f32 = res+AB ; 5: Ch[M,N/2] = u1*sigmoid(u2)
// 6: Ch[M,N/2] = relu(even)*relu(odd) ; 7: Ch[M,N] = AB
#define BMT 128
#define BNT 128
#define BKT 64
#define ASTR 72
#define BSTR 72
#define STAGE_H (BMT*ASTR + BNT*BSTR)            // 18432 halves = 36864 B
#define TG_SMEM_BYTES (2*STAGE_H*2)              // 73728 B

template <int MODE>
__global__ void __launch_bounds__(256, 2) tgemm_kernel(
    const __half* __restrict__ A, const __half* __restrict__ Wt,
    float* __restrict__ C, __half* __restrict__ Ch,
    const float* __restrict__ res,
    int M, int N, int K, int lda, int ldb)
{
    extern __shared__ __half smh[];
    int tid = threadIdx.x;
    int lane = tid & 31, warp = tid >> 5;
    int g = lane >> 2, q = lane & 3;
    int warp_m = warp >> 2;
    int warp_n = warp & 3;
    int m0 = blockIdx.y * BMT, n0 = blockIdx.x * BNT;
    const uint32_t s_u32 = (uint32_t)__cvta_generic_to_shared(smh);

    float acc[4][4][4];
#pragma unroll
    for (int mt = 0; mt < 4; mt++)
#pragma unroll
        for (int nt = 0; nt < 4; nt++)
#pragma unroll
            for (int r = 0; r < 4; r++) acc[mt][nt][r] = 0.f;

#define TG_ISSUE(s, k0) do {                                                          \
    uint32_t ab_ = s_u32 + (s) * (STAGE_H * 2);                                       \
    _Pragma("unroll")                                                                 \
    for (int j_ = 0; j_ < 4; j_++) {                                                  \
        int idx_ = j_ * 256 + tid; int r_ = idx_ >> 3, ch_ = idx_ & 7;                \
        cp16(ab_ + (uint32_t)(r_ * ASTR + ch_ * 8) * 2,                               \
             A + (size_t)(m0 + r_) * lda + (k0) + ch_ * 8);                           \
    }                                                                                 \
    uint32_t bb_ = ab_ + BMT * ASTR * 2;                                              \
    _Pragma("unroll")                                                                 \
    for (int j_ = 0; j_ < 4; j_++) {                                                  \
        int idx_ = j_ * 256 + tid; int r_ = idx_ >> 3, ch_ = idx_ & 7;                \
        cp16(bb_ + (uint32_t)(r_ * BSTR + ch_ * 8) * 2,                               \
             Wt + (size_t)(n0 + r_) * ldb + (k0) + ch_ * 8);                          \
    }                                                                                 \
    asm volatile("cp.async.commit_group;" ::: "memory");                              \
} while (0)

    int nk = K / BKT;
    TG_ISSUE(0, 0);

    for (int kt = 0; kt < nk; kt++) {
        int cur = kt & 1;
        asm volatile("cp.async.wait_group 0;" ::: "memory");
        __syncthreads();
        if (kt + 1 < nk) TG_ISSUE(cur ^ 1, (kt + 1) * BKT);

        uint32_t a_row = s_u32 + cur * (STAGE_H * 2)
                       + (uint32_t)((warp_m * 64 + (lane & 15)) * ASTR + (lane >> 4) * 8) * 2;
        const __half* BsH = smh + cur * STAGE_H + BMT * ASTR;

#pragma unroll
        for (int kk = 0; kk < 4; kk++) {       // four k16 steps
            uint32_t a[4][4];
#pragma unroll
            for (int mt = 0; mt < 4; mt++) {
                uint32_t addr = a_row + (uint32_t)(mt * 16 * ASTR + kk * 16) * 2;
                asm volatile("ldmatrix.sync.aligned.m8n8.x4.shared.b16 {%0,%1,%2,%3}, [%4];"
                             : "=r"(a[mt][0]), "=r"(a[mt][1]), "=r"(a[mt][2]), "=r"(a[mt][3])
                             : "r"(addr));
            }
#pragma unroll
            for (int nt = 0; nt < 4; nt++) {
                const __half* bp = BsH + (warp_n * 32 + nt * 8 + g) * BSTR + kk * 16 + 2 * q;
                uint32_t b0 = *reinterpret_cast<const uint32_t*>(bp);
                uint32_t b1 = *reinterpret_cast<const uint32_t*>(bp + 8);
#pragma unroll
                for (int mt = 0; mt < 4; mt++)
                    MMA_F16(acc[mt][nt], a[mt], b0, b1);
            }
        }
    }
#undef TG_ISSUE

#pragma unroll
    for (int mt = 0; mt < 4; mt++) {
#pragma unroll
        for (int nt = 0; nt < 4; nt++) {
            int colbase = n0 + warp_n * 32 + nt * 8;
#pragma unroll
            for (int half_ = 0; half_ < 2; half_++) {
                int row = m0 + warp_m * 64 + mt * 16 + g + half_ * 8;
                float v0 = acc[mt][nt][half_ * 2 + 0];
                float v1 = acc[mt][nt][half_ * 2 + 1];
                if (MODE == 5) {
                    size_t o = (size_t)row * (N >> 1) + (colbase >> 1) + q;
                    Ch[o] = __float2half(v0 / (1.0f + __expf(-v1)));
                } else if (MODE == 6) {
                    size_t o = (size_t)row * (N >> 1) + (colbase >> 1) + q;
                    Ch[o] = __float2half(fmaxf(v0, 0.f) * fmaxf(v1, 0.f));
                } else if (MODE == 7) {
                    size_t o = (size_t)row * N + colbase + 2 * q;
                    Ch[o]     = __float2half(v0);
                    Ch[o + 1] = __float2half(v1);
                } else {
                    size_t o = (size_t)row * N + colbase + 2 * q;
                    if (MODE == 1) { C[o] = v0 + res[o]; C[o + 1] = v1 + res[o + 1]; }
                }
            }
        }
    }
}

// ----------------- per-head zcRMS(64) + RoPE, half in/out; ldt = row stride of tmp -----------------
__global__ void __launch_bounds__(256) qkpost_kernel(const __half* __restrict__ tmp, int ldt,
                              const float* __restrict__ ns,
                              const float* __restrict__ cosp, const float* __restrict__ sinp,
                              __half* __restrict__ out, int NH) {
    int warp = threadIdx.x >> 5, lane = threadIdx.x & 31;
    int row = blockIdx.x * 8 + warp;
    if (row >= BB * TT * NH) return;
    int hh = row % NH;
    int bt = row / NH;
    int t = bt % TT;
    int b = bt / TT;
    const __half* xin = tmp + (size_t)bt * ldt + hh * HDIM;
    float x1 = __half2float(xin[lane]), x2 = __half2float(xin[lane + 32]);
    float ss = x1 * x1 + x2 * x2;
#pragma unroll
    for (int o = 16; o > 0; o >>= 1) ss += __shfl_xor_sync(0xffffffffu, ss, o);
    float inv = rsqrtf(ss / (float)HDIM + 1e-6f);
    float y1 = (1.0f + ns[lane]) * x1 * inv;
    float y2 = (1.0f + ns[lane + 32]) * x2 * inv;
    float c = cosp[t * HALF + lane];
    float s = sinp[t * HALF + lane];
    __half* orow = out + ((size_t)(b * NH + hh) * TT + t) * HDIM;
    orow[lane]      = __float2half(y1 * c - y2 * s);
    orow[lane + 32] = __float2half(y2 * c + y1 * s);
}

// ----------------- v transpose to (B,KVH,HD,T) half (reads qkv buffer cols 1280+) -----------------
__global__ void __launch_bounds__(256) vtrans_kernel() {
    int idx = blockIdx.x * blockDim.x + threadIdx.x;
    if (idx >= BB * TT * KVH * HDIM) return;
    int d = idx & 63;
    int r = idx >> 6;
    int hh = r % KVH;
    int bt = r / KVH;
    int t = bt % TT;
    int b = bt / TT;
    g_vth[(((size_t)(b * KVH + hh)) * HDIM + d) * TT + t] =
        g_qkvh[(size_t)bt * NQKV + 1280 + hh * HDIM + d];
}

// ----------------- fp16 tensor-core flash attention -----------------
#define FQR 128
#define FKV 64
#define FKSTR 72
#define FT_STAGE_H (FKV*FKSTR*2)
#define FT_SMEM_BYTES (2*FT_STAGE_H*2)

__global__ void __launch_bounds__(256) flash_tc_kernel() {
    extern __shared__ __half smh[];
    int tid = threadIdx.x;
    int lane = tid & 31, warp = tid >> 5;
    int g = lane >> 2, q = lane & 3;
    int z = blockIdx.y;
    int b = z / HH, h = z % HH;
    const __half* Q  = g_qh + (size_t)z * TT * HDIM;
    const __half* Kp = g_kh + (size_t)(b * KVH + h / REP) * TT * HDIM;
    const __half* Vt = g_vth + (size_t)(b * KVH + h / REP) * HDIM * TT;
    int i0 = blockIdx.x * FQR;
    const uint32_t s_u32 = (uint32_t)__cvta_generic_to_shared(smh);

    uint32_t qa[4][4];
    {
        const __half* Qw = Q + (size_t)(i0 + warp * 16) * HDIM;
#pragma unroll
        for (int kk = 0; kk < 4; kk++) {
            qa[kk][0] = *reinterpret_cast<const uint32_t*>(Qw + (size_t)g * HDIM + kk * 16 + 2 * q);
            qa[kk][1] = *reinterpret_cast<const uint32_t*>(Qw + (size_t)(g + 8) * HDIM + kk * 16 + 2 * q);
            qa[kk][2] = *reinterpret_cast<const uint32_t*>(Qw + (size_t)g * HDIM + kk * 16 + 2 * q + 8);
            qa[kk][3] = *reinterpret_cast<const uint32_t*>(Qw + (size_t)(g + 8) * HDIM + kk * 16 + 2 * q + 8);
        }
    }

    float o[8][4];
#pragma unroll
    for (int dt = 0; dt < 8; dt++)
#pragma unroll
        for (int r = 0; r < 4; r++) o[dt][r] = 0.f;
    float m0 = -1e30f, m1 = -1e30f, l0 = 0.f, l1 = 0.f;

#define FT_ISSUE(s, j0) do {                                                          \
    uint32_t kb_ = s_u32 + (s) * (FT_STAGE_H * 2);                                    \
    _Pragma("unroll")                                                                 \
    for (int j_ = 0; j_ < 2; j_++) {                                                  \
        int idx_ = j_ * 256 + tid; int r_ = idx_ >> 3, ch_ = idx_ & 7;                \
        cp16(kb_ + (uint32_t)(r_ * FKSTR + ch_ * 8) * 2,                              \
             Kp + (size_t)((j0) + r_) * HDIM + ch_ * 8);                              \
    }                                                                                 \
    uint32_t vb_ = kb_ + FKV * FKSTR * 2;                                             \
    _Pragma("unroll")                                                                 \
    for (int j_ = 0; j_ < 2; j_++) {                                                  \
        int idx_ = j_ * 256 + tid; int r_ = idx_ >> 3, ch_ = idx_ & 7;                \
        cp16(vb_ + (uint32_t)(r_ * FKSTR + ch_ * 8) * 2,                              \
             Vt + (size_t)r_ * TT + (j0) + ch_ * 8);                                  \
    }                                                                                 \
    asm volatile("cp.async.commit_group;" ::: "memory");                              \
} while (0)

    FT_ISSUE(0, 0);

    for (int it = 0; it < TT / FKV; it++) {
        int cur = it & 1;
        asm volatile("cp.async.wait_group 0;" ::: "memory");
        __syncthreads();
        if (it + 1 < TT / FKV) FT_ISSUE(cur ^ 1, (it + 1) * FKV);

        const __half* Ks = smh + cur * FT_STAGE_H;
        const __half* Vs = Ks + FKV * FKSTR;

        float s[8][4];
#pragma unroll
        for (int t = 0; t < 8; t++)
#pragma unroll
            for (int r = 0; r < 4; r++) s[t][r] = 0.f;
#pragma unroll
        for (int kk = 0; kk < 4; kk++)
#pragma unroll
            for (int t = 0; t < 8; t++) {
                const __half* kp = Ks + (8 * t + g) * FKSTR + kk * 16 + 2 * q;
                uint32_t b0 = *reinterpret_cast<const uint32_t*>(kp);
                uint32_t b1 = *reinterpret_cast<const uint32_t*>(kp + 8);
                MMA_F16(s[t], qa[kk], b0, b1);
            }

        float mx0 = -1e30f, mx1 = -1e30f;
#pragma unroll
        for (int t = 0; t < 8; t++) {
            s[t][0] *= 0.125f; s[t][1] *= 0.125f; s[t][2] *= 0.125f; s[t][3] *= 0.125f;
            mx0 = fmaxf(mx0, fmaxf(s[t][0], s[t][1]));
            mx1 = fmaxf(mx1, fmaxf(s[t][2], s[t][3]));
        }
#pragma unroll
        for (int off = 1; off < 4; off <<= 1) {
            mx0 = fmaxf(mx0, __shfl_xor_sync(0xffffffffu, mx0, off));
            mx1 = fmaxf(mx1, __shfl_xor_sync(0xffffffffu, mx1, off));
        }
        float mn0 = fmaxf(m0, mx0), mn1 = fmaxf(m1, mx1);
        float al0 = __expf(m0 - mn0), al1 = __expf(m1 - mn1);
        m0 = mn0; m1 = mn1;
        float rs0 = 0.f, rs1 = 0.f;
#pragma unroll
        for (int t = 0; t < 8; t++) {
            s[t][0] = __expf(s[t][0] - mn0);
            s[t][1] = __expf(s[t][1] - mn0);
            s[t][2] = __expf(s[t][2] - mn1);
            s[t][3] = __expf(s[t][3] - mn1);
            rs0 += s[t][0] + s[t][1];
            rs1 += s[t][2] + s[t][3];
        }
#pragma unroll
        for (int off = 1; off < 4; off <<= 1) {
            rs0 += __shfl_xor_sync(0xffffffffu, rs0, off);
            rs1 += __shfl_xor_sync(0xffffffffu, rs1, off);
        }
        l0 = l0 * al0 + rs0;
        l1 = l1 * al1 + rs1;
#pragma unroll
        for (int dt = 0; dt < 8; dt++) {
            o[dt][0] *= al0; o[dt][1] *= al0;
            o[dt][2] *= al1; o[dt][3] *= al1;
        }

#pragma unroll
        for (int kt = 0; kt < 4; kt++) {
            uint32_t pa[4];
            pa[0] = packh2(s[2 * kt][0],     s[2 * kt][1]);
            pa[1] = packh2(s[2 * kt][2],     s[2 * kt][3]);
            pa[2] = packh2(s[2 * kt + 1][0], s[2 * kt + 1][1]);
            pa[3] = packh2(s[2 * kt + 1][2], s[2 * kt + 1][3]);
#pragma unroll
            for (int dt = 0; dt < 8; dt++) {
                const __half* vp = Vs + (8 * dt + g) * FKSTR + kt * 16 + 2 * q;
                uint32_t b0 = *reinterpret_cast<const uint32_t*>(vp);
                uint32_t b1 = *reinterpret_cast<const uint32_t*>(vp + 8);
                MMA_F16(o[dt], pa, b0, b1);
            }
        }
    }
#undef FT_ISSUE

    float inv0 = 1.0f / l0, inv1 = 1.0f / l1;
    int r0 = i0 + warp * 16 + g;
    int r1 = r0 + 8;
    __half* out0 = g_attnh + ((size_t)(b * TT + r0) * HH + h) * HDIM;
    __half* out1 = g_attnh + ((size_t)(b * TT + r1) * HH + h) * HDIM;
#pragma unroll
    for (int dt = 0; dt < 8; dt++) {
        int c0 = 8 * dt + 2 * q;
        out0[c0]     = __float2half(o[dt][0] * inv0);
        out0[c0 + 1] = __float2half(o[dt][1] * inv0);
        out1[c0]     = __float2half(o[dt][2] * inv1);
        out1[c0 + 1] = __float2half(o[dt][3] * inv1);
    }
}

// ----------------- depthwise conv KW=15 SAME, 4 t per thread -----------------
__global__ void __launch_bounds__(256) dwconv_kernel(const float* __restrict__ dw) {
    int idx = blockIdx.x * blockDim.x + threadIdx.x;
    if (idx >= BB * (TT / 4) * DD) return;
    int d = idx & (DD - 1);
    int tq = (idx >> 10) & (TT / 4 - 1);
    int b = idx >> 19;
    float wv[KW];
#pragma unroll
    for (int w = 0; w < KW; w++) wv[w] = dw[w * DD + d];
    float gv[18];
    int tbase = tq * 4 - 7;
#pragma unroll
    for (int i = 0; i < 18; i++) {
        int t = tbase + i;
        gv[i] = (t >= 0 && t < TT) ? __half2float(g_gh[((size_t)(b * TT + t)) * DD + d]) : 0.f;
    }
#pragma unroll
    for (int j = 0; j < 4; j++) {
        float acc = 0.f;
#pragma unroll
        for (int w = 0; w < KW; w++) acc += gv[j + w] * wv[w];
        g_c[((size_t)(b * TT + tq * 4 + j)) * DD + d] = acc;
    }
}

// ----------------- staged-sync diagnostics (no-op while capturing) -----------------
static void dbg(const char* name) {
    cudaStreamCaptureStatus st = cudaStreamCaptureStatusActive;
    cudaError_t qe = cudaStreamIsCapturing((cudaStream_t)0, &st);
    if (qe != cudaSuccess || st != cudaStreamCaptureStatusNone) return;
    cudaError_t e = cudaStreamSynchronize((cudaStream_t)0);
    fprintf(stderr, "[dbg] %-12s -> %s\n", name, cudaGetErrorString(e));
}

extern "C" void kernel_launch(void* const* d_in, const int* in_sizes, int n_in,
                              void* d_out, int out_size) {
    if (n_in < 20) { fprintf(stderr, "[klaunch] unexpected n_in=%d\n", n_in); return; }

    const float* x       = (const float*)d_in[0];
    const float* cosp    = (const float*)d_in[2];
    const float* sinp    = (const float*)d_in[3];
    const float* attn_ns = (const float*)d_in[4];
    const float* qk      = (const float*)d_in[5];
    const float* kk      = (const float*)d_in[6];
    const float* vk      = (const float*)d_in[7];
    const float* qns     = (const float*)d_in[8];
    const float* kns     = (const float*)d_in[9];
    const float* ok      = (const float*)d_in[10];
    const float* conv_ns = (const float*)d_in[11];
    const float* pwup    = (const float*)d_in[12];
    const float* dwk     = (const float*)d_in[13];
    const float* cin_ns  = (const float*)d_in[14];
    const float* pwdown  = (const float*)d_in[15];
    const float* ffn_ns  = (const float*)d_in[16];
    const float* gatek   = (const float*)d_in[17];
    const float* upk     = (const float*)d_in[18];
    const float* downk   = (const float*)d_in[19];
    float* out = (float*)d_out;

    float *p_res, *p_c;
    __half *ph_h, *ph_qkvw, *ph_ok, *ph_pwup, *ph_pwd, *ph_gu, *ph_down;
    __half *ph_attn, *ph_ff, *ph_g, *ph_qkv, *ph_q, *ph_k, *ph_vt;
    cudaGetSymbolAddress((void**)&ph_qkvw, wh_qkv);
    cudaGetSymbolAddress((void**)&ph_ok, wh_ok);
    cudaGetSymbolAddress((void**)&ph_pwup, wh_pwup);
    cudaGetSymbolAddress((void**)&ph_pwd, wh_pwd);
    cudaGetSymbolAddress((void**)&ph_gu, wh_gu);
    cudaGetSymbolAddress((void**)&ph_down, wh_down);
    cudaGetSymbolAddress((void**)&p_res, g_res);
    cudaGetSymbolAddress((void**)&ph_h, g_hh);
    cudaGetSymbolAddress((void**)&ph_qkv, g_qkvh);
    cudaGetSymbolAddress((void**)&ph_attn, g_attnh);
    cudaGetSymbolAddress((void**)&ph_g, g_gh);
    cudaGetSymbolAddress((void**)&p_c, g_c);
    cudaGetSymbolAddress((void**)&ph_ff, g_ffh);
    cudaGetSymbolAddress((void**)&ph_q, g_qh);
    cudaGetSymbolAddress((void**)&ph_k, g_kh);
    cudaError_t es = cudaGetSymbolAddress((void**)&ph_vt, g_vth);
    if (es != cudaSuccess) { fprintf(stderr, "[sym] g_vth err=%d\n", (int)es); return; }

    cudaFuncSetAttribute(flash_tc_kernel, cudaFuncAttributeMaxDynamicSharedMemorySize, FT_SMEM_BYTES);
    cudaFuncSetAttribute(tgemm_kernel<1>, cudaFuncAttributeMaxDynamicSharedMemorySize, TG_SMEM_BYTES);
    cudaFuncSetAttribute(tgemm_kernel<5>, cudaFuncAttributeMaxDynamicSharedMemorySize, TG_SMEM_BYTES);
    cudaFuncSetAttribute(tgemm_kernel<6>, cudaFuncAttributeMaxDynamicSharedMemorySize, TG_SMEM_BYTES);
    es = cudaFuncSetAttribute(tgemm_kernel<7>, cudaFuncAttributeMaxDynamicSharedMemorySize, TG_SMEM_BYTES);
    if (es != cudaSuccess) fprintf(stderr, "[klaunch] smem attr err=%d\n", (int)es);

    // ---- transpose+convert weights (q/k/v packed into one [1536][1024] buffer) ----
    struct { const float* in; __half* out; int K; int N; int imode; } tw[9] = {
        {qk, ph_qkvw, DD, DD, 0},
        {kk, ph_qkvw + (size_t)1024 * DD, DD, 256, 0},
        {vk, ph_qkvw + (size_t)1280 * DD, DD, 256, 0},
        {ok, ph_ok, DD, DD, 0},
        {pwup, ph_pwup, DD, 2 * DD, 1},
        {pwdown, ph_pwd, DD, DD, 0},
        {gatek, ph_gu, DD, DFF, 2},
        {upk, ph_gu, DD, DFF, 3},
        {downk, ph_down, DFF, DD, 0}
    };
    for (int i = 0; i < 9; i++)
        wtrans_kernel<<<dim3(tw[i].N / 32, tw[i].K / 32), dim3(32, 8)>>>(tw[i].in, tw[i].out, tw[i].K, tw[i].N, tw[i].imode);
    dbg("wtrans");

    // ---- attention block ----
    rmsnorm_kernel<<<MROWS, 256>>>(x, attn_ns, ph_h);
    tgemm_kernel<7><<<dim3(NQKV / BNT, MROWS / BMT), 256, TG_SMEM_BYTES>>>(ph_h, ph_qkvw, nullptr, ph_qkv, nullptr, MROWS, NQKV, DD, DD, DD);
    dbg("qkv");
    qkpost_kernel<<<(BB * TT * HH) / 8, 256>>>(ph_qkv, NQKV, qns, cosp, sinp, ph_q, HH);
    qkpost_kernel<<<(BB * TT * KVH) / 8, 256>>>(ph_qkv + 1024, NQKV, kns, cosp, sinp, ph_k, KVH);
    vtrans_kernel<<<(BB * TT * KVH * HDIM) / 256, 256>>>();
    flash_tc_kernel<<<dim3(TT / FQR, BB * HH), 256, FT_SMEM_BYTES>>>();
    dbg("flash");
    tgemm_kernel<1><<<dim3(DD / BNT, MROWS / BMT), 256, TG_SMEM_BYTES>>>(ph_attn, ph_ok, p_res, nullptr, x, MROWS, DD, DD, DD, DD);
    dbg("oproj");

    // ---- conv block ----
    rmsnorm_kernel<<<MROWS, 256>>>(p_res, conv_ns, ph_h);
    tgemm_kernel<5><<<dim3((2 * DD) / BNT, MROWS / BMT), 256, TG_SMEM_BYTES>>>(ph_h, ph_pwup, nullptr, ph_g, nullptr, MROWS, 2 * DD, DD, DD, DD);
    dwconv_kernel<<<(BB * (TT / 4) * DD) / 256, 256>>>(dwk);
    rmsnorm_kernel<<<MROWS, 256>>>(p_c, cin_ns, ph_h);
    tgemm_kernel<1><<<dim3(DD / BNT, MROWS / BMT), 256, TG_SMEM_BYTES>>>(ph_h, ph_pwd, p_res, nullptr, p_res, MROWS, DD, DD, DD, DD);
    dbg("conv");

    // ---- FFN block ----
    rmsnorm_kernel<<<MROWS, 256>>>(p_res, ffn_ns, ph_h);
    tgemm_kernel<6><<<dim3((2 * DFF) / BNT, MROWS / BMT), 256, TG_SMEM_BYTES>>>(ph_h, ph_gu, nullptr, ph_ff, nullptr, MROWS, 2 * DFF, DD, DD, DD);
    tgemm_kernel<1><<<dim3(DD / BNT, MROWS / BMT), 256, TG_SMEM_BYTES>>>(ph_ff, ph_down, out, nullptr, p_res, MROWS, DD, DFF, DFF, DFF);
    dbg("ffn");
}

// round 15
// speedup vs baseline: 7.0460x; 1.0104x over previous
#include <cuda_runtime.h>
#include <cuda_fp16.h>
#include <math.h>
#include <stdint.h>
#include <stdio.h>

#define BB 2
#define TT 2048
#define DD 1024
#define HH 16
#define KVH 4
#define HDIM 64
#define HALF 32
#define DFF 4096
#define KW 15
#define MROWS (BB*TT)   // 4096
#define REP (HH/KVH)    // 4
#define NQKV 1536

#define SZ_QK   1048576
#define SZ_KK   262144
#define SZ_PWUP 2097152
#define SZ_X    4194304

// ----------------- fp16 transposed weights [N][K] (column-interleaved where fused) -----------------
__device__ __align__(256) __half wh_qkv [NQKV*DD];
__device__ __align__(256) __half wh_ok  [SZ_QK];
__device__ __align__(256) __half wh_pwup[SZ_PWUP];
__device__ __align__(256) __half wh_pwd [SZ_QK];
__device__ __align__(256) __half wh_gu  [2*SZ_X];
__device__ __align__(256) __half wh_down[SZ_X];

// ----------------- scratch -----------------
__device__ __align__(256) float  g_res [(size_t)MROWS*DD];
__device__ __align__(256) __half g_hh  [(size_t)MROWS*DD];
__device__ __align__(256) __half g_qkvh[(size_t)MROWS*NQKV];
__device__ __align__(256) __half g_qh  [(size_t)BB*HH*TT*HDIM];
__device__ __align__(256) __half g_kh  [(size_t)BB*KVH*TT*HDIM];
__device__ __align__(256) __half g_vth [(size_t)BB*KVH*HDIM*TT];
__device__ __align__(256) __half g_attnh[(size_t)MROWS*DD];
__device__ __align__(256) __half g_gh  [(size_t)MROWS*DD];
__device__ __align__(256) float  g_c   [(size_t)MROWS*DD];
__device__ __align__(256) __half g_ffh [(size_t)MROWS*DFF];

__device__ __forceinline__ uint32_t packh2(float a, float b) {
    __half2 h = __floats2half2_rn(a, b);
    return *reinterpret_cast<uint32_t*>(&h);
}

#define MMA_F16(acc, a, b0, b1)                                               \
    asm volatile(                                                             \
        "mma.sync.aligned.m16n8k16.row.col.f32.f16.f16.f32 "                  \
        "{%0,%1,%2,%3}, {%4,%5,%6,%7}, {%8,%9}, {%0,%1,%2,%3};"               \
        : "+f"((acc)[0]), "+f"((acc)[1]), "+f"((acc)[2]), "+f"((acc)[3])      \
        : "r"((a)[0]), "r"((a)[1]), "r"((a)[2]), "r"((a)[3]),                 \
          "r"(b0), "r"(b1))

__device__ __forceinline__ void cp16(uint32_t dst, const void* src) {
    asm volatile("cp.async.cg.shared.global [%0], [%1], 16;" :: "r"(dst), "l"(src));
}

// ----------------- merged weight transpose+convert: fp32 [K][N] -> half [rowmap(n)][K] -----------------
struct WTDesc { const float* in; __half* out; int K; int N; int imode; int boff; };
struct WTPack { WTDesc d[9]; int total; };

__global__ void __launch_bounds__(256) wtrans_all_kernel(WTPack p) {
    __shared__ float t[32][33];
    int bid = blockIdx.x;
    int wi = 0;
#pragma unroll
    for (int i = 1; i < 9; i++) if (bid >= p.d[i].boff) wi = i;
    const WTDesc& D = p.d[wi];
    int local = bid - D.boff;
    int nbx = D.N >> 5;
    int kb = (local / nbx) * 32, nb = (local % nbx) * 32;
    int tx = threadIdx.x, ty = threadIdx.y;
#pragma unroll
    for (int i = ty; i < 32; i += 8)
        t[i][tx] = D.in[(size_t)(kb + i) * D.N + nb + tx];
    __syncthreads();
#pragma unroll
    for (int i = ty; i < 32; i += 8) {
        int n = nb + i;
        int r = (D.imode == 0) ? n
              : (D.imode == 1) ? ((n < D.N / 2) ? 2 * n : 2 * (n - D.N / 2) + 1)
              : (D.imode == 2) ? 2 * n : 2 * n + 1;
        D.out[(size_t)r * D.K + kb + tx] = __float2half(t[tx][i]);
    }
}

// ----------------- zcRMS over D=1024, half out -----------------
__global__ void __launch_bounds__(256) rmsnorm_kernel(const float* __restrict__ in,
                               const float* __restrict__ scale,
                               __half* __restrict__ out) {
    size_t row = blockIdx.x;
    const float* xr = in + row * DD;
    __half* orow = out + row * DD;
    int tid = threadIdx.x;
    float v[4];
    float ss = 0.f;
#pragma unroll
    for (int i = 0; i < 4; i++) { v[i] = xr[tid + i * 256]; ss += v[i] * v[i]; }
    __shared__ float red[256];
    red[tid] = ss; __syncthreads();
    for (int s = 128; s > 0; s >>= 1) { if (tid < s) red[tid] += red[tid + s]; __syncthreads(); }
    float inv = rsqrtf(red[0] / (float)DD + 1e-6f);
#pragma unroll
    for (int i = 0; i < 4; i++) {
        int c = tid + i * 256;
        orow[c] = __float2half((1.0f + scale[c]) * v[i] * inv);
    }
}

// ----------------- fp16 tensor-core GEMM, BKT=64, 3-stage pipeline -----------------
// MODE 1: C f32 = res+AB ; 5: Ch[M,N/2] = u1*sigmoid(u2)
// 6: Ch[M,N/2] = relu(even)*relu(odd) ; 7: Ch[M,N] = AB
#define BMT 128
#define BNT 128
#define BKT 64
#define ASTR 72
#define BSTR 72
#define STAGE_H (BMT*ASTR + BNT*BSTR)            // 18432 halves = 36864 B
#define TG_SMEM_BYTES (3*STAGE_H*2)              // 110592 B

template <int MODE>
__global__ void __launch_bounds__(256, 2) tgemm_kernel(
    const __half* __restrict__ A, const __half* __restrict__ Wt,
    float* __restrict__ C, __half* __restrict__ Ch,
    const float* __restrict__ res,
    int M, int N, int K, int lda, int ldb)
{
    extern __shared__ __half smh[];
    int tid = threadIdx.x;
    int lane = tid & 31, warp = tid >> 5;
    int g = lane >> 2, q = lane & 3;
    int warp_m = warp >> 2;
    int warp_n = warp & 3;
    int m0 = blockIdx.y * BMT, n0 = blockIdx.x * BNT;
    const uint32_t s_u32 = (uint32_t)__cvta_generic_to_shared(smh);

    float acc[4][4][4];
#pragma unroll
    for (int mt = 0; mt < 4; mt++)
#pragma unroll
        for (int nt = 0; nt < 4; nt++)
#pragma unroll
            for (int r = 0; r < 4; r++) acc[mt][nt][r] = 0.f;

#define TG_ISSUE(s, k0) do {                                                          \
    uint32_t ab_ = s_u32 + (s) * (STAGE_H * 2);                                       \
    _Pragma("unroll")                                                                 \
    for (int j_ = 0; j_ < 4; j_++) {                                                  \
        int idx_ = j_ * 256 + tid; int r_ = idx_ >> 3, ch_ = idx_ & 7;                \
        cp16(ab_ + (uint32_t)(r_ * ASTR + ch_ * 8) * 2,                               \
             A + (size_t)(m0 + r_) * lda + (k0) + ch_ * 8);                           \
    }                                                                                 \
    uint32_t bb_ = ab_ + BMT * ASTR * 2;                                              \
    _Pragma("unroll")                                                                 \
    for (int j_ = 0; j_ < 4; j_++) {                                                  \
        int idx_ = j_ * 256 + tid; int r_ = idx_ >> 3, ch_ = idx_ & 7;                \
        cp16(bb_ + (uint32_t)(r_ * BSTR + ch_ * 8) * 2,                               \
             Wt + (size_t)(n0 + r_) * ldb + (k0) + ch_ * 8);                          \
    }                                                                                 \
    asm volatile("cp.async.commit_group;" ::: "memory");                              \
} while (0)

    int nk = K / BKT;
    TG_ISSUE(0, 0);
    TG_ISSUE(1, BKT);

    for (int kt = 0; kt < nk; kt++) {
        int cur = kt % 3;
        asm volatile("cp.async.wait_group 1;" ::: "memory");
        __syncthreads();
        if (kt + 2 < nk) TG_ISSUE((kt + 2) % 3, (kt + 2) * BKT);

        uint32_t a_row = s_u32 + cur * (STAGE_H * 2)
                       + (uint32_t)((warp_m * 64 + (lane & 15)) * ASTR + (lane >> 4) * 8) * 2;
        const __half* BsH = smh + cur * STAGE_H + BMT * ASTR;

#pragma unroll
        for (int kk = 0; kk < 4; kk++) {
            uint32_t a[4][4];
#pragma unroll
            for (int mt = 0; mt < 4; mt++) {
                uint32_t addr = a_row + (uint32_t)(mt * 16 * ASTR + kk * 16) * 2;
                asm volatile("ldmatrix.sync.aligned.m8n8.x4.shared.b16 {%0,%1,%2,%3}, [%4];"
                             : "=r"(a[mt][0]), "=r"(a[mt][1]), "=r"(a[mt][2]), "=r"(a[mt][3])
                             : "r"(addr));
            }
#pragma unroll
            for (int nt = 0; nt < 4; nt++) {
                const __half* bp = BsH + (warp_n * 32 + nt * 8 + g) * BSTR + kk * 16 + 2 * q;
                uint32_t b0 = *reinterpret_cast<const uint32_t*>(bp);
                uint32_t b1 = *reinterpret_cast<const uint32_t*>(bp + 8);
#pragma unroll
                for (int mt = 0; mt < 4; mt++)
                    MMA_F16(acc[mt][nt], a[mt], b0, b1);
            }
        }
    }
#undef TG_ISSUE

#pragma unroll
    for (int mt = 0; mt < 4; mt++) {
#pragma unroll
        for (int nt = 0; nt < 4; nt++) {
            int colbase = n0 + warp_n * 32 + nt * 8;
#pragma unroll
            for (int half_ = 0; half_ < 2; half_++) {
                int row = m0 + warp_m * 64 + mt * 16 + g + half_ * 8;
                float v0 = acc[mt][nt][half_ * 2 + 0];
                float v1 = acc[mt][nt][half_ * 2 + 1];
                if (MODE == 5) {
                    size_t o = (size_t)row * (N >> 1) + (colbase >> 1) + q;
                    Ch[o] = __float2half(v0 / (1.0f + __expf(-v1)));
                } else if (MODE == 6) {
                    size_t o = (size_t)row * (N >> 1) + (colbase >> 1) + q;
                    Ch[o] = __float2half(fmaxf(v0, 0.f) * fmaxf(v1, 0.f));
                } else if (MODE == 7) {
                    size_t o = (size_t)row * N + colbase + 2 * q;
                    Ch[o]     = __float2half(v0);
                    Ch[o + 1] = __float2half(v1);
                } else {
                    size_t o = (size_t)row * N + colbase + 2 * q;
                    if (MODE == 1) { C[o] = v0 + res[o]; C[o + 1] = v1 + res[o + 1]; }
                }
            }
        }
    }
}

// ----------------- per-head zcRMS(64) + RoPE, half in/out; ldt = row stride of tmp -----------------
__global__ void __launch_bounds__(256) qkpost_kernel(const __half* __restrict__ tmp, int ldt,
                              const float* __restrict__ ns,
                              const float* __restrict__ cosp, const float* __restrict__ sinp,
                              __half* __restrict__ out, int NH) {
    int warp = threadIdx.x >> 5, lane = threadIdx.x & 31;
    int row = blockIdx.x * 8 + warp;
    if (row >= BB * TT * NH) return;
    int hh = row % NH;
    int bt = row / NH;
    int t = bt % TT;
    int b = bt / TT;
    const __half* xin = tmp + (size_t)bt * ldt + hh * HDIM;
    float x1 = __half2float(xin[lane]), x2 = __half2float(xin[lane + 32]);
    float ss = x1 * x1 + x2 * x2;
#pragma unroll
    for (int o = 16; o > 0; o >>= 1) ss += __shfl_xor_sync(0xffffffffu, ss, o);
    float inv = rsqrtf(ss / (float)HDIM + 1e-6f);
    float y1 = (1.0f + ns[lane]) * x1 * inv;
    float y2 = (1.0f + ns[lane + 32]) * x2 * inv;
    float c = cosp[t * HALF + lane];
    float s = sinp[t * HALF + lane];
    __half* orow = out + ((size_t)(b * NH + hh) * TT + t) * HDIM;
    orow[lane]      = __float2half(y1 * c - y2 * s);
    orow[lane + 32] = __float2half(y2 * c + y1 * s);
}

// ----------------- v transpose to (B,KVH,HD,T) half -----------------
__global__ void __launch_bounds__(256) vtrans_kernel() {
    int idx = blockIdx.x * blockDim.x + threadIdx.x;
    if (idx >= BB * TT * KVH * HDIM) return;
    int d = idx & 63;
    int r = idx >> 6;
    int hh = r % KVH;
    int bt = r / KVH;
    int t = bt % TT;
    int b = bt / TT;
    g_vth[(((size_t)(b * KVH + hh)) * HDIM + d) * TT + t] =
        g_qkvh[(size_t)bt * NQKV + 1280 + hh * HDIM + d];
}

// ----------------- fp16 tensor-core flash attention, 128-key stages, 2 sub-blocks -----------------
#define FQR 128
#define FKV 128
#define FKSTR 72                                 // K rows stride (halves)
#define FVSTR 136                                // V rows stride (halves)
#define FT_STAGE_H (FKV*FKSTR + HDIM*FVSTR)      // 9216 + 8704 = 17920 halves
#define FT_SMEM_BYTES (2*FT_STAGE_H*2)           // 71680 B

__global__ void __launch_bounds__(256) flash_tc_kernel() {
    extern __shared__ __half smh[];
    int tid = threadIdx.x;
    int lane = tid & 31, warp = tid >> 5;
    int g = lane >> 2, q = lane & 3;
    int z = blockIdx.y;
    int b = z / HH, h = z % HH;
    const __half* Q  = g_qh + (size_t)z * TT * HDIM;
    const __half* Kp = g_kh + (size_t)(b * KVH + h / REP) * TT * HDIM;
    const __half* Vt = g_vth + (size_t)(b * KVH + h / REP) * HDIM * TT;
    int i0 = blockIdx.x * FQR;
    const uint32_t s_u32 = (uint32_t)__cvta_generic_to_shared(smh);

    uint32_t qa[4][4];
    {
        const __half* Qw = Q + (size_t)(i0 + warp * 16) * HDIM;
#pragma unroll
        for (int kk = 0; kk < 4; kk++) {
            qa[kk][0] = *reinterpret_cast<const uint32_t*>(Qw + (size_t)g * HDIM + kk * 16 + 2 * q);
            qa[kk][1] = *reinterpret_cast<const uint32_t*>(Qw + (size_t)(g + 8) * HDIM + kk * 16 + 2 * q);
            qa[kk][2] = *reinterpret_cast<const uint32_t*>(Qw + (size_t)g * HDIM + kk * 16 + 2 * q + 8);
            qa[kk][3] = *reinterpret_cast<const uint32_t*>(Qw + (size_t)(g + 8) * HDIM + kk * 16 + 2 * q + 8);
        }
    }

    float o[8][4];
#pragma unroll
    for (int dt = 0; dt < 8; dt++)
#pragma unroll
        for (int r = 0; r < 4; r++) o[dt][r] = 0.f;
    float m0 = -1e30f, m1 = -1e30f, l0 = 0.f, l1 = 0.f;

#define FT_ISSUE(s, j0) do {                                                          \
    uint32_t kb_ = s_u32 + (s) * (FT_STAGE_H * 2);                                    \
    _Pragma("unroll")                                                                 \
    for (int j_ = 0; j_ < 4; j_++) {                                                  \
        int idx_ = j_ * 256 + tid; int r_ = idx_ >> 3, ch_ = idx_ & 7;                \
        cp16(kb_ + (uint32_t)(r_ * FKSTR + ch_ * 8) * 2,                              \
             Kp + (size_t)((j0) + r_) * HDIM + ch_ * 8);                              \
    }                                                                                 \
    uint32_t vb_ = kb_ + FKV * FKSTR * 2;                                             \
    _Pragma("unroll")                                                                 \
    for (int j_ = 0; j_ < 4; j_++) {                                                  \
        int idx_ = j_ * 256 + tid; int r_ = idx_ >> 4, ch_ = idx_ & 15;               \
        cp16(vb_ + (uint32_t)(r_ * FVSTR + ch_ * 8) * 2,                              \
             Vt + (size_t)r_ * TT + (j0) + ch_ * 8);                                  \
    }                                                                                 \
    asm volatile("cp.async.commit_group;" ::: "memory");                              \
} while (0)

    FT_ISSUE(0, 0);

    for (int it = 0; it < TT / FKV; it++) {
        int cur = it & 1;
        asm volatile("cp.async.wait_group 0;" ::: "memory");
        __syncthreads();
        if (it + 1 < TT / FKV) FT_ISSUE(cur ^ 1, (it + 1) * FKV);

        const __half* Kst = smh + cur * FT_STAGE_H;
        const __half* Vst = Kst + FKV * FKSTR;

#pragma unroll
        for (int sb = 0; sb < 2; sb++) {
            const __half* Ks = Kst + sb * 64 * FKSTR;
            const __half* Vs = Vst + sb * 64;

            float s[8][4];
#pragma unroll
            for (int t = 0; t < 8; t++)
#pragma unroll
                for (int r = 0; r < 4; r++) s[t][r] = 0.f;
#pragma unroll
            for (int kk = 0; kk < 4; kk++)
#pragma unroll
                for (int t = 0; t < 8; t++) {
                    const __half* kp = Ks + (8 * t + g) * FKSTR + kk * 16 + 2 * q;
                    uint32_t b0 = *reinterpret_cast<const uint32_t*>(kp);
                    uint32_t b1 = *reinterpret_cast<const uint32_t*>(kp + 8);
                    MMA_F16(s[t], qa[kk], b0, b1);
                }

            float mx0 = -1e30f, mx1 = -1e30f;
#pragma unroll
            for (int t = 0; t < 8; t++) {
                s[t][0] *= 0.125f; s[t][1] *= 0.125f; s[t][2] *= 0.125f; s[t][3] *= 0.125f;
                mx0 = fmaxf(mx0, fmaxf(s[t][0], s[t][1]));
                mx1 = fmaxf(mx1, fmaxf(s[t][2], s[t][3]));
            }
#pragma unroll
            for (int off = 1; off < 4; off <<= 1) {
                mx0 = fmaxf(mx0, __shfl_xor_sync(0xffffffffu, mx0, off));
                mx1 = fmaxf(mx1, __shfl_xor_sync(0xffffffffu, mx1, off));
            }
            float mn0 = fmaxf(m0, mx0), mn1 = fmaxf(m1, mx1);
            float al0 = __expf(m0 - mn0), al1 = __expf(m1 - mn1);
            m0 = mn0; m1 = mn1;
            float rs0 = 0.f, rs1 = 0.f;
#pragma unroll
            for (int t = 0; t < 8; t++) {
                s[t][0] = __expf(s[t][0] - mn0);
                s[t][1] = __expf(s[t][1] - mn0);
                s[t][2] = __expf(s[t][2] - mn1);
                s[t][3] = __expf(s[t][3] - mn1);
                rs0 += s[t][0] + s[t][1];
                rs1 += s[t][2] + s[t][3];
            }
#pragma unroll
            for (int off = 1; off < 4; off <<= 1) {
                rs0 += __shfl_xor_sync(0xffffffffu, rs0, off);
                rs1 += __shfl_xor_sync(0xffffffffu, rs1, off);
            }
            l0 = l0 * al0 + rs0;
            l1 = l1 * al1 + rs1;
#pragma unroll
            for (int dt = 0; dt < 8; dt++) {
                o[dt][0] *= al0; o[dt][1] *= al0;
                o[dt][2] *= al1; o[dt][3] *= al1;
            }

#pragma unroll
            for (int kt = 0; kt < 4; kt++) {
                uint32_t pa[4];
                pa[0] = packh2(s[2 * kt][0],     s[2 * kt][1]);
                pa[1] = packh2(s[2 * kt][2],     s[2 * kt][3]);
                pa[2] = packh2(s[2 * kt + 1][0], s[2 * kt + 1][1]);
                pa[3] = packh2(s[2 * kt + 1][2], s[2 * kt + 1][3]);
#pragma unroll
                for (int dt = 0; dt < 8; dt++) {
                    const __half* vp = Vs + (8 * dt + g) * FVSTR + kt * 16 + 2 * q;
                    uint32_t b0 = *reinterpret_cast<const uint32_t*>(vp);
                    uint32_t b1 = *reinterpret_cast<const uint32_t*>(vp + 8);
                    MMA_F16(o[dt], pa, b0, b1);
                }
            }
        }
    }
#undef FT_ISSUE

    float inv0 = 1.0f / l0, inv1 = 1.0f / l1;
    int r0 = i0 + warp * 16 + g;
    int r1 = r0 + 8;
    __half* out0 = g_attnh + ((size_t)(b * TT + r0) * HH + h) * HDIM;
    __half* out1 = g_attnh + ((size_t)(b * TT + r1) * HH + h) * HDIM;
#pragma unroll
    for (int dt = 0; dt < 8; dt++) {
        int c0 = 8 * dt + 2 * q;
        out0[c0]     = __float2half(o[dt][0] * inv0);
        out0[c0 + 1] = __float2half(o[dt][1] * inv0);
        out1[c0]     = __float2half(o[dt][2] * inv1);
        out1[c0 + 1] = __float2half(o[dt][3] * inv1);
    }
}

// ----------------- depthwise conv KW=15 SAME, 4 t per thread -----------------
__global__ void __launch_bounds__(256) dwconv_kernel(const float* __restrict__ dw) {
    int idx = blockIdx.x * blockDim.x + threadIdx.x;
    if (idx >= BB * (TT / 4) * DD) return;
    int d = idx & (DD - 1);
    int tq = (idx >> 10) & (TT / 4 - 1);
    int b = idx >> 19;
    float wv[KW];
#pragma unroll
    for (int w = 0; w < KW; w++) wv[w] = dw[w * DD + d];
    float gv[18];
    int tbase = tq * 4 - 7;
#pragma unroll
    for (int i = 0; i < 18; i++) {
        int t = tbase + i;
        gv[i] = (t >= 0 && t < TT) ? __half2float(g_gh[((size_t)(b * TT + t)) * DD + d]) : 0.f;
    }
#pragma unroll
    for (int j = 0; j < 4; j++) {
        float acc = 0.f;
#pragma unroll
        for (int w = 0; w < KW; w++) acc += gv[j + w] * wv[w];
        g_c[((size_t)(b * TT + tq * 4 + j)) * DD + d] = acc;
    }
}

// ----------------- staged-sync diagnostics (no-op while capturing) -----------------
static void dbg(const char* name) {
    cudaStreamCaptureStatus st = cudaStreamCaptureStatusActive;
    cudaError_t qe = cudaStreamIsCapturing((cudaStream_t)0, &st);
    if (qe != cudaSuccess || st != cudaStreamCaptureStatusNone) return;
    cudaError_t e = cudaStreamSynchronize((cudaStream_t)0);
    fprintf(stderr, "[dbg] %-12s -> %s\n", name, cudaGetErrorString(e));
}

extern "C" void kernel_launch(void* const* d_in, const int* in_sizes, int n_in,
                              void* d_out, int out_size) {
    if (n_in < 20) { fprintf(stderr, "[klaunch] unexpected n_in=%d\n", n_in); return; }

    const float* x       = (const float*)d_in[0];
    const float* cosp    = (const float*)d_in[2];
    const float* sinp    = (const float*)d_in[3];
    const float* attn_ns = (const float*)d_in[4];
    const float* qk      = (const float*)d_in[5];
    const float* kk      = (const float*)d_in[6];
    const float* vk      = (const float*)d_in[7];
    const float* qns     = (const float*)d_in[8];
    const float* kns     = (const float*)d_in[9];
    const float* ok      = (const float*)d_in[10];
    const float* conv_ns = (const float*)d_in[11];
    const float* pwup    = (const float*)d_in[12];
    const float* dwk     = (const float*)d_in[13];
    const float* cin_ns  = (const float*)d_in[14];
    const float* pwdown  = (const float*)d_in[15];
    const float* ffn_ns  = (const float*)d_in[16];
    const float* gatek   = (const float*)d_in[17];
    const float* upk     = (const float*)d_in[18];
    const float* downk   = (const float*)d_in[19];
    float* out = (float*)d_out;

    float *p_res, *p_c;
    __half *ph_h, *ph_qkvw, *ph_ok, *ph_pwup, *ph_pwd, *ph_gu, *ph_down;
    __half *ph_attn, *ph_ff, *ph_g, *ph_qkv, *ph_q, *ph_k, *ph_vt;
    cudaGetSymbolAddress((void**)&ph_qkvw, wh_qkv);
    cudaGetSymbolAddress((void**)&ph_ok, wh_ok);
    cudaGetSymbolAddress((void**)&ph_pwup, wh_pwup);
    cudaGetSymbolAddress((void**)&ph_pwd, wh_pwd);
    cudaGetSymbolAddress((void**)&ph_gu, wh_gu);
    cudaGetSymbolAddress((void**)&ph_down, wh_down);
    cudaGetSymbolAddress((void**)&p_res, g_res);
    cudaGetSymbolAddress((void**)&ph_h, g_hh);
    cudaGetSymbolAddress((void**)&ph_qkv, g_qkvh);
    cudaGetSymbolAddress((void**)&ph_attn, g_attnh);
    cudaGetSymbolAddress((void**)&ph_g, g_gh);
    cudaGetSymbolAddress((void**)&p_c, g_c);
    cudaGetSymbolAddress((void**)&ph_ff, g_ffh);
    cudaGetSymbolAddress((void**)&ph_q, g_qh);
    cudaGetSymbolAddress((void**)&ph_k, g_kh);
    cudaError_t es = cudaGetSymbolAddress((void**)&ph_vt, g_vth);
    if (es != cudaSuccess) { fprintf(stderr, "[sym] g_vth err=%d\n", (int)es); return; }

    cudaFuncSetAttribute(flash_tc_kernel, cudaFuncAttributeMaxDynamicSharedMemorySize, FT_SMEM_BYTES);
    cudaFuncSetAttribute(tgemm_kernel<1>, cudaFuncAttributeMaxDynamicSharedMemorySize, TG_SMEM_BYTES);
    cudaFuncSetAttribute(tgemm_kernel<5>, cudaFuncAttributeMaxDynamicSharedMemorySize, TG_SMEM_BYTES);
    cudaFuncSetAttribute(tgemm_kernel<6>, cudaFuncAttributeMaxDynamicSharedMemorySize, TG_SMEM_BYTES);
    es = cudaFuncSetAttribute(tgemm_kernel<7>, cudaFuncAttributeMaxDynamicSharedMemorySize, TG_SMEM_BYTES);
    if (es != cudaSuccess) fprintf(stderr, "[klaunch] smem attr err=%d\n", (int)es);

    // ---- merged weight transpose (one launch) ----
    WTPack wp;
    {
        struct { const float* in; __half* out; int K; int N; int imode; } tw[9] = {
            {qk, ph_qkvw, DD, DD, 0},
            {kk, ph_qkvw + (size_t)1024 * DD, DD, 256, 0},
            {vk, ph_qkvw + (size_t)1280 * DD, DD, 256, 0},
            {ok, ph_ok, DD, DD, 0},
            {pwup, ph_pwup, DD, 2 * DD, 1},
            {pwdown, ph_pwd, DD, DD, 0},
            {gatek, ph_gu, DD, DFF, 2},
            {upk, ph_gu, DD, DFF, 3},
            {downk, ph_down, DFF, DD, 0}
        };
        int off = 0;
        for (int i = 0; i < 9; i++) {
            wp.d[i].in = tw[i].in; wp.d[i].out = tw[i].out;
            wp.d[i].K = tw[i].K; wp.d[i].N = tw[i].N; wp.d[i].imode = tw[i].imode;
            wp.d[i].boff = off;
            off += (tw[i].N / 32) * (tw[i].K / 32);
        }
        wp.total = off;
    }
    wtrans_all_kernel<<<wp.total, dim3(32, 8)>>>(wp);
    dbg("wtrans");

    // ---- attention block ----
    rmsnorm_kernel<<<MROWS, 256>>>(x, attn_ns, ph_h);
    tgemm_kernel<7><<<dim3(NQKV / BNT, MROWS / BMT), 256, TG_SMEM_BYTES>>>(ph_h, ph_qkvw, nullptr, ph_qkv, nullptr, MROWS, NQKV, DD, DD, DD);
    dbg("qkv");
    qkpost_kernel<<<(BB * TT * HH) / 8, 256>>>(ph_qkv, NQKV, qns, cosp, sinp, ph_q, HH);
    qkpost_kernel<<<(BB * TT * KVH) / 8, 256>>>(ph_qkv + 1024, NQKV, kns, cosp, sinp, ph_k, KVH);
    vtrans_kernel<<<(BB * TT * KVH * HDIM) / 256, 256>>>();
    flash_tc_kernel<<<dim3(TT / FQR, BB * HH), 256, FT_SMEM_BYTES>>>();
    dbg("flash");
    tgemm_kernel<1><<<dim3(DD / BNT, MROWS / BMT), 256, TG_SMEM_BYTES>>>(ph_attn, ph_ok, p_res, nullptr, x, MROWS, DD, DD, DD, DD);
    dbg("oproj");

    // ---- conv block ----
    rmsnorm_kernel<<<MROWS, 256>>>(p_res, conv_ns, ph_h);
    tgemm_kernel<5><<<dim3((2 * DD) / BNT, MROWS / BMT), 256, TG_SMEM_BYTES>>>(ph_h, ph_pwup, nullptr, ph_g, nullptr, MROWS, 2 * DD, DD, DD, DD);
    dwconv_kernel<<<(BB * (TT / 4) * DD) / 256, 256>>>(dwk);
    rmsnorm_kernel<<<MROWS, 256>>>(p_c, cin_ns, ph_h);
    tgemm_kernel<1><<<dim3(DD / BNT, MROWS / BMT), 256, TG_SMEM_BYTES>>>(ph_h, ph_pwd, p_res, nullptr, p_res, MROWS, DD, DD, DD, DD);
    dbg("conv");

    // ---- FFN block ----
    rmsnorm_kernel<<<MROWS, 256>>>(p_res, ffn_ns, ph_h);
    tgemm_kernel<6><<<dim3((2 * DFF) / BNT, MROWS / BMT), 256, TG_SMEM_BYTES>>>(ph_h, ph_gu, nullptr, ph_ff, nullptr, MROWS, 2 * DFF, DD, DD, DD);
    tgemm_kernel<1><<<dim3(DD / BNT, MROWS / BMT), 256, TG_SMEM_BYTES>>>(ph_ff, ph_down, out, nullptr, p_res, MROWS, DD, DFF, DFF, DFF);
    dbg("ffn");
}

// round 16
// speedup vs baseline: 7.3679x; 1.0457x over previous
#include <cuda_runtime.h>
#include <cuda_fp16.h>
#include <math.h>
#include <stdint.h>
#include <stdio.h>

#define BB 2
#define TT 2048
#define DD 1024
#define HH 16
#define KVH 4
#define HDIM 64
#define HALF 32
#define DFF 4096
#define KW 15
#define MROWS (BB*TT)   // 4096
#define REP (HH/KVH)    // 4
#define NQKV 1536

#define SZ_QK   1048576
#define SZ_KK   262144
#define SZ_PWUP 2097152
#define SZ_X    4194304

// ----------------- fp16 transposed weights [N][K] (column-interleaved where fused) -----------------
__device__ __align__(256) __half wh_qkv [NQKV*DD];
__device__ __align__(256) __half wh_ok  [SZ_QK];
__device__ __align__(256) __half wh_pwup[SZ_PWUP];
__device__ __align__(256) __half wh_pwd [SZ_QK];
__device__ __align__(256) __half wh_gu  [2*SZ_X];
__device__ __align__(256) __half wh_down[SZ_X];

// ----------------- scratch -----------------
__device__ __align__(256) float  g_res [(size_t)MROWS*DD];
__device__ __align__(256) __half g_hh  [(size_t)MROWS*DD];
__device__ __align__(256) __half g_qkvh[(size_t)MROWS*NQKV];
__device__ __align__(256) __half g_qh  [(size_t)BB*HH*TT*HDIM];
__device__ __align__(256) __half g_kh  [(size_t)BB*KVH*TT*HDIM];
__device__ __align__(256) __half g_vth [(size_t)BB*KVH*HDIM*TT];
__device__ __align__(256) __half g_attnh[(size_t)MROWS*DD];
__device__ __align__(256) __half g_gh  [(size_t)MROWS*DD];
__device__ __align__(256) float  g_c   [(size_t)MROWS*DD];
__device__ __align__(256) __half g_ffh [(size_t)MROWS*DFF];

__device__ __forceinline__ uint32_t packh2(float a, float b) {
    __half2 h = __floats2half2_rn(a, b);
    return *reinterpret_cast<uint32_t*>(&h);
}

#define MMA_F16(acc, a, b0, b1)                                               \
    asm volatile(                                                             \
        "mma.sync.aligned.m16n8k16.row.col.f32.f16.f16.f32 "                  \
        "{%0,%1,%2,%3}, {%4,%5,%6,%7}, {%8,%9}, {%0,%1,%2,%3};"               \
        : "+f"((acc)[0]), "+f"((acc)[1]), "+f"((acc)[2]), "+f"((acc)[3])      \
        : "r"((a)[0]), "r"((a)[1]), "r"((a)[2]), "r"((a)[3]),                 \
          "r"(b0), "r"(b1))

#define LDMX4(r0, r1, r2, r3, addr)                                           \
    asm volatile("ldmatrix.sync.aligned.m8n8.x4.shared.b16 {%0,%1,%2,%3}, [%4];" \
                 : "=r"(r0), "=r"(r1), "=r"(r2), "=r"(r3) : "r"(addr))

__device__ __forceinline__ void cp16(uint32_t dst, const void* src) {
    asm volatile("cp.async.cg.shared.global [%0], [%1], 16;" :: "r"(dst), "l"(src));
}

// ----------------- merged weight transpose+convert: fp32 [K][N] -> half [rowmap(n)][K] -----------------
struct WTDesc { const float* in; __half* out; int K; int N; int imode; int boff; };
struct WTPack { WTDesc d[9]; int total; };

__global__ void __launch_bounds__(256) wtrans_all_kernel(WTPack p) {
    __shared__ float t[32][33];
    int bid = blockIdx.x;
    int wi = 0;
#pragma unroll
    for (int i = 1; i < 9; i++) if (bid >= p.d[i].boff) wi = i;
    const WTDesc& D = p.d[wi];
    int local = bid - D.boff;
    int nbx = D.N >> 5;
    int kb = (local / nbx) * 32, nb = (local % nbx) * 32;
    int tx = threadIdx.x, ty = threadIdx.y;
#pragma unroll
    for (int i = ty; i < 32; i += 8)
        t[i][tx] = D.in[(size_t)(kb + i) * D.N + nb + tx];
    __syncthreads();
#pragma unroll
    for (int i = ty; i < 32; i += 8) {
        int n = nb + i;
        int r = (D.imode == 0) ? n
              : (D.imode == 1) ? ((n < D.N / 2) ? 2 * n : 2 * (n - D.N / 2) + 1)
              : (D.imode == 2) ? 2 * n : 2 * n + 1;
        D.out[(size_t)r * D.K + kb + tx] = __float2half(t[tx][i]);
    }
}

// ----------------- zcRMS over D=1024, half out -----------------
__global__ void __launch_bounds__(256) rmsnorm_kernel(const float* __restrict__ in,
                               const float* __restrict__ scale,
                               __half* __restrict__ out) {
    size_t row = blockIdx.x;
    const float* xr = in + row * DD;
    __half* orow = out + row * DD;
    int tid = threadIdx.x;
    float v[4];
    float ss = 0.f;
#pragma unroll
    for (int i = 0; i < 4; i++) { v[i] = xr[tid + i * 256]; ss += v[i] * v[i]; }
    __shared__ float red[256];
    red[tid] = ss; __syncthreads();
    for (int s = 128; s > 0; s >>= 1) { if (tid < s) red[tid] += red[tid + s]; __syncthreads(); }
    float inv = rsqrtf(red[0] / (float)DD + 1e-6f);
#pragma unroll
    for (int i = 0; i < 4; i++) {
        int c = tid + i * 256;
        orow[c] = __float2half((1.0f + scale[c]) * v[i] * inv);
    }
}

// ----------------- fp16 tensor-core GEMM, BKT=64, 3-stage pipeline, ldmatrix B-frags -----------------
// MODE 1: C f32 = res+AB ; 5: Ch[M,N/2] = u1*sigmoid(u2)
// 6: Ch[M,N/2] = relu(even)*relu(odd) ; 7: Ch[M,N] = AB
#define BMT 128
#define BNT 128
#define BKT 64
#define ASTR 72
#define BSTR 72
#define STAGE_H (BMT*ASTR + BNT*BSTR)
#define TG_SMEM_BYTES (3*STAGE_H*2)

template <int MODE>
__global__ void __launch_bounds__(256, 2) tgemm_kernel(
    const __half* __restrict__ A, const __half* __restrict__ Wt,
    float* __restrict__ C, __half* __restrict__ Ch,
    const float* __restrict__ res,
    int M, int N, int K, int lda, int ldb)
{
    extern __shared__ __half smh[];
    int tid = threadIdx.x;
    int lane = tid & 31, warp = tid >> 5;
    int g = lane >> 2, q = lane & 3;
    int btile = lane >> 3, brow = lane & 7;
    int warp_m = warp >> 2;
    int warp_n = warp & 3;
    int m0 = blockIdx.y * BMT, n0 = blockIdx.x * BNT;
    const uint32_t s_u32 = (uint32_t)__cvta_generic_to_shared(smh);

    float acc[4][4][4];
#pragma unroll
    for (int mt = 0; mt < 4; mt++)
#pragma unroll
        for (int nt = 0; nt < 4; nt++)
#pragma unroll
            for (int r = 0; r < 4; r++) acc[mt][nt][r] = 0.f;

#define TG_ISSUE(s, k0) do {                                                          \
    uint32_t ab_ = s_u32 + (s) * (STAGE_H * 2);                                       \
    _Pragma("unroll")                                                                 \
    for (int j_ = 0; j_ < 4; j_++) {                                                  \
        int idx_ = j_ * 256 + tid; int r_ = idx_ >> 3, ch_ = idx_ & 7;                \
        cp16(ab_ + (uint32_t)(r_ * ASTR + ch_ * 8) * 2,                               \
             A + (size_t)(m0 + r_) * lda + (k0) + ch_ * 8);                           \
    }                                                                                 \
    uint32_t bb_ = ab_ + BMT * ASTR * 2;                                              \
    _Pragma("unroll")                                                                 \
    for (int j_ = 0; j_ < 4; j_++) {                                                  \
        int idx_ = j_ * 256 + tid; int r_ = idx_ >> 3, ch_ = idx_ & 7;                \
        cp16(bb_ + (uint32_t)(r_ * BSTR + ch_ * 8) * 2,                               \
             Wt + (size_t)(n0 + r_) * ldb + (k0) + ch_ * 8);                          \
    }                                                                                 \
    asm volatile("cp.async.commit_group;" ::: "memory");                              \
} while (0)

    int nk = K / BKT;
    TG_ISSUE(0, 0);
    TG_ISSUE(1, BKT);

    for (int kt = 0; kt < nk; kt++) {
        int cur = kt % 3;
        asm volatile("cp.async.wait_group 1;" ::: "memory");
        __syncthreads();
        if (kt + 2 < nk) TG_ISSUE((kt + 2) % 3, (kt + 2) * BKT);

        uint32_t a_row = s_u32 + cur * (STAGE_H * 2)
                       + (uint32_t)((warp_m * 64 + (lane & 15)) * ASTR + (lane >> 4) * 8) * 2;
        uint32_t b_base = s_u32 + cur * (STAGE_H * 2) + BMT * ASTR * 2;

#pragma unroll
        for (int kk = 0; kk < 4; kk++) {
            uint32_t a[4][4];
#pragma unroll
            for (int mt = 0; mt < 4; mt++) {
                uint32_t addr = a_row + (uint32_t)(mt * 16 * ASTR + kk * 16) * 2;
                LDMX4(a[mt][0], a[mt][1], a[mt][2], a[mt][3], addr);
            }
            uint32_t bq[4][2];
#pragma unroll
            for (int p = 0; p < 2; p++) {
                int ntl = p * 2 + (btile >> 1);
                uint32_t baddr = b_base + (uint32_t)((warp_n * 32 + ntl * 8 + brow) * BSTR
                                                     + kk * 16 + (btile & 1) * 8) * 2;
                LDMX4(bq[p * 2][0], bq[p * 2][1], bq[p * 2 + 1][0], bq[p * 2 + 1][1], baddr);
            }
#pragma unroll
            for (int nt = 0; nt < 4; nt++)
#pragma unroll
                for (int mt = 0; mt < 4; mt++)
                    MMA_F16(acc[mt][nt], a[mt], bq[nt][0], bq[nt][1]);
        }
    }
#undef TG_ISSUE

#pragma unroll
    for (int mt = 0; mt < 4; mt++) {
#pragma unroll
        for (int nt = 0; nt < 4; nt++) {
            int colbase = n0 + warp_n * 32 + nt * 8;
#pragma unroll
            for (int half_ = 0; half_ < 2; half_++) {
                int row = m0 + warp_m * 64 + mt * 16 + g + half_ * 8;
                float v0 = acc[mt][nt][half_ * 2 + 0];
                float v1 = acc[mt][nt][half_ * 2 + 1];
                if (MODE == 5) {
                    size_t o = (size_t)row * (N >> 1) + (colbase >> 1) + q;
                    Ch[o] = __float2half(v0 / (1.0f + __expf(-v1)));
                } else if (MODE == 6) {
                    size_t o = (size_t)row * (N >> 1) + (colbase >> 1) + q;
                    Ch[o] = __float2half(fmaxf(v0, 0.f) * fmaxf(v1, 0.f));
                } else if (MODE == 7) {
                    size_t o = (size_t)row * N + colbase + 2 * q;
                    Ch[o]     = __float2half(v0);
                    Ch[o + 1] = __float2half(v1);
                } else {
                    size_t o = (size_t)row * N + colbase + 2 * q;
                    if (MODE == 1) { C[o] = v0 + res[o]; C[o + 1] = v1 + res[o + 1]; }
                }
            }
        }
    }
}

// ----------------- per-head zcRMS(64) + RoPE, half in/out; ldt = row stride of tmp -----------------
__global__ void __launch_bounds__(256) qkpost_kernel(const __half* __restrict__ tmp, int ldt,
                              const float* __restrict__ ns,
                              const float* __restrict__ cosp, const float* __restrict__ sinp,
                              __half* __restrict__ out, int NH) {
    int warp = threadIdx.x >> 5, lane = threadIdx.x & 31;
    int row = blockIdx.x * 8 + warp;
    if (row >= BB * TT * NH) return;
    int hh = row % NH;
    int bt = row / NH;
    int t = bt % TT;
    int b = bt / TT;
    const __half* xin = tmp + (size_t)bt * ldt + hh * HDIM;
    float x1 = __half2float(xin[lane]), x2 = __half2float(xin[lane + 32]);
    float ss = x1 * x1 + x2 * x2;
#pragma unroll
    for (int o = 16; o > 0; o >>= 1) ss += __shfl_xor_sync(0xffffffffu, ss, o);
    float inv = rsqrtf(ss / (float)HDIM + 1e-6f);
    float y1 = (1.0f + ns[lane]) * x1 * inv;
    float y2 = (1.0f + ns[lane + 32]) * x2 * inv;
    float c = cosp[t * HALF + lane];
    float s = sinp[t * HALF + lane];
    __half* orow = out + ((size_t)(b * NH + hh) * TT + t) * HDIM;
    orow[lane]      = __float2half(y1 * c - y2 * s);
    orow[lane + 32] = __float2half(y2 * c + y1 * s);
}

// ----------------- v transpose to (B,KVH,HD,T) half -----------------
__global__ void __launch_bounds__(256) vtrans_kernel() {
    int idx = blockIdx.x * blockDim.x + threadIdx.x;
    if (idx >= BB * TT * KVH * HDIM) return;
    int d = idx & 63;
    int r = idx >> 6;
    int hh = r % KVH;
    int bt = r / KVH;
    int t = bt % TT;
    int b = bt / TT;
    g_vth[(((size_t)(b * KVH + hh)) * HDIM + d) * TT + t] =
        g_qkvh[(size_t)bt * NQKV + 1280 + hh * HDIM + d];
}

// ----------------- fp16 tensor-core flash attention, 128-key stages, ldmatrix K/V frags -----------------
#define FQR 128
#define FKV 128
#define FKSTR 72
#define FVSTR 136
#define FT_STAGE_H (FKV*FKSTR + HDIM*FVSTR)
#define FT_SMEM_BYTES (2*FT_STAGE_H*2)

__global__ void __launch_bounds__(256) flash_tc_kernel() {
    extern __shared__ __half smh[];
    int tid = threadIdx.x;
    int lane = tid & 31, warp = tid >> 5;
    int g = lane >> 2, q = lane & 3;
    int btile = lane >> 3, brow = lane & 7;
    int z = blockIdx.y;
    int b = z / HH, h = z % HH;
    const __half* Q  = g_qh + (size_t)z * TT * HDIM;
    const __half* Kp = g_kh + (size_t)(b * KVH + h / REP) * TT * HDIM;
    const __half* Vt = g_vth + (size_t)(b * KVH + h / REP) * HDIM * TT;
    int i0 = blockIdx.x * FQR;
    const uint32_t s_u32 = (uint32_t)__cvta_generic_to_shared(smh);

    uint32_t qa[4][4];
    {
        const __half* Qw = Q + (size_t)(i0 + warp * 16) * HDIM;
#pragma unroll
        for (int kk = 0; kk < 4; kk++) {
            qa[kk][0] = *reinterpret_cast<const uint32_t*>(Qw + (size_t)g * HDIM + kk * 16 + 2 * q);
            qa[kk][1] = *reinterpret_cast<const uint32_t*>(Qw + (size_t)(g + 8) * HDIM + kk * 16 + 2 * q);
            qa[kk][2] = *reinterpret_cast<const uint32_t*>(Qw + (size_t)g * HDIM + kk * 16 + 2 * q + 8);
            qa[kk][3] = *reinterpret_cast<const uint32_t*>(Qw + (size_t)(g + 8) * HDIM + kk * 16 + 2 * q + 8);
        }
    }

    float o[8][4];
#pragma unroll
    for (int dt = 0; dt < 8; dt++)
#pragma unroll
        for (int r = 0; r < 4; r++) o[dt][r] = 0.f;
    float m0 = -1e30f, m1 = -1e30f, l0 = 0.f, l1 = 0.f;

#define FT_ISSUE(s, j0) do {                                                          \
    uint32_t kb_ = s_u32 + (s) * (FT_STAGE_H * 2);                                    \
    _Pragma("unroll")                                                                 \
    for (int j_ = 0; j_ < 4; j_++) {                                                  \
        int idx_ = j_ * 256 + tid; int r_ = idx_ >> 3, ch_ = idx_ & 7;                \
        cp16(kb_ + (uint32_t)(r_ * FKSTR + ch_ * 8) * 2,                              \
             Kp + (size_t)((j0) + r_) * HDIM + ch_ * 8);                              \
    }                                                                                 \
    uint32_t vb_ = kb_ + FKV * FKSTR * 2;                                             \
    _Pragma("unroll")                                                                 \
    for (int j_ = 0; j_ < 4; j_++) {                                                  \
        int idx_ = j_ * 256 + tid; int r_ = idx_ >> 4, ch_ = idx_ & 15;               \
        cp16(vb_ + (uint32_t)(r_ * FVSTR + ch_ * 8) * 2,                              \
             Vt + (size_t)r_ * TT + (j0) + ch_ * 8);                                  \
    }                                                                                 \
    asm volatile("cp.async.commit_group;" ::: "memory");                              \
} while (0)

    FT_ISSUE(0, 0);

    for (int it = 0; it < TT / FKV; it++) {
        int cur = it & 1;
        asm volatile("cp.async.wait_group 0;" ::: "memory");
        __syncthreads();
        if (it + 1 < TT / FKV) FT_ISSUE(cur ^ 1, (it + 1) * FKV);

#pragma unroll
        for (int sb = 0; sb < 2; sb++) {
            uint32_t kbase = s_u32 + cur * (FT_STAGE_H * 2) + sb * 64 * FKSTR * 2;
            uint32_t vbase = s_u32 + cur * (FT_STAGE_H * 2) + FKV * FKSTR * 2 + sb * 64 * 2;

            float s[8][4];
#pragma unroll
            for (int t = 0; t < 8; t++)
#pragma unroll
                for (int r = 0; r < 4; r++) s[t][r] = 0.f;
#pragma unroll
            for (int kk = 0; kk < 4; kk++) {
                uint32_t bq[8][2];
#pragma unroll
                for (int p = 0; p < 4; p++) {
                    int tl = p * 2 + (btile >> 1);
                    uint32_t baddr = kbase + (uint32_t)((tl * 8 + brow) * FKSTR
                                                        + kk * 16 + (btile & 1) * 8) * 2;
                    LDMX4(bq[p * 2][0], bq[p * 2][1], bq[p * 2 + 1][0], bq[p * 2 + 1][1], baddr);
                }
#pragma unroll
                for (int t = 0; t < 8; t++)
                    MMA_F16(s[t], qa[kk], bq[t][0], bq[t][1]);
            }

            float mx0 = -1e30f, mx1 = -1e30f;
#pragma unroll
            for (int t = 0; t < 8; t++) {
                s[t][0] *= 0.125f; s[t][1] *= 0.125f; s[t][2] *= 0.125f; s[t][3] *= 0.125f;
                mx0 = fmaxf(mx0, fmaxf(s[t][0], s[t][1]));
                mx1 = fmaxf(mx1, fmaxf(s[t][2], s[t][3]));
            }
#pragma unroll
            for (int off = 1; off < 4; off <<= 1) {
                mx0 = fmaxf(mx0, __shfl_xor_sync(0xffffffffu, mx0, off));
                mx1 = fmaxf(mx1, __shfl_xor_sync(0xffffffffu, mx1, off));
            }
            float mn0 = fmaxf(m0, mx0), mn1 = fmaxf(m1, mx1);
            float al0 = __expf(m0 - mn0), al1 = __expf(m1 - mn1);
            m0 = mn0; m1 = mn1;
            float rs0 = 0.f, rs1 = 0.f;
#pragma unroll
            for (int t = 0; t < 8; t++) {
                s[t][0] = __expf(s[t][0] - mn0);
                s[t][1] = __expf(s[t][1] - mn0);
                s[t][2] = __expf(s[t][2] - mn1);
                s[t][3] = __expf(s[t][3] - mn1);
                rs0 += s[t][0] + s[t][1];
                rs1 += s[t][2] + s[t][3];
            }
#pragma unroll
            for (int off = 1; off < 4; off <<= 1) {
                rs0 += __shfl_xor_sync(0xffffffffu, rs0, off);
                rs1 += __shfl_xor_sync(0xffffffffu, rs1, off);
            }
            l0 = l0 * al0 + rs0;
            l1 = l1 * al1 + rs1;
#pragma unroll
            for (int dt = 0; dt < 8; dt++) {
                o[dt][0] *= al0; o[dt][1] *= al0;
                o[dt][2] *= al1; o[dt][3] *= al1;
            }

#pragma unroll
            for (int kt = 0; kt < 4; kt++) {
                uint32_t pa[4];
                pa[0] = packh2(s[2 * kt][0],     s[2 * kt][1]);
                pa[1] = packh2(s[2 * kt][2],     s[2 * kt][3]);
                pa[2] = packh2(s[2 * kt + 1][0], s[2 * kt + 1][1]);
                pa[3] = packh2(s[2 * kt + 1][2], s[2 * kt + 1][3]);
                uint32_t vq[8][2];
#pragma unroll
                for (int p = 0; p < 4; p++) {
                    int dl = p * 2 + (btile >> 1);
                    uint32_t vaddr = vbase + (uint32_t)((dl * 8 + brow) * FVSTR
                                                        + kt * 16 + (btile & 1) * 8) * 2;
                    LDMX4(vq[p * 2][0], vq[p * 2][1], vq[p * 2 + 1][0], vq[p * 2 + 1][1], vaddr);
                }
#pragma unroll
                for (int dt = 0; dt < 8; dt++)
                    MMA_F16(o[dt], pa, vq[dt][0], vq[dt][1]);
            }
        }
    }
#undef FT_ISSUE

    float inv0 = 1.0f / l0, inv1 = 1.0f / l1;
    int r0 = i0 + warp * 16 + g;
    int r1 = r0 + 8;
    __half* out0 = g_attnh + ((size_t)(b * TT + r0) * HH + h) * HDIM;
    __half* out1 = g_attnh + ((size_t)(b * TT + r1) * HH + h) * HDIM;
#pragma unroll
    for (int dt = 0; dt < 8; dt++) {
        int c0 = 8 * dt + 2 * q;
        out0[c0]     = __float2half(o[dt][0] * inv0);
        out0[c0 + 1] = __float2half(o[dt][1] * inv0);
        out1[c0]     = __float2half(o[dt][2] * inv1);
        out1[c0 + 1] = __float2half(o[dt][3] * inv1);
    }
}

// ----------------- depthwise conv KW=15 SAME, 4 t per thread -----------------
__global__ void __launch_bounds__(256) dwconv_kernel(const float* __restrict__ dw) {
    int idx = blockIdx.x * blockDim.x + threadIdx.x;
    if (idx >= BB * (TT / 4) * DD) return;
    int d = idx & (DD - 1);
    int tq = (idx >> 10) & (TT / 4 - 1);
    int b = idx >> 19;
    float wv[KW];
#pragma unroll
    for (int w = 0; w < KW; w++) wv[w] = dw[w * DD + d];
    float gv[18];
    int tbase = tq * 4 - 7;
#pragma unroll
    for (int i = 0; i < 18; i++) {
        int t = tbase + i;
        gv[i] = (t >= 0 && t < TT) ? __half2float(g_gh[((size_t)(b * TT + t)) * DD + d]) : 0.f;
    }
#pragma unroll
    for (int j = 0; j < 4; j++) {
        float acc = 0.f;
#pragma unroll
        for (int w = 0; w < KW; w++) acc += gv[j + w] * wv[w];
        g_c[((size_t)(b * TT + tq * 4 + j)) * DD + d] = acc;
    }
}

// ----------------- staged-sync diagnostics (no-op while capturing) -----------------
static void dbg(const char* name) {
    cudaStreamCaptureStatus st = cudaStreamCaptureStatusActive;
    cudaError_t qe = cudaStreamIsCapturing((cudaStream_t)0, &st);
    if (qe != cudaSuccess || st != cudaStreamCaptureStatusNone) return;
    cudaError_t e = cudaStreamSynchronize((cudaStream_t)0);
    fprintf(stderr, "[dbg] %-12s -> %s\n", name, cudaGetErrorString(e));
}

extern "C" void kernel_launch(void* const* d_in, const int* in_sizes, int n_in,
                              void* d_out, int out_size) {
    if (n_in < 20) { fprintf(stderr, "[klaunch] unexpected n_in=%d\n", n_in); return; }

    const float* x       = (const float*)d_in[0];
    const float* cosp    = (const float*)d_in[2];
    const float* sinp    = (const float*)d_in[3];
    const float* attn_ns = (const float*)d_in[4];
    const float* qk      = (const float*)d_in[5];
    const float* kk      = (const float*)d_in[6];
    const float* vk      = (const float*)d_in[7];
    const float* qns     = (const float*)d_in[8];
    const float* kns     = (const float*)d_in[9];
    const float* ok      = (const float*)d_in[10];
    const float* conv_ns = (const float*)d_in[11];
    const float* pwup    = (const float*)d_in[12];
    const float* dwk     = (const float*)d_in[13];
    const float* cin_ns  = (const float*)d_in[14];
    const float* pwdown  = (const float*)d_in[15];
    const float* ffn_ns  = (const float*)d_in[16];
    const float* gatek   = (const float*)d_in[17];
    const float* upk     = (const float*)d_in[18];
    const float* downk   = (const float*)d_in[19];
    float* out = (float*)d_out;

    float *p_res, *p_c;
    __half *ph_h, *ph_qkvw, *ph_ok, *ph_pwup, *ph_pwd, *ph_gu, *ph_down;
    __half *ph_attn, *ph_ff, *ph_g, *ph_qkv, *ph_q, *ph_k, *ph_vt;
    cudaGetSymbolAddress((void**)&ph_qkvw, wh_qkv);
    cudaGetSymbolAddress((void**)&ph_ok, wh_ok);
    cudaGetSymbolAddress((void**)&ph_pwup, wh_pwup);
    cudaGetSymbolAddress((void**)&ph_pwd, wh_pwd);
    cudaGetSymbolAddress((void**)&ph_gu, wh_gu);
    cudaGetSymbolAddress((void**)&ph_down, wh_down);
    cudaGetSymbolAddress((void**)&p_res, g_res);
    cudaGetSymbolAddress((void**)&ph_h, g_hh);
    cudaGetSymbolAddress((void**)&ph_qkv, g_qkvh);
    cudaGetSymbolAddress((void**)&ph_attn, g_attnh);
    cudaGetSymbolAddress((void**)&ph_g, g_gh);
    cudaGetSymbolAddress((void**)&p_c, g_c);
    cudaGetSymbolAddress((void**)&ph_ff, g_ffh);
    cudaGetSymbolAddress((void**)&ph_q, g_qh);
    cudaGetSymbolAddress((void**)&ph_k, g_kh);
    cudaError_t es = cudaGetSymbolAddress((void**)&ph_vt, g_vth);
    if (es != cudaSuccess) { fprintf(stderr, "[sym] g_vth err=%d\n", (int)es); return; }

    cudaFuncSetAttribute(flash_tc_kernel, cudaFuncAttributeMaxDynamicSharedMemorySize, FT_SMEM_BYTES);
    cudaFuncSetAttribute(tgemm_kernel<1>, cudaFuncAttributeMaxDynamicSharedMemorySize, TG_SMEM_BYTES);
    cudaFuncSetAttribute(tgemm_kernel<5>, cudaFuncAttributeMaxDynamicSharedMemorySize, TG_SMEM_BYTES);
    cudaFuncSetAttribute(tgemm_kernel<6>, cudaFuncAttributeMaxDynamicSharedMemorySize, TG_SMEM_BYTES);
    es = cudaFuncSetAttribute(tgemm_kernel<7>, cudaFuncAttributeMaxDynamicSharedMemorySize, TG_SMEM_BYTES);
    if (es != cudaSuccess) fprintf(stderr, "[klaunch] smem attr err=%d\n", (int)es);

    // ---- merged weight transpose (one launch) ----
    WTPack wp;
    {
        struct { const float* in; __half* out; int K; int N; int imode; } tw[9] = {
            {qk, ph_qkvw, DD, DD, 0},
            {kk, ph_qkvw + (size_t)1024 * DD, DD, 256, 0},
            {vk, ph_qkvw + (size_t)1280 * DD, DD, 256, 0},
            {ok, ph_ok, DD, DD, 0},
            {pwup, ph_pwup, DD, 2 * DD, 1},
            {pwdown, ph_pwd, DD, DD, 0},
            {gatek, ph_gu, DD, DFF, 2},
            {upk, ph_gu, DD, DFF, 3},
            {downk, ph_down, DFF, DD, 0}
        };
        int off = 0;
        for (int i = 0; i < 9; i++) {
            wp.d[i].in = tw[i].in; wp.d[i].out = tw[i].out;
            wp.d[i].K = tw[i].K; wp.d[i].N = tw[i].N; wp.d[i].imode = tw[i].imode;
            wp.d[i].boff = off;
            off += (tw[i].N / 32) * (tw[i].K / 32);
        }
        wp.total = off;
    }
    wtrans_all_kernel<<<wp.total, dim3(32, 8)>>>(wp);
    dbg("wtrans");

    // ---- attention block ----
    rmsnorm_kernel<<<MROWS, 256>>>(x, attn_ns, ph_h);
    tgemm_kernel<7><<<dim3(NQKV / BNT, MROWS / BMT), 256, TG_SMEM_BYTES>>>(ph_h, ph_qkvw, nullptr, ph_qkv, nullptr, MROWS, NQKV, DD, DD, DD);
    dbg("qkv");
    qkpost_kernel<<<(BB * TT * HH) / 8, 256>>>(ph_qkv, NQKV, qns, cosp, sinp, ph_q, HH);
    qkpost_kernel<<<(BB * TT * KVH) / 8, 256>>>(ph_qkv + 1024, NQKV, kns, cosp, sinp, ph_k, KVH);
    vtrans_kernel<<<(BB * TT * KVH * HDIM) / 256, 256>>>();
    flash_tc_kernel<<<dim3(TT / FQR, BB * HH), 256, FT_SMEM_BYTES>>>();
    dbg("flash");
    tgemm_kernel<1><<<dim3(DD / BNT, MROWS / BMT), 256, TG_SMEM_BYTES>>>(ph_attn, ph_ok, p_res, nullptr, x, MROWS, DD, DD, DD, DD);
    dbg("oproj");

    // ---- conv block ----
    rmsnorm_kernel<<<MROWS, 256>>>(p_res, conv_ns, ph_h);
    tgemm_kernel<5><<<dim3((2 * DD) / BNT, MROWS / BMT), 256, TG_SMEM_BYTES>>>(ph_h, ph_pwup, nullptr, ph_g, nullptr, MROWS, 2 * DD, DD, DD, DD);
    dwconv_kernel<<<(BB * (TT / 4) * DD) / 256, 256>>>(dwk);
    rmsnorm_kernel<<<MROWS, 256>>>(p_c, cin_ns, ph_h);
    tgemm_kernel<1><<<dim3(DD / BNT, MROWS / BMT), 256, TG_SMEM_BYTES>>>(ph_h, ph_pwd, p_res, nullptr, p_res, MROWS, DD, DD, DD, DD);
    dbg("conv");

    // ---- FFN block ----
    rmsnorm_kernel<<<MROWS, 256>>>(p_res, ffn_ns, ph_h);
    tgemm_kernel<6><<<dim3((2 * DFF) / BNT, MROWS / BMT), 256, TG_SMEM_BYTES>>>(ph_h, ph_gu, nullptr, ph_ff, nullptr, MROWS, 2 * DFF, DD, DD, DD);
    tgemm_kernel<1><<<dim3(DD / BNT, MROWS / BMT), 256, TG_SMEM_BYTES>>>(ph_ff, ph_down, out, nullptr, p_res, MROWS, DD, DFF, DFF, DFF);
    dbg("ffn");
}